// round 1
// baseline (speedup 1.0000x reference)
#include <cuda_runtime.h>

// Shapes (fixed): B=4, S=2048, D=1024, H=16, dk=64.
// All four GEMMs are [8192,1024] x [1024,1024].
#define MDIM 8192
#define NDIM 1024
#define KDIM 1024

// Scratch (device globals: allocation-free per harness rules)
__device__ float g_Qp[MDIM * NDIM];
__device__ float g_Kp[MDIM * NDIM];
__device__ float g_Vp[MDIM * NDIM];
__device__ float g_Ctx[MDIM * NDIM];

// ---------------------------------------------------------------------------
// SGEMM: C[M,N] = A[M,K] @ B[K,N], row-major, 128x128 tile, BK=8, 256 thr,
// 8x8 register microtile.
// ---------------------------------------------------------------------------
__device__ __forceinline__ void sgemm_body(const float* __restrict__ A,
                                           const float* __restrict__ B,
                                           float* __restrict__ C)
{
    __shared__ float As[8][128];   // transposed A tile: As[k][row]
    __shared__ float Bs[8][128];   // Bs[k][col]

    const int tid = threadIdx.x;
    const int bx = blockIdx.x, by = blockIdx.y;
    const int tx = tid & 15;       // 0..15 -> C cols tx*8..
    const int ty = tid >> 4;       // 0..15 -> C rows ty*8..

    // A tile loads: 128 rows x 8 cols = 256 float4 (2 per row)
    const int arow = tid >> 1;
    const int acol = (tid & 1) << 2;
    // B tile loads: 8 rows x 128 cols = 256 float4
    const int brow = tid >> 5;
    const int bcol = (tid & 31) << 2;

    const float* Ap = A + (size_t)(by * 128 + arow) * KDIM + acol;
    const float* Bp = B + (size_t)brow * NDIM + bx * 128 + bcol;

    float acc[8][8];
#pragma unroll
    for (int i = 0; i < 8; i++)
#pragma unroll
        for (int j = 0; j < 8; j++) acc[i][j] = 0.0f;

    for (int k0 = 0; k0 < KDIM; k0 += 8) {
        float4 av = *(const float4*)(Ap + k0);
        float4 bv = *(const float4*)(Bp + (size_t)k0 * NDIM);
        As[acol + 0][arow] = av.x;
        As[acol + 1][arow] = av.y;
        As[acol + 2][arow] = av.z;
        As[acol + 3][arow] = av.w;
        *(float4*)&Bs[brow][bcol] = bv;
        __syncthreads();

#pragma unroll
        for (int kk = 0; kk < 8; kk++) {
            float4 a0 = *(const float4*)&As[kk][ty * 8];
            float4 a1 = *(const float4*)&As[kk][ty * 8 + 4];
            float4 b0 = *(const float4*)&Bs[kk][tx * 8];
            float4 b1 = *(const float4*)&Bs[kk][tx * 8 + 4];
            float ar[8] = {a0.x, a0.y, a0.z, a0.w, a1.x, a1.y, a1.z, a1.w};
            float br[8] = {b0.x, b0.y, b0.z, b0.w, b1.x, b1.y, b1.z, b1.w};
#pragma unroll
            for (int i = 0; i < 8; i++)
#pragma unroll
                for (int j = 0; j < 8; j++) acc[i][j] += ar[i] * br[j];
        }
        __syncthreads();
    }

#pragma unroll
    for (int i = 0; i < 8; i++) {
        float* Cp = C + (size_t)(by * 128 + ty * 8 + i) * NDIM + bx * 128 + tx * 8;
        float4 c0 = make_float4(acc[i][0], acc[i][1], acc[i][2], acc[i][3]);
        float4 c1 = make_float4(acc[i][4], acc[i][5], acc[i][6], acc[i][7]);
        *(float4*)Cp = c0;
        *(float4*)(Cp + 4) = c1;
    }
}

struct Ptrs3 {
    const float* A0; const float* A1; const float* A2;
    const float* B0; const float* B1; const float* B2;
    float* C0; float* C1; float* C2;
};

__global__ __launch_bounds__(256) void sgemm3_kernel(Ptrs3 p)
{
    const float* A; const float* B; float* C;
    if (blockIdx.z == 0)      { A = p.A0; B = p.B0; C = p.C0; }
    else if (blockIdx.z == 1) { A = p.A1; B = p.B1; C = p.C1; }
    else                      { A = p.A2; B = p.B2; C = p.C2; }
    sgemm_body(A, B, C);
}

__global__ __launch_bounds__(256) void sgemm1_kernel(const float* __restrict__ A,
                                                     const float* __restrict__ B,
                                                     float* __restrict__ C)
{
    sgemm_body(A, B, C);
}

// ---------------------------------------------------------------------------
// Attention: for head h of batch b, q/k/v are the CONTIGUOUS 128x1024 row
// block [h*128, h*128+128) of the projection output viewed as [2048][64]
// (this reproduces the reference's raw reshape exactly).
// One thread owns one query row (q and o fully in registers). Softmax without
// max subtraction (scores are O(1) gaussian; exp safe in fp32).
// Output written pre-transposed: Co[b, s, h*64 + d] = ctx[b,h,s,d].
// ---------------------------------------------------------------------------
__global__ __launch_bounds__(128) void attn_kernel(const float* __restrict__ Qp,
                                                   const float* __restrict__ Kp,
                                                   const float* __restrict__ Vp,
                                                   float* __restrict__ Co)
{
    __shared__ float4 Ks[64 * 16];  // 64 keys x 64 floats = 16 KB
    __shared__ float4 Vs[64 * 16];

    const int tid = threadIdx.x;
    const int h = blockIdx.y;
    const int b = blockIdx.z;
    const int sq = blockIdx.x * 128 + tid;                 // query row 0..2047
    const size_t off = ((size_t)b * 2048 + h * 128) * 1024; // floats

    float4 q[16], o[16];
    const float4* qg = (const float4*)(Qp + off) + (size_t)sq * 16;
#pragma unroll
    for (int i = 0; i < 16; i++) {
        q[i] = qg[i];
        o[i] = make_float4(0.f, 0.f, 0.f, 0.f);
    }
    float l = 0.f;

    const float4* Kg = (const float4*)(Kp + off);
    const float4* Vg = (const float4*)(Vp + off);

    for (int kt = 0; kt < 32; kt++) {      // 32 tiles x 64 keys = 2048
        __syncthreads();
#pragma unroll
        for (int i = 0; i < 8; i++) {
            int idx = tid + i * 128;
            Ks[idx] = Kg[kt * 1024 + idx];
            Vs[idx] = Vg[kt * 1024 + idx];
        }
        __syncthreads();

        for (int j = 0; j < 64; j++) {
            const float4* kr = &Ks[j * 16];
            float s0 = 0.f, s1 = 0.f, s2 = 0.f, s3 = 0.f;
#pragma unroll
            for (int i = 0; i < 16; i++) {
                float4 kv = kr[i];
                s0 += q[i].x * kv.x;
                s1 += q[i].y * kv.y;
                s2 += q[i].z * kv.z;
                s3 += q[i].w * kv.w;
            }
            float p = __expf(((s0 + s1) + (s2 + s3)) * 0.125f);
            l += p;
            const float4* vr = &Vs[j * 16];
#pragma unroll
            for (int i = 0; i < 16; i++) {
                float4 vv = vr[i];
                o[i].x += p * vv.x;
                o[i].y += p * vv.y;
                o[i].z += p * vv.z;
                o[i].w += p * vv.w;
            }
        }
    }

    float inv = 1.0f / l;
    float4* outp = (float4*)(Co + ((size_t)(b * 2048 + sq)) * 1024 + h * 64);
#pragma unroll
    for (int i = 0; i < 16; i++) {
        float4 v = o[i];
        v.x *= inv; v.y *= inv; v.z *= inv; v.w *= inv;
        outp[i] = v;
    }
}

// ---------------------------------------------------------------------------
// Launch
// ---------------------------------------------------------------------------
extern "C" void kernel_launch(void* const* d_in, const int* in_sizes, int n_in,
                              void* d_out, int out_size)
{
    const float* Q  = (const float*)d_in[0];
    const float* K  = (const float*)d_in[1];
    const float* V  = (const float*)d_in[2];
    const float* WQ = (const float*)d_in[3];
    const float* WK = (const float*)d_in[4];
    const float* WV = (const float*)d_in[5];
    const float* Wf = (const float*)d_in[6];
    float* out = (float*)d_out;

    float *Qp, *Kp, *Vp, *Ctx;
    cudaGetSymbolAddress((void**)&Qp,  g_Qp);
    cudaGetSymbolAddress((void**)&Kp,  g_Kp);
    cudaGetSymbolAddress((void**)&Vp,  g_Vp);
    cudaGetSymbolAddress((void**)&Ctx, g_Ctx);

    Ptrs3 p;
    p.A0 = Q;  p.A1 = K;  p.A2 = V;
    p.B0 = WQ; p.B1 = WK; p.B2 = WV;
    p.C0 = Qp; p.C1 = Kp; p.C2 = Vp;

    dim3 gproj(NDIM / 128, MDIM / 128, 3);   // (8, 64, 3) = 1536 blocks
    sgemm3_kernel<<<gproj, 256>>>(p);

    dim3 gattn(16, 16, 4);                   // (q-tiles, H, B) = 1024 blocks
    attn_kernel<<<gattn, 128>>>(Qp, Kp, Vp, Ctx);

    dim3 gout(NDIM / 128, MDIM / 128);       // 512 blocks
    sgemm1_kernel<<<gout, 256>>>(Ctx, Wf, out);
}

// round 3
// speedup vs baseline: 1.2108x; 1.2108x over previous
#include <cuda_runtime.h>
#include <cstdint>

// Shapes (fixed): B=4, S=2048, D=1024, H=16, dk=64.
#define MDIM 8192
#define NDIM 1024
#define KDIM 1024

// ---------------------------------------------------------------------------
// Device scratch (allocation-free per harness rules)
// ---------------------------------------------------------------------------
__device__ float g_Qp[MDIM * NDIM];
__device__ float g_Kp[MDIM * NDIM];
__device__ float g_Vp[MDIM * NDIM];
__device__ float g_Ctx[MDIM * NDIM];
__device__ float g_WT[4 * 1024 * 1024];   // transposed weights WT[n][k]

// ---------------------------------------------------------------------------
// Helpers
// ---------------------------------------------------------------------------
__device__ __forceinline__ uint32_t smem_u32(const void* p) {
    uint32_t a;
    asm("{ .reg .u64 t; cvta.to.shared.u64 t, %1; cvt.u32.u64 %0, t; }"
        : "=r"(a) : "l"(p));
    return a;
}

__device__ __forceinline__ uint32_t tf32r(float x) {
    uint32_t u;
    asm("cvt.rna.tf32.f32 %0, %1;" : "=r"(u) : "f"(x));
    return u;
}

__device__ __forceinline__ void mma_tf32(float* c, uint32_t a0, uint32_t a1,
                                         uint32_t a2, uint32_t a3,
                                         uint32_t b0, uint32_t b1) {
    asm volatile(
        "mma.sync.aligned.m16n8k8.row.col.f32.tf32.tf32.f32 "
        "{%0,%1,%2,%3}, {%4,%5,%6,%7}, {%8,%9}, {%0,%1,%2,%3};"
        : "+f"(c[0]), "+f"(c[1]), "+f"(c[2]), "+f"(c[3])
        : "r"(a0), "r"(a1), "r"(a2), "r"(a3), "r"(b0), "r"(b1));
}

__device__ __forceinline__ void cp_async16(uint32_t dst, const void* src) {
    asm volatile("cp.async.cg.shared.global [%0], [%1], 16;"
                 :: "r"(dst), "l"(src) : "memory");
}
__device__ __forceinline__ void cp_commit() {
    asm volatile("cp.async.commit_group;" ::: "memory");
}
template <int N>
__device__ __forceinline__ void cp_wait() {
    asm volatile("cp.async.wait_group %0;" :: "n"(N) : "memory");
}

// ---------------------------------------------------------------------------
// Weight transpose: WT[z][n][k] = W[z][k][n]
// ---------------------------------------------------------------------------
struct TransArgs { const float* src[4]; float* dst; };

__global__ __launch_bounds__(256) void transpose4_kernel(TransArgs a)
{
    __shared__ float t[32][33];
    const int z = blockIdx.z;
    const float* W = a.src[z];
    float* D = a.dst + (size_t)z * 1024 * 1024;

    int x = blockIdx.x * 32 + threadIdx.x;
    int y0 = blockIdx.y * 32;
#pragma unroll
    for (int j = 0; j < 32; j += 8)
        t[threadIdx.y + j][threadIdx.x] = W[(size_t)(y0 + threadIdx.y + j) * 1024 + x];
    __syncthreads();
    int x2 = blockIdx.y * 32 + threadIdx.x;
    int y2 = blockIdx.x * 32;
#pragma unroll
    for (int j = 0; j < 32; j += 8)
        D[(size_t)(y2 + threadIdx.y + j) * 1024 + x2] = t[threadIdx.x][threadIdx.y + j];
}

// ---------------------------------------------------------------------------
// 3xtf32 mma.sync GEMM: C[M,N] = A[M,K] @ BT[N,K]^T
// CTA 128x128, 256 thr, 8 warps (2M x 4N), warp tile 64x32, K staged by 32,
// double-buffered cp.async smem.  Error ~ al*bl ~= 2^-22 (fp32-class).
// ---------------------------------------------------------------------------
#define BK 32
#define LDW 36                      // smem row stride (floats): conflict-free
#define TILE_F (128 * LDW)          // floats per tile (A or B)
#define STAGE_F (2 * TILE_F)        // A + B
#define GSMEM (2 * STAGE_F * 4)     // bytes, 2 stages = 73728

struct GemmArgs {
    const float* A[3];
    const float* BT[3];
    float* C[3];
};

__device__ __forceinline__ void gemm_load_stage(
    const float* __restrict__ Ab, const float* __restrict__ Bb,
    int s, uint32_t sA, uint32_t sB, int tid)
{
    // 128 rows x 32 floats = 1024 float4 per tile; 256 thr -> 4 each
#pragma unroll
    for (int i = 0; i < 4; i++) {
        int idx = tid + i * 256;
        int r = idx >> 3;
        int c4 = idx & 7;
        uint32_t doff = (uint32_t)(r * (LDW * 4) + c4 * 16);
        cp_async16(sA + doff, Ab + (size_t)r * KDIM + s * BK + c4 * 4);
        cp_async16(sB + doff, Bb + (size_t)r * KDIM + s * BK + c4 * 4);
    }
    cp_commit();
}

__global__ void __launch_bounds__(256, 1)
gemm_tf32x3_kernel(GemmArgs args)
{
    extern __shared__ float smem[];
    const int tid = threadIdx.x;
    const int lane = tid & 31;
    const int wid = tid >> 5;
    const int wm = wid >> 2;          // 0..1 -> M offset wm*64
    const int wn = wid & 3;           // 0..3 -> N offset wn*32
    const int z = blockIdx.z;

    const float* Ab = args.A[z] + (size_t)blockIdx.y * 128 * KDIM;
    const float* Bb = args.BT[z] + (size_t)blockIdx.x * 128 * KDIM;
    float* C = args.C[z];

    const uint32_t sbase = smem_u32(smem);
    const uint32_t sA0 = sbase;
    const uint32_t sB0 = sbase + TILE_F * 4;

    float acc[4][4][4];
#pragma unroll
    for (int i = 0; i < 4; i++)
#pragma unroll
        for (int j = 0; j < 4; j++)
#pragma unroll
            for (int k = 0; k < 4; k++) acc[i][j][k] = 0.0f;

    const int r0 = lane >> 2;          // 0..7
    const int c0 = lane & 3;           // 0..3

    gemm_load_stage(Ab, Bb, 0, sA0, sB0, tid);

    const int NST = KDIM / BK;         // 32
    for (int s = 0; s < NST; s++) {
        const int buf = s & 1;
        if (s + 1 < NST) {
            const int nb = (s + 1) & 1;
            gemm_load_stage(Ab, Bb, s + 1,
                            sA0 + nb * STAGE_F * 4, sB0 + nb * STAGE_F * 4, tid);
            cp_wait<1>();
        } else {
            cp_wait<0>();
        }
        __syncthreads();

        const float* As = smem + buf * STAGE_F;
        const float* Bs = As + TILE_F;

#pragma unroll
        for (int ks = 0; ks < BK / 8; ks++) {
            const int kc = ks * 8 + c0;
            // A fragments (hi/lo), 4 m-tiles
            uint32_t ah[4][4], al[4][4];
#pragma unroll
            for (int mt = 0; mt < 4; mt++) {
                const int mr = wm * 64 + mt * 16 + r0;
#pragma unroll
                for (int q = 0; q < 4; q++) {
                    const int rr = mr + (q & 1) * 8;
                    const int cc = kc + (q >> 1) * 4;
                    float v = As[rr * LDW + cc];
                    uint32_t h = tf32r(v);
                    ah[mt][q] = h;
                    al[mt][q] = tf32r(v - __uint_as_float(h));
                }
            }
            // B fragments (hi/lo), 4 n-tiles
            uint32_t bh[4][2], bl[4][2];
#pragma unroll
            for (int nt = 0; nt < 4; nt++) {
                const int nr = wn * 32 + nt * 8 + r0;
#pragma unroll
                for (int q = 0; q < 2; q++) {
                    float v = Bs[nr * LDW + kc + q * 4];
                    uint32_t h = tf32r(v);
                    bh[nt][q] = h;
                    bl[nt][q] = tf32r(v - __uint_as_float(h));
                }
            }
#pragma unroll
            for (int mt = 0; mt < 4; mt++)
#pragma unroll
                for (int nt = 0; nt < 4; nt++) {
                    float* c = acc[mt][nt];
                    mma_tf32(c, ah[mt][0], ah[mt][1], ah[mt][2], ah[mt][3],
                             bh[nt][0], bh[nt][1]);
                    mma_tf32(c, al[mt][0], al[mt][1], al[mt][2], al[mt][3],
                             bh[nt][0], bh[nt][1]);
                    mma_tf32(c, ah[mt][0], ah[mt][1], ah[mt][2], ah[mt][3],
                             bl[nt][0], bl[nt][1]);
                }
        }
        __syncthreads();
    }

    // Epilogue
    const size_t crow0 = (size_t)blockIdx.y * 128 + wm * 64;
    const size_t ccol0 = (size_t)blockIdx.x * 128 + wn * 32;
#pragma unroll
    for (int mt = 0; mt < 4; mt++) {
#pragma unroll
        for (int nt = 0; nt < 4; nt++) {
            const size_t row = crow0 + mt * 16 + r0;
            const size_t col = ccol0 + nt * 8 + c0 * 2;
            float* c = acc[mt][nt];
            *(float2*)(C + row * NDIM + col)       = make_float2(c[0], c[1]);
            *(float2*)(C + (row + 8) * NDIM + col) = make_float2(c[2], c[3]);
        }
    }
}

// ---------------------------------------------------------------------------
// Attention (verified, unchanged): per (b,h), q/k/v are the contiguous
// 128-row block of the projection output viewed as [2048][64].
// ---------------------------------------------------------------------------
__global__ __launch_bounds__(128) void attn_kernel(const float* __restrict__ Qp,
                                                   const float* __restrict__ Kp,
                                                   const float* __restrict__ Vp,
                                                   float* __restrict__ Co)
{
    __shared__ float4 Ks[64 * 16];
    __shared__ float4 Vs[64 * 16];

    const int tid = threadIdx.x;
    const int h = blockIdx.y;
    const int b = blockIdx.z;
    const int sq = blockIdx.x * 128 + tid;
    const size_t off = ((size_t)b * 2048 + h * 128) * 1024;

    float4 q[16], o[16];
    const float4* qg = (const float4*)(Qp + off) + (size_t)sq * 16;
#pragma unroll
    for (int i = 0; i < 16; i++) {
        q[i] = qg[i];
        o[i] = make_float4(0.f, 0.f, 0.f, 0.f);
    }
    float l = 0.f;

    const float4* Kg = (const float4*)(Kp + off);
    const float4* Vg = (const float4*)(Vp + off);

    for (int kt = 0; kt < 32; kt++) {
        __syncthreads();
#pragma unroll
        for (int i = 0; i < 8; i++) {
            int idx = tid + i * 128;
            Ks[idx] = Kg[kt * 1024 + idx];
            Vs[idx] = Vg[kt * 1024 + idx];
        }
        __syncthreads();

        for (int j = 0; j < 64; j++) {
            const float4* kr = &Ks[j * 16];
            float s0 = 0.f, s1 = 0.f, s2 = 0.f, s3 = 0.f;
#pragma unroll
            for (int i = 0; i < 16; i++) {
                float4 kv = kr[i];
                s0 += q[i].x * kv.x;
                s1 += q[i].y * kv.y;
                s2 += q[i].z * kv.z;
                s3 += q[i].w * kv.w;
            }
            float p = __expf(((s0 + s1) + (s2 + s3)) * 0.125f);
            l += p;
            const float4* vr = &Vs[j * 16];
#pragma unroll
            for (int i = 0; i < 16; i++) {
                float4 vv = vr[i];
                o[i].x += p * vv.x;
                o[i].y += p * vv.y;
                o[i].z += p * vv.z;
                o[i].w += p * vv.w;
            }
        }
    }

    float inv = 1.0f / l;
    float4* outp = (float4*)(Co + ((size_t)(b * 2048 + sq)) * 1024 + h * 64);
#pragma unroll
    for (int i = 0; i < 16; i++) {
        float4 v = o[i];
        v.x *= inv; v.y *= inv; v.z *= inv; v.w *= inv;
        outp[i] = v;
    }
}

// ---------------------------------------------------------------------------
// Launch
// ---------------------------------------------------------------------------
extern "C" void kernel_launch(void* const* d_in, const int* in_sizes, int n_in,
                              void* d_out, int out_size)
{
    const float* Q  = (const float*)d_in[0];
    const float* K  = (const float*)d_in[1];
    const float* V  = (const float*)d_in[2];
    const float* WQ = (const float*)d_in[3];
    const float* WK = (const float*)d_in[4];
    const float* WV = (const float*)d_in[5];
    const float* Wf = (const float*)d_in[6];
    float* out = (float*)d_out;

    float *Qp, *Kp, *Vp, *Ctx, *WT;
    cudaGetSymbolAddress((void**)&Qp,  g_Qp);
    cudaGetSymbolAddress((void**)&Kp,  g_Kp);
    cudaGetSymbolAddress((void**)&Vp,  g_Vp);
    cudaGetSymbolAddress((void**)&Ctx, g_Ctx);
    cudaGetSymbolAddress((void**)&WT,  g_WT);

    cudaFuncSetAttribute(gemm_tf32x3_kernel,
                         cudaFuncAttributeMaxDynamicSharedMemorySize, GSMEM);

    // 1) transpose the four weight matrices
    TransArgs t;
    t.src[0] = WQ; t.src[1] = WK; t.src[2] = WV; t.src[3] = Wf;
    t.dst = WT;
    transpose4_kernel<<<dim3(32, 32, 4), dim3(32, 8)>>>(t);

    // 2) Q/K/V projections
    GemmArgs g1;
    g1.A[0] = Q;  g1.A[1] = K;  g1.A[2] = V;
    g1.BT[0] = WT + 0 * 1024 * 1024;
    g1.BT[1] = WT + 1 * 1024 * 1024;
    g1.BT[2] = WT + 2 * 1024 * 1024;
    g1.C[0] = Qp; g1.C[1] = Kp; g1.C[2] = Vp;
    gemm_tf32x3_kernel<<<dim3(NDIM / 128, MDIM / 128, 3), 256, GSMEM>>>(g1);

    // 3) attention (fp32 SIMT, verified)
    attn_kernel<<<dim3(16, 16, 4), 128>>>(Qp, Kp, Vp, Ctx);

    // 4) output projection
    GemmArgs g2;
    g2.A[0] = Ctx; g2.A[1] = Ctx; g2.A[2] = Ctx;
    g2.BT[0] = WT + 3 * 1024 * 1024;
    g2.BT[1] = g2.BT[0]; g2.BT[2] = g2.BT[0];
    g2.C[0] = out; g2.C[1] = out; g2.C[2] = out;
    gemm_tf32x3_kernel<<<dim3(NDIM / 128, MDIM / 128, 1), 256, GSMEM>>>(g2);
}

// round 4
// speedup vs baseline: 2.1536x; 1.7787x over previous
#include <cuda_runtime.h>
#include <cstdint>

// Shapes (fixed): B=4, S=2048, D=1024, H=16, dk=64.
#define MDIM 8192
#define NDIM 1024
#define KDIM 1024

// ---------------------------------------------------------------------------
// Device scratch (allocation-free per harness rules)
// ---------------------------------------------------------------------------
__device__ float g_Qp[MDIM * NDIM];
__device__ float g_Kp[MDIM * NDIM];
__device__ float g_Vp[MDIM * NDIM];
__device__ float g_Ctx[MDIM * NDIM];
__device__ float g_WT[4 * 1024 * 1024];   // transposed weights WT[n][k]

// ---------------------------------------------------------------------------
// Helpers
// ---------------------------------------------------------------------------
__device__ __forceinline__ uint32_t smem_u32(const void* p) {
    uint32_t a;
    asm("{ .reg .u64 t; cvta.to.shared.u64 t, %1; cvt.u32.u64 %0, t; }"
        : "=r"(a) : "l"(p));
    return a;
}

__device__ __forceinline__ uint32_t tf32r(float x) {
    uint32_t u;
    asm("cvt.rna.tf32.f32 %0, %1;" : "=r"(u) : "f"(x));
    return u;
}

__device__ __forceinline__ void mma_tf32(float* c, uint32_t a0, uint32_t a1,
                                         uint32_t a2, uint32_t a3,
                                         uint32_t b0, uint32_t b1) {
    asm volatile(
        "mma.sync.aligned.m16n8k8.row.col.f32.tf32.tf32.f32 "
        "{%0,%1,%2,%3}, {%4,%5,%6,%7}, {%8,%9}, {%0,%1,%2,%3};"
        : "+f"(c[0]), "+f"(c[1]), "+f"(c[2]), "+f"(c[3])
        : "r"(a0), "r"(a1), "r"(a2), "r"(a3), "r"(b0), "r"(b1));
}

__device__ __forceinline__ void cp_async16(uint32_t dst, const void* src) {
    asm volatile("cp.async.cg.shared.global [%0], [%1], 16;"
                 :: "r"(dst), "l"(src) : "memory");
}
__device__ __forceinline__ void cp_commit() {
    asm volatile("cp.async.commit_group;" ::: "memory");
}
template <int N>
__device__ __forceinline__ void cp_wait() {
    asm volatile("cp.async.wait_group %0;" :: "n"(N) : "memory");
}

// ---------------------------------------------------------------------------
// Weight transpose: WT[z][n][k] = W[z][k][n]
// ---------------------------------------------------------------------------
struct TransArgs { const float* src[4]; float* dst; };

__global__ __launch_bounds__(256) void transpose4_kernel(TransArgs a)
{
    __shared__ float t[32][33];
    const int z = blockIdx.z;
    const float* W = a.src[z];
    float* D = a.dst + (size_t)z * 1024 * 1024;

    int x = blockIdx.x * 32 + threadIdx.x;
    int y0 = blockIdx.y * 32;
#pragma unroll
    for (int j = 0; j < 32; j += 8)
        t[threadIdx.y + j][threadIdx.x] = W[(size_t)(y0 + threadIdx.y + j) * 1024 + x];
    __syncthreads();
    int x2 = blockIdx.y * 32 + threadIdx.x;
    int y2 = blockIdx.x * 32;
#pragma unroll
    for (int j = 0; j < 32; j += 8)
        D[(size_t)(y2 + threadIdx.y + j) * 1024 + x2] = t[threadIdx.x][threadIdx.y + j];
}

// ---------------------------------------------------------------------------
// 3xtf32 mma.sync GEMM (verified round 3): C[M,N] = A[M,K] @ BT[N,K]^T
// ---------------------------------------------------------------------------
#define BK 32
#define LDW 36
#define TILE_F (128 * LDW)
#define STAGE_F (2 * TILE_F)
#define GSMEM (2 * STAGE_F * 4)

struct GemmArgs {
    const float* A[3];
    const float* BT[3];
    float* C[3];
};

__device__ __forceinline__ void gemm_load_stage(
    const float* __restrict__ Ab, const float* __restrict__ Bb,
    int s, uint32_t sA, uint32_t sB, int tid)
{
#pragma unroll
    for (int i = 0; i < 4; i++) {
        int idx = tid + i * 256;
        int r = idx >> 3;
        int c4 = idx & 7;
        uint32_t doff = (uint32_t)(r * (LDW * 4) + c4 * 16);
        cp_async16(sA + doff, Ab + (size_t)r * KDIM + s * BK + c4 * 4);
        cp_async16(sB + doff, Bb + (size_t)r * KDIM + s * BK + c4 * 4);
    }
    cp_commit();
}

__global__ void __launch_bounds__(256, 1)
gemm_tf32x3_kernel(GemmArgs args)
{
    extern __shared__ float smem[];
    const int tid = threadIdx.x;
    const int lane = tid & 31;
    const int wid = tid >> 5;
    const int wm = wid >> 2;
    const int wn = wid & 3;
    const int z = blockIdx.z;

    const float* Ab = args.A[z] + (size_t)blockIdx.y * 128 * KDIM;
    const float* Bb = args.BT[z] + (size_t)blockIdx.x * 128 * KDIM;
    float* C = args.C[z];

    const uint32_t sbase = smem_u32(smem);
    const uint32_t sA0 = sbase;
    const uint32_t sB0 = sbase + TILE_F * 4;

    float acc[4][4][4];
#pragma unroll
    for (int i = 0; i < 4; i++)
#pragma unroll
        for (int j = 0; j < 4; j++)
#pragma unroll
            for (int k = 0; k < 4; k++) acc[i][j][k] = 0.0f;

    const int r0 = lane >> 2;
    const int c0 = lane & 3;

    gemm_load_stage(Ab, Bb, 0, sA0, sB0, tid);

    const int NST = KDIM / BK;
    for (int s = 0; s < NST; s++) {
        const int buf = s & 1;
        if (s + 1 < NST) {
            const int nb = (s + 1) & 1;
            gemm_load_stage(Ab, Bb, s + 1,
                            sA0 + nb * STAGE_F * 4, sB0 + nb * STAGE_F * 4, tid);
            cp_wait<1>();
        } else {
            cp_wait<0>();
        }
        __syncthreads();

        const float* As = smem + buf * STAGE_F;
        const float* Bs = As + TILE_F;

#pragma unroll
        for (int ks = 0; ks < BK / 8; ks++) {
            const int kc = ks * 8 + c0;
            uint32_t ah[4][4], al[4][4];
#pragma unroll
            for (int mt = 0; mt < 4; mt++) {
                const int mr = wm * 64 + mt * 16 + r0;
#pragma unroll
                for (int q = 0; q < 4; q++) {
                    const int rr = mr + (q & 1) * 8;
                    const int cc = kc + (q >> 1) * 4;
                    float v = As[rr * LDW + cc];
                    uint32_t h = tf32r(v);
                    ah[mt][q] = h;
                    al[mt][q] = tf32r(v - __uint_as_float(h));
                }
            }
            uint32_t bh[4][2], bl[4][2];
#pragma unroll
            for (int nt = 0; nt < 4; nt++) {
                const int nr = wn * 32 + nt * 8 + r0;
#pragma unroll
                for (int q = 0; q < 2; q++) {
                    float v = Bs[nr * LDW + kc + q * 4];
                    uint32_t h = tf32r(v);
                    bh[nt][q] = h;
                    bl[nt][q] = tf32r(v - __uint_as_float(h));
                }
            }
#pragma unroll
            for (int mt = 0; mt < 4; mt++)
#pragma unroll
                for (int nt = 0; nt < 4; nt++) {
                    float* c = acc[mt][nt];
                    mma_tf32(c, ah[mt][0], ah[mt][1], ah[mt][2], ah[mt][3],
                             bh[nt][0], bh[nt][1]);
                    mma_tf32(c, al[mt][0], al[mt][1], al[mt][2], al[mt][3],
                             bh[nt][0], bh[nt][1]);
                    mma_tf32(c, ah[mt][0], ah[mt][1], ah[mt][2], ah[mt][3],
                             bl[nt][0], bl[nt][1]);
                }
        }
        __syncthreads();
    }

    const size_t crow0 = (size_t)blockIdx.y * 128 + wm * 64;
    const size_t ccol0 = (size_t)blockIdx.x * 128 + wn * 32;
#pragma unroll
    for (int mt = 0; mt < 4; mt++) {
#pragma unroll
        for (int nt = 0; nt < 4; nt++) {
            const size_t row = crow0 + mt * 16 + r0;
            const size_t col = ccol0 + nt * 8 + c0 * 2;
            float* c = acc[mt][nt];
            *(float2*)(C + row * NDIM + col)       = make_float2(c[0], c[1]);
            *(float2*)(C + (row + 8) * NDIM + col) = make_float2(c[2], c[3]);
        }
    }
}

// ---------------------------------------------------------------------------
// Tensor-core attention (mma.sync tf32).
// CTA = 128 queries of one (b,h). 8 warps x 16 query rows each.
// Streams K/V in 64-key tiles (cp.async double-buffered).
// QK^T: 2-pass (Q hi/lo split, K single tf32-RN).  PV: single-pass tf32-RN.
// Softmax without max subtraction (verified R1). P re-fragmented via per-warp
// smem scratch. Strides chosen conflict-free: K=68, V=72, P=68.
// ---------------------------------------------------------------------------
#define AKS 68
#define AVS 72
#define APS 68
#define AOFF_K 0
#define AOFF_V (2 * 64 * AKS)                  // 8704
#define AOFF_P (AOFF_V + 2 * 64 * AVS)         // 17920
#define ASMEM_F (AOFF_P + 8 * 16 * APS)        // 26624 floats
#define ASMEM_BYTES (ASMEM_F * 4)              // 106496 B

__device__ __forceinline__ void attn_load_kv(
    const float* __restrict__ Kg, const float* __restrict__ Vg,
    int t, int buf, uint32_t sb, int tid)
{
    const uint32_t kb = sb + (AOFF_K + buf * 64 * AKS) * 4;
    const uint32_t vb = sb + (AOFF_V + buf * 64 * AVS) * 4;
#pragma unroll
    for (int i = 0; i < 4; i++) {
        int idx = tid + i * 256;
        int r = idx >> 4;            // 0..63 key row
        int c4 = idx & 15;           // 16B chunk
        const float* src = Kg + (size_t)(t * 64 + r) * 64 + c4 * 4;
        cp_async16(kb + (uint32_t)(r * AKS + c4 * 4) * 4, src);
        const float* srcv = Vg + (size_t)(t * 64 + r) * 64 + c4 * 4;
        cp_async16(vb + (uint32_t)(r * AVS + c4 * 4) * 4, srcv);
    }
    cp_commit();
}

__global__ void __launch_bounds__(256, 1)
attn_mma_kernel(const float* __restrict__ Qp, const float* __restrict__ Kp,
                const float* __restrict__ Vp, float* __restrict__ Co)
{
    extern __shared__ float sm[];
    const int tid = threadIdx.x;
    const int lane = tid & 31;
    const int w = tid >> 5;
    const int r0 = lane >> 2;        // 0..7
    const int c0 = lane & 3;         // 0..3
    const int h = blockIdx.y;
    const int b = blockIdx.z;
    const int qbase = blockIdx.x * 128;
    const size_t off = ((size_t)b * 2048 + h * 128) * 1024;  // head block, [2048][64]

    const float* Qg = Qp + off;
    const float* Kg = Kp + off;
    const float* Vg = Vp + off;
    const uint32_t sb = smem_u32(sm);

    // Q fragments (hi/lo), rows w*16 + r0 (+8), cols kg*8 + c0 (+4)
    uint32_t qh[8][4], ql[8][4];
#pragma unroll
    for (int kg = 0; kg < 8; kg++)
#pragma unroll
        for (int qi = 0; qi < 4; qi++) {
            int row = qbase + w * 16 + r0 + (qi & 1) * 8;
            int col = kg * 8 + c0 + (qi >> 1) * 4;
            float v = Qg[(size_t)row * 64 + col];
            uint32_t hb = tf32r(v);
            qh[kg][qi] = hb;
            ql[kg][qi] = tf32r(v - __uint_as_float(hb));
        }

    float oacc[8][4];
#pragma unroll
    for (int nt = 0; nt < 8; nt++)
#pragma unroll
        for (int j = 0; j < 4; j++) oacc[nt][j] = 0.0f;
    float ls0 = 0.f, ls1 = 0.f;

    attn_load_kv(Kg, Vg, 0, 0, sb, tid);

    float* Psw = sm + AOFF_P + w * 16 * APS;

    for (int t = 0; t < 32; t++) {
        const int buf = t & 1;
        if (t + 1 < 32) {
            attn_load_kv(Kg, Vg, t + 1, (t + 1) & 1, sb, tid);
            cp_wait<1>();
        } else {
            cp_wait<0>();
        }
        __syncthreads();

        const float* Ks = sm + AOFF_K + buf * 64 * AKS;
        const float* Vs = sm + AOFF_V + buf * 64 * AVS;

        // ---- S = Q @ K^T (2-pass) ----
        float sacc[8][4];
#pragma unroll
        for (int nt = 0; nt < 8; nt++)
#pragma unroll
            for (int j = 0; j < 4; j++) sacc[nt][j] = 0.0f;

#pragma unroll
        for (int kg = 0; kg < 8; kg++) {
            uint32_t bk[8][2];
#pragma unroll
            for (int nt = 0; nt < 8; nt++) {
                const float* kp = Ks + (nt * 8 + r0) * AKS + kg * 8 + c0;
                bk[nt][0] = tf32r(kp[0]);
                bk[nt][1] = tf32r(kp[4]);
            }
#pragma unroll
            for (int nt = 0; nt < 8; nt++)
                mma_tf32(sacc[nt], qh[kg][0], qh[kg][1], qh[kg][2], qh[kg][3],
                         bk[nt][0], bk[nt][1]);
#pragma unroll
            for (int nt = 0; nt < 8; nt++)
                mma_tf32(sacc[nt], ql[kg][0], ql[kg][1], ql[kg][2], ql[kg][3],
                         bk[nt][0], bk[nt][1]);
        }

        // ---- P = exp(S/8), tf32-rounded; accumulate row sums; stash in smem ----
#pragma unroll
        for (int nt = 0; nt < 8; nt++) {
            float p0 = __uint_as_float(tf32r(__expf(sacc[nt][0] * 0.125f)));
            float p1 = __uint_as_float(tf32r(__expf(sacc[nt][1] * 0.125f)));
            float p2 = __uint_as_float(tf32r(__expf(sacc[nt][2] * 0.125f)));
            float p3 = __uint_as_float(tf32r(__expf(sacc[nt][3] * 0.125f)));
            ls0 += p0 + p1;
            ls1 += p2 + p3;
            *(float2*)(Psw + r0 * APS + nt * 8 + 2 * c0)       = make_float2(p0, p1);
            *(float2*)(Psw + (r0 + 8) * APS + nt * 8 + 2 * c0) = make_float2(p2, p3);
        }
        __syncwarp();

        // ---- O += P @ V ----
#pragma unroll
        for (int kg = 0; kg < 8; kg++) {
            uint32_t pa[4];
            pa[0] = __float_as_uint(Psw[r0 * APS + kg * 8 + c0]);
            pa[1] = __float_as_uint(Psw[(r0 + 8) * APS + kg * 8 + c0]);
            pa[2] = __float_as_uint(Psw[r0 * APS + kg * 8 + c0 + 4]);
            pa[3] = __float_as_uint(Psw[(r0 + 8) * APS + kg * 8 + c0 + 4]);
#pragma unroll
            for (int nt = 0; nt < 8; nt++) {
                uint32_t b0 = tf32r(Vs[(kg * 8 + c0) * AVS + nt * 8 + r0]);
                uint32_t b1 = tf32r(Vs[(kg * 8 + c0 + 4) * AVS + nt * 8 + r0]);
                mma_tf32(oacc[nt], pa[0], pa[1], pa[2], pa[3], b0, b1);
            }
        }
        __syncthreads();
    }

    // reduce l over the quad (lanes sharing r0)
    ls0 += __shfl_xor_sync(0xffffffffu, ls0, 1);
    ls0 += __shfl_xor_sync(0xffffffffu, ls0, 2);
    ls1 += __shfl_xor_sync(0xffffffffu, ls1, 1);
    ls1 += __shfl_xor_sync(0xffffffffu, ls1, 2);
    const float inv0 = 1.0f / ls0;
    const float inv1 = 1.0f / ls1;

    // write ctx: Co[b][q][h*64 + d]
    const int row0 = qbase + w * 16 + r0;
#pragma unroll
    for (int nt = 0; nt < 8; nt++) {
        const int col = h * 64 + nt * 8 + 2 * c0;
        *(float2*)(Co + ((size_t)(b * 2048 + row0)) * 1024 + col) =
            make_float2(oacc[nt][0] * inv0, oacc[nt][1] * inv0);
        *(float2*)(Co + ((size_t)(b * 2048 + row0 + 8)) * 1024 + col) =
            make_float2(oacc[nt][2] * inv1, oacc[nt][3] * inv1);
    }
}

// ---------------------------------------------------------------------------
// Launch
// ---------------------------------------------------------------------------
extern "C" void kernel_launch(void* const* d_in, const int* in_sizes, int n_in,
                              void* d_out, int out_size)
{
    const float* Q  = (const float*)d_in[0];
    const float* K  = (const float*)d_in[1];
    const float* V  = (const float*)d_in[2];
    const float* WQ = (const float*)d_in[3];
    const float* WK = (const float*)d_in[4];
    const float* WV = (const float*)d_in[5];
    const float* Wf = (const float*)d_in[6];
    float* out = (float*)d_out;

    float *Qp, *Kp, *Vp, *Ctx, *WT;
    cudaGetSymbolAddress((void**)&Qp,  g_Qp);
    cudaGetSymbolAddress((void**)&Kp,  g_Kp);
    cudaGetSymbolAddress((void**)&Vp,  g_Vp);
    cudaGetSymbolAddress((void**)&Ctx, g_Ctx);
    cudaGetSymbolAddress((void**)&WT,  g_WT);

    cudaFuncSetAttribute(gemm_tf32x3_kernel,
                         cudaFuncAttributeMaxDynamicSharedMemorySize, GSMEM);
    cudaFuncSetAttribute(attn_mma_kernel,
                         cudaFuncAttributeMaxDynamicSharedMemorySize, ASMEM_BYTES);

    // 1) transpose the four weight matrices
    TransArgs t;
    t.src[0] = WQ; t.src[1] = WK; t.src[2] = WV; t.src[3] = Wf;
    t.dst = WT;
    transpose4_kernel<<<dim3(32, 32, 4), dim3(32, 8)>>>(t);

    // 2) Q/K/V projections
    GemmArgs g1;
    g1.A[0] = Q;  g1.A[1] = K;  g1.A[2] = V;
    g1.BT[0] = WT + 0 * 1024 * 1024;
    g1.BT[1] = WT + 1 * 1024 * 1024;
    g1.BT[2] = WT + 2 * 1024 * 1024;
    g1.C[0] = Qp; g1.C[1] = Kp; g1.C[2] = Vp;
    gemm_tf32x3_kernel<<<dim3(NDIM / 128, MDIM / 128, 3), 256, GSMEM>>>(g1);

    // 3) attention (tensor cores)
    attn_mma_kernel<<<dim3(16, 16, 4), 256, ASMEM_BYTES>>>(Qp, Kp, Vp, Ctx);

    // 4) output projection
    GemmArgs g2;
    g2.A[0] = Ctx; g2.A[1] = Ctx; g2.A[2] = Ctx;
    g2.BT[0] = WT + 3 * 1024 * 1024;
    g2.BT[1] = g2.BT[0]; g2.BT[2] = g2.BT[0];
    g2.C[0] = out; g2.C[1] = out; g2.C[2] = out;
    gemm_tf32x3_kernel<<<dim3(NDIM / 128, MDIM / 128, 1), 256, GSMEM>>>(g2);
}

// round 5
// speedup vs baseline: 2.6513x; 1.2311x over previous
#include <cuda_runtime.h>
#include <cuda_bf16.h>
#include <cstdint>

// Shapes (fixed): B=4, S=2048, D=1024, H=16, dk=64.
#define MDIM 8192
#define NDIM 1024
#define KDIM 1024

// ---------------------------------------------------------------------------
// Device scratch (allocation-free per harness rules)
// ---------------------------------------------------------------------------
__device__ float g_Qp[MDIM * NDIM];
__device__ float g_Kp[MDIM * NDIM];
__device__ float g_Vp[MDIM * NDIM];
__device__ float g_Ctx[MDIM * NDIM];
__device__ __nv_bfloat16 g_Xh[3][MDIM * NDIM];   // split activations (hi)
__device__ __nv_bfloat16 g_Xl[3][MDIM * NDIM];   // split activations (lo)
__device__ __nv_bfloat16 g_WTh[4][NDIM * KDIM];  // transposed+split weights (hi)
__device__ __nv_bfloat16 g_WTl[4][NDIM * KDIM];  // transposed+split weights (lo)

// ---------------------------------------------------------------------------
// Helpers
// ---------------------------------------------------------------------------
__device__ __forceinline__ uint32_t smem_u32(const void* p) {
    uint32_t a;
    asm("{ .reg .u64 t; cvta.to.shared.u64 t, %1; cvt.u32.u64 %0, t; }"
        : "=r"(a) : "l"(p));
    return a;
}

__device__ __forceinline__ uint32_t tf32r(float x) {
    uint32_t u;
    asm("cvt.rna.tf32.f32 %0, %1;" : "=r"(u) : "f"(x));
    return u;
}

__device__ __forceinline__ void bsplit(float x, __nv_bfloat16& h, __nv_bfloat16& l) {
    h = __float2bfloat16_rn(x);
    l = __float2bfloat16_rn(x - __bfloat162float(h));
}

__device__ __forceinline__ void mma_tf32(float* c, uint32_t a0, uint32_t a1,
                                         uint32_t a2, uint32_t a3,
                                         uint32_t b0, uint32_t b1) {
    asm volatile(
        "mma.sync.aligned.m16n8k8.row.col.f32.tf32.tf32.f32 "
        "{%0,%1,%2,%3}, {%4,%5,%6,%7}, {%8,%9}, {%0,%1,%2,%3};"
        : "+f"(c[0]), "+f"(c[1]), "+f"(c[2]), "+f"(c[3])
        : "r"(a0), "r"(a1), "r"(a2), "r"(a3), "r"(b0), "r"(b1));
}

__device__ __forceinline__ void mma_bf16(float* c, const uint32_t* a,
                                         uint32_t b0, uint32_t b1) {
    asm volatile(
        "mma.sync.aligned.m16n8k16.row.col.f32.bf16.bf16.f32 "
        "{%0,%1,%2,%3}, {%4,%5,%6,%7}, {%8,%9}, {%0,%1,%2,%3};"
        : "+f"(c[0]), "+f"(c[1]), "+f"(c[2]), "+f"(c[3])
        : "r"(a[0]), "r"(a[1]), "r"(a[2]), "r"(a[3]), "r"(b0), "r"(b1));
}

__device__ __forceinline__ void cp_async16(uint32_t dst, const void* src) {
    asm volatile("cp.async.cg.shared.global [%0], [%1], 16;"
                 :: "r"(dst), "l"(src) : "memory");
}
__device__ __forceinline__ void cp_commit() {
    asm volatile("cp.async.commit_group;" ::: "memory");
}
template <int N>
__device__ __forceinline__ void cp_wait() {
    asm volatile("cp.async.wait_group %0;" :: "n"(N) : "memory");
}

// ---------------------------------------------------------------------------
// Prepass 1: weight transpose + bf16 split: WTh/WTl[z][n][k] = split(W[z][k][n])
// ---------------------------------------------------------------------------
struct TransArgs { const float* src[4]; __nv_bfloat16* dh; __nv_bfloat16* dl; };

__global__ __launch_bounds__(256) void transsplit4_kernel(TransArgs a)
{
    __shared__ float t[32][33];
    const int z = blockIdx.z;
    const float* W = a.src[z];
    __nv_bfloat16* Dh = a.dh + (size_t)z * NDIM * KDIM;
    __nv_bfloat16* Dl = a.dl + (size_t)z * NDIM * KDIM;

    int x = blockIdx.x * 32 + threadIdx.x;
    int y0 = blockIdx.y * 32;
#pragma unroll
    for (int j = 0; j < 32; j += 8)
        t[threadIdx.y + j][threadIdx.x] = W[(size_t)(y0 + threadIdx.y + j) * 1024 + x];
    __syncthreads();
    int x2 = blockIdx.y * 32 + threadIdx.x;
    int y2 = blockIdx.x * 32;
#pragma unroll
    for (int j = 0; j < 32; j += 8) {
        float v = t[threadIdx.x][threadIdx.y + j];
        __nv_bfloat16 h, l;
        bsplit(v, h, l);
        Dh[(size_t)(y2 + threadIdx.y + j) * 1024 + x2] = h;
        Dl[(size_t)(y2 + threadIdx.y + j) * 1024 + x2] = l;
    }
}

// ---------------------------------------------------------------------------
// Prepass 2: elementwise bf16 split of activations
// ---------------------------------------------------------------------------
struct SplitArgs { const float* src[3]; __nv_bfloat16* dh[3]; __nv_bfloat16* dl[3]; };

__global__ __launch_bounds__(256) void split_kernel(SplitArgs a)
{
    const int z = blockIdx.z;
    const float* X = a.src[z];
    __nv_bfloat16* H = a.dh[z];
    __nv_bfloat16* L = a.dl[z];
    size_t i = ((size_t)blockIdx.x * 256 + threadIdx.x) * 4;
    if (i >= (size_t)MDIM * NDIM) return;
    float4 v = *(const float4*)(X + i);
    __nv_bfloat16 h[4], l[4];
    bsplit(v.x, h[0], l[0]);
    bsplit(v.y, h[1], l[1]);
    bsplit(v.z, h[2], l[2]);
    bsplit(v.w, h[3], l[3]);
    *(uint2*)(H + i) = *(uint2*)h;
    *(uint2*)(L + i) = *(uint2*)l;
}

// ---------------------------------------------------------------------------
// 3xbf16 mma.sync GEMM: C[M,N] = A[M,K] @ BT[N,K]^T, operands pre-split.
// CTA 128x128, 512 thr, 16 warps (4M x 4N), warp tile 32x32, BK=32,
// double-buffered cp.async. Passes: ah*bh + al*bh + ah*bl.
// Smem tile: 128 rows x 16 k-words (20-word stride) per half-operand.
// ---------------------------------------------------------------------------
#define WROW 20                       // words per smem row (40 bf16)
#define TILEW (128 * WROW)            // 2560 words per tile
#define STW (4 * TILEW)               // stage: Ah, Al, Bh, Bl = 10240 words
#define GSMEM (2 * STW * 4)           // 81920 bytes

struct GemmArgsB {
    const __nv_bfloat16 *Ah[3], *Al[3], *Bh[3], *Bl[3];
    float* C[3];
};

__device__ __forceinline__ void gemm_load_stage(
    const __nv_bfloat16* __restrict__ Ah, const __nv_bfloat16* __restrict__ Al,
    const __nv_bfloat16* __restrict__ Bh, const __nv_bfloat16* __restrict__ Bl,
    int s, uint32_t sbase, int tid)
{
    const int r = tid >> 2;            // 0..127
    const int c16 = tid & 3;           // 16B chunk (8 bf16)
    const uint32_t doff = (uint32_t)(r * WROW + c16 * 4) * 4;
    const size_t goff = (size_t)r * KDIM + s * 32 + c16 * 8;
    cp_async16(sbase + doff,                 Ah + goff);
    cp_async16(sbase + TILEW * 4 + doff,     Al + goff);
    cp_async16(sbase + 2 * TILEW * 4 + doff, Bh + goff);
    cp_async16(sbase + 3 * TILEW * 4 + doff, Bl + goff);
    cp_commit();
}

__global__ void __launch_bounds__(512, 1)
gemm_bf16x3_kernel(GemmArgsB args)
{
    extern __shared__ uint32_t sw[];
    const int tid = threadIdx.x;
    const int lane = tid & 31;
    const int wid = tid >> 5;          // 0..15
    const int wm = wid >> 2;           // 0..3 -> M offset wm*32
    const int wn = wid & 3;            // 0..3 -> N offset wn*32
    const int r0 = lane >> 2;
    const int c0 = lane & 3;
    const int z = blockIdx.z;

    const size_t aoff = (size_t)blockIdx.y * 128 * KDIM;
    const size_t boff = (size_t)blockIdx.x * 128 * KDIM;
    const __nv_bfloat16* Ah = args.Ah[z] + aoff;
    const __nv_bfloat16* Al = args.Al[z] + aoff;
    const __nv_bfloat16* Bh = args.Bh[z] + boff;
    const __nv_bfloat16* Bl = args.Bl[z] + boff;
    float* C = args.C[z];

    const uint32_t sbase = smem_u32(sw);

    float acc[2][4][4];
#pragma unroll
    for (int i = 0; i < 2; i++)
#pragma unroll
        for (int j = 0; j < 4; j++)
#pragma unroll
            for (int k = 0; k < 4; k++) acc[i][j][k] = 0.0f;

    gemm_load_stage(Ah, Al, Bh, Bl, 0, sbase, tid);

    const int NST = KDIM / 32;         // 32
    for (int s = 0; s < NST; s++) {
        const int buf = s & 1;
        if (s + 1 < NST) {
            gemm_load_stage(Ah, Al, Bh, Bl, s + 1,
                            sbase + ((s + 1) & 1) * STW * 4, tid);
            cp_wait<1>();
        } else {
            cp_wait<0>();
        }
        __syncthreads();

        const uint32_t* St = sw + buf * STW;

#pragma unroll
        for (int ks = 0; ks < 2; ks++) {
            uint32_t ah[2][4], al[2][4];
#pragma unroll
            for (int mt = 0; mt < 2; mt++) {
                const int row = wm * 32 + mt * 16 + r0;
                const int base = row * WROW + ks * 8 + c0;
                ah[mt][0] = St[base];
                ah[mt][1] = St[base + 8 * WROW];
                ah[mt][2] = St[base + 4];
                ah[mt][3] = St[base + 8 * WROW + 4];
                al[mt][0] = St[TILEW + base];
                al[mt][1] = St[TILEW + base + 8 * WROW];
                al[mt][2] = St[TILEW + base + 4];
                al[mt][3] = St[TILEW + base + 8 * WROW + 4];
            }
            uint32_t bh[4][2], bl[4][2];
#pragma unroll
            for (int nt = 0; nt < 4; nt++) {
                const int n = wn * 32 + nt * 8 + r0;
                const int base = n * WROW + ks * 8 + c0;
                bh[nt][0] = St[2 * TILEW + base];
                bh[nt][1] = St[2 * TILEW + base + 4];
                bl[nt][0] = St[3 * TILEW + base];
                bl[nt][1] = St[3 * TILEW + base + 4];
            }
#pragma unroll
            for (int mt = 0; mt < 2; mt++)
#pragma unroll
                for (int nt = 0; nt < 4; nt++) {
                    float* c = acc[mt][nt];
                    mma_bf16(c, ah[mt], bh[nt][0], bh[nt][1]);
                    mma_bf16(c, al[mt], bh[nt][0], bh[nt][1]);
                    mma_bf16(c, ah[mt], bl[nt][0], bl[nt][1]);
                }
        }
        __syncthreads();
    }

    const size_t crow0 = (size_t)blockIdx.y * 128 + wm * 32;
    const size_t ccol0 = (size_t)blockIdx.x * 128 + wn * 32;
#pragma unroll
    for (int mt = 0; mt < 2; mt++) {
#pragma unroll
        for (int nt = 0; nt < 4; nt++) {
            const size_t row = crow0 + mt * 16 + r0;
            const size_t col = ccol0 + nt * 8 + c0 * 2;
            float* c = acc[mt][nt];
            *(float2*)(C + row * NDIM + col)       = make_float2(c[0], c[1]);
            *(float2*)(C + (row + 8) * NDIM + col) = make_float2(c[2], c[3]);
        }
    }
}

// ---------------------------------------------------------------------------
// Tensor-core attention (verified round 4, unchanged).
// ---------------------------------------------------------------------------
#define AKS 68
#define AVS 72
#define APS 68
#define AOFF_K 0
#define AOFF_V (2 * 64 * AKS)
#define AOFF_P (AOFF_V + 2 * 64 * AVS)
#define ASMEM_F (AOFF_P + 8 * 16 * APS)
#define ASMEM_BYTES (ASMEM_F * 4)

__device__ __forceinline__ void attn_load_kv(
    const float* __restrict__ Kg, const float* __restrict__ Vg,
    int t, int buf, uint32_t sb, int tid)
{
    const uint32_t kb = sb + (AOFF_K + buf * 64 * AKS) * 4;
    const uint32_t vb = sb + (AOFF_V + buf * 64 * AVS) * 4;
#pragma unroll
    for (int i = 0; i < 4; i++) {
        int idx = tid + i * 256;
        int r = idx >> 4;
        int c4 = idx & 15;
        const float* src = Kg + (size_t)(t * 64 + r) * 64 + c4 * 4;
        cp_async16(kb + (uint32_t)(r * AKS + c4 * 4) * 4, src);
        const float* srcv = Vg + (size_t)(t * 64 + r) * 64 + c4 * 4;
        cp_async16(vb + (uint32_t)(r * AVS + c4 * 4) * 4, srcv);
    }
    cp_commit();
}

__global__ void __launch_bounds__(256, 1)
attn_mma_kernel(const float* __restrict__ Qp, const float* __restrict__ Kp,
                const float* __restrict__ Vp, float* __restrict__ Co)
{
    extern __shared__ float sm[];
    const int tid = threadIdx.x;
    const int lane = tid & 31;
    const int w = tid >> 5;
    const int r0 = lane >> 2;
    const int c0 = lane & 3;
    const int h = blockIdx.y;
    const int b = blockIdx.z;
    const int qbase = blockIdx.x * 128;
    const size_t off = ((size_t)b * 2048 + h * 128) * 1024;

    const float* Qg = Qp + off;
    const float* Kg = Kp + off;
    const float* Vg = Vp + off;
    const uint32_t sb = smem_u32(sm);

    uint32_t qh[8][4], ql[8][4];
#pragma unroll
    for (int kg = 0; kg < 8; kg++)
#pragma unroll
        for (int qi = 0; qi < 4; qi++) {
            int row = qbase + w * 16 + r0 + (qi & 1) * 8;
            int col = kg * 8 + c0 + (qi >> 1) * 4;
            float v = Qg[(size_t)row * 64 + col];
            uint32_t hb = tf32r(v);
            qh[kg][qi] = hb;
            ql[kg][qi] = tf32r(v - __uint_as_float(hb));
        }

    float oacc[8][4];
#pragma unroll
    for (int nt = 0; nt < 8; nt++)
#pragma unroll
        for (int j = 0; j < 4; j++) oacc[nt][j] = 0.0f;
    float ls0 = 0.f, ls1 = 0.f;

    attn_load_kv(Kg, Vg, 0, 0, sb, tid);

    float* Psw = sm + AOFF_P + w * 16 * APS;

    for (int t = 0; t < 32; t++) {
        const int buf = t & 1;
        if (t + 1 < 32) {
            attn_load_kv(Kg, Vg, t + 1, (t + 1) & 1, sb, tid);
            cp_wait<1>();
        } else {
            cp_wait<0>();
        }
        __syncthreads();

        const float* Ks = sm + AOFF_K + buf * 64 * AKS;
        const float* Vs = sm + AOFF_V + buf * 64 * AVS;

        float sacc[8][4];
#pragma unroll
        for (int nt = 0; nt < 8; nt++)
#pragma unroll
            for (int j = 0; j < 4; j++) sacc[nt][j] = 0.0f;

#pragma unroll
        for (int kg = 0; kg < 8; kg++) {
            uint32_t bk[8][2];
#pragma unroll
            for (int nt = 0; nt < 8; nt++) {
                const float* kp = Ks + (nt * 8 + r0) * AKS + kg * 8 + c0;
                bk[nt][0] = tf32r(kp[0]);
                bk[nt][1] = tf32r(kp[4]);
            }
#pragma unroll
            for (int nt = 0; nt < 8; nt++)
                mma_tf32(sacc[nt], qh[kg][0], qh[kg][1], qh[kg][2], qh[kg][3],
                         bk[nt][0], bk[nt][1]);
#pragma unroll
            for (int nt = 0; nt < 8; nt++)
                mma_tf32(sacc[nt], ql[kg][0], ql[kg][1], ql[kg][2], ql[kg][3],
                         bk[nt][0], bk[nt][1]);
        }

#pragma unroll
        for (int nt = 0; nt < 8; nt++) {
            float p0 = __uint_as_float(tf32r(__expf(sacc[nt][0] * 0.125f)));
            float p1 = __uint_as_float(tf32r(__expf(sacc[nt][1] * 0.125f)));
            float p2 = __uint_as_float(tf32r(__expf(sacc[nt][2] * 0.125f)));
            float p3 = __uint_as_float(tf32r(__expf(sacc[nt][3] * 0.125f)));
            ls0 += p0 + p1;
            ls1 += p2 + p3;
            *(float2*)(Psw + r0 * APS + nt * 8 + 2 * c0)       = make_float2(p0, p1);
            *(float2*)(Psw + (r0 + 8) * APS + nt * 8 + 2 * c0) = make_float2(p2, p3);
        }
        __syncwarp();

#pragma unroll
        for (int kg = 0; kg < 8; kg++) {
            uint32_t pa[4];
            pa[0] = __float_as_uint(Psw[r0 * APS + kg * 8 + c0]);
            pa[1] = __float_as_uint(Psw[(r0 + 8) * APS + kg * 8 + c0]);
            pa[2] = __float_as_uint(Psw[r0 * APS + kg * 8 + c0 + 4]);
            pa[3] = __float_as_uint(Psw[(r0 + 8) * APS + kg * 8 + c0 + 4]);
#pragma unroll
            for (int nt = 0; nt < 8; nt++) {
                uint32_t b0 = tf32r(Vs[(kg * 8 + c0) * AVS + nt * 8 + r0]);
                uint32_t b1 = tf32r(Vs[(kg * 8 + c0 + 4) * AVS + nt * 8 + r0]);
                mma_tf32(oacc[nt], pa[0], pa[1], pa[2], pa[3], b0, b1);
            }
        }
        __syncthreads();
    }

    ls0 += __shfl_xor_sync(0xffffffffu, ls0, 1);
    ls0 += __shfl_xor_sync(0xffffffffu, ls0, 2);
    ls1 += __shfl_xor_sync(0xffffffffu, ls1, 1);
    ls1 += __shfl_xor_sync(0xffffffffu, ls1, 2);
    const float inv0 = 1.0f / ls0;
    const float inv1 = 1.0f / ls1;

    const int row0 = qbase + w * 16 + r0;
#pragma unroll
    for (int nt = 0; nt < 8; nt++) {
        const int col = h * 64 + nt * 8 + 2 * c0;
        *(float2*)(Co + ((size_t)(b * 2048 + row0)) * 1024 + col) =
            make_float2(oacc[nt][0] * inv0, oacc[nt][1] * inv0);
        *(float2*)(Co + ((size_t)(b * 2048 + row0 + 8)) * 1024 + col) =
            make_float2(oacc[nt][2] * inv1, oacc[nt][3] * inv1);
    }
}

// ---------------------------------------------------------------------------
// Launch
// ---------------------------------------------------------------------------
extern "C" void kernel_launch(void* const* d_in, const int* in_sizes, int n_in,
                              void* d_out, int out_size)
{
    const float* Q  = (const float*)d_in[0];
    const float* K  = (const float*)d_in[1];
    const float* V  = (const float*)d_in[2];
    const float* WQ = (const float*)d_in[3];
    const float* WK = (const float*)d_in[4];
    const float* WV = (const float*)d_in[5];
    const float* Wf = (const float*)d_in[6];
    float* out = (float*)d_out;

    float *Qp, *Kp, *Vp, *Ctx;
    __nv_bfloat16 *Xh, *Xl, *WTh, *WTl;
    cudaGetSymbolAddress((void**)&Qp,  g_Qp);
    cudaGetSymbolAddress((void**)&Kp,  g_Kp);
    cudaGetSymbolAddress((void**)&Vp,  g_Vp);
    cudaGetSymbolAddress((void**)&Ctx, g_Ctx);
    cudaGetSymbolAddress((void**)&Xh,  g_Xh);
    cudaGetSymbolAddress((void**)&Xl,  g_Xl);
    cudaGetSymbolAddress((void**)&WTh, g_WTh);
    cudaGetSymbolAddress((void**)&WTl, g_WTl);

    cudaFuncSetAttribute(gemm_bf16x3_kernel,
                         cudaFuncAttributeMaxDynamicSharedMemorySize, GSMEM);
    cudaFuncSetAttribute(attn_mma_kernel,
                         cudaFuncAttributeMaxDynamicSharedMemorySize, ASMEM_BYTES);

    const size_t NEL = (size_t)MDIM * NDIM;

    // 1) weights: transpose + split
    TransArgs t;
    t.src[0] = WQ; t.src[1] = WK; t.src[2] = WV; t.src[3] = Wf;
    t.dh = WTh; t.dl = WTl;
    transsplit4_kernel<<<dim3(32, 32, 4), dim3(32, 8)>>>(t);

    // 2) activations: split Q, K, V
    SplitArgs sp;
    sp.src[0] = Q; sp.src[1] = K; sp.src[2] = V;
    for (int i = 0; i < 3; i++) { sp.dh[i] = Xh + i * NEL; sp.dl[i] = Xl + i * NEL; }
    split_kernel<<<dim3((unsigned)(NEL / 4 / 256), 1, 3), 256>>>(sp);

    // 3) Q/K/V projections (3xbf16 mma)
    GemmArgsB g1;
    for (int i = 0; i < 3; i++) {
        g1.Ah[i] = Xh + i * NEL;
        g1.Al[i] = Xl + i * NEL;
        g1.Bh[i] = WTh + (size_t)i * NDIM * KDIM;
        g1.Bl[i] = WTl + (size_t)i * NDIM * KDIM;
    }
    g1.C[0] = Qp; g1.C[1] = Kp; g1.C[2] = Vp;
    gemm_bf16x3_kernel<<<dim3(NDIM / 128, MDIM / 128, 3), 512, GSMEM>>>(g1);

    // 4) attention (verified)
    attn_mma_kernel<<<dim3(16, 16, 4), 256, ASMEM_BYTES>>>(Qp, Kp, Vp, Ctx);

    // 5) split Ctx (reuse slot 0)
    SplitArgs sp2;
    sp2.src[0] = Ctx; sp2.src[1] = Ctx; sp2.src[2] = Ctx;
    for (int i = 0; i < 3; i++) { sp2.dh[i] = Xh; sp2.dl[i] = Xl; }
    split_kernel<<<dim3((unsigned)(NEL / 4 / 256), 1, 1), 256>>>(sp2);

    // 6) output projection
    GemmArgsB g2;
    for (int i = 0; i < 3; i++) {
        g2.Ah[i] = Xh;
        g2.Al[i] = Xl;
        g2.Bh[i] = WTh + (size_t)3 * NDIM * KDIM;
        g2.Bl[i] = WTl + (size_t)3 * NDIM * KDIM;
        g2.C[i] = out;
    }
    gemm_bf16x3_kernel<<<dim3(NDIM / 128, MDIM / 128, 1), 512, GSMEM>>>(g2);
}

// round 6
// speedup vs baseline: 3.4615x; 1.3056x over previous
#include <cuda_runtime.h>
#include <cuda_bf16.h>
#include <cuda_fp16.h>
#include <cstdint>

// Shapes (fixed): B=4, S=2048, D=1024, H=16, dk=64.
#define MDIM 8192
#define NDIM 1024
#define KDIM 1024

// ---------------------------------------------------------------------------
// Device scratch (allocation-free per harness rules)
// ---------------------------------------------------------------------------
__device__ __nv_bfloat16 g_Xh[3][MDIM * NDIM];   // split activations (hi) for GEMM A
__device__ __nv_bfloat16 g_Xl[3][MDIM * NDIM];   // split activations (lo)
__device__ __nv_bfloat16 g_WTh[4][NDIM * KDIM];  // transposed+split weights (hi)
__device__ __nv_bfloat16 g_WTl[4][NDIM * KDIM];  // transposed+split weights (lo)
__device__ __half g_Qh[MDIM * NDIM];             // fp16 projections for attention
__device__ __half g_Ql[MDIM * NDIM];
__device__ __half g_Kh[MDIM * NDIM];
__device__ __half g_Vh[MDIM * NDIM];

// ---------------------------------------------------------------------------
// Helpers
// ---------------------------------------------------------------------------
__device__ __forceinline__ uint32_t smem_u32(const void* p) {
    uint32_t a;
    asm("{ .reg .u64 t; cvta.to.shared.u64 t, %1; cvt.u32.u64 %0, t; }"
        : "=r"(a) : "l"(p));
    return a;
}

__device__ __forceinline__ void bsplit(float x, __nv_bfloat16& h, __nv_bfloat16& l) {
    h = __float2bfloat16_rn(x);
    l = __float2bfloat16_rn(x - __bfloat162float(h));
}

__device__ __forceinline__ void mma_bf16(float* c, const uint32_t* a,
                                         uint32_t b0, uint32_t b1) {
    asm volatile(
        "mma.sync.aligned.m16n8k16.row.col.f32.bf16.bf16.f32 "
        "{%0,%1,%2,%3}, {%4,%5,%6,%7}, {%8,%9}, {%0,%1,%2,%3};"
        : "+f"(c[0]), "+f"(c[1]), "+f"(c[2]), "+f"(c[3])
        : "r"(a[0]), "r"(a[1]), "r"(a[2]), "r"(a[3]), "r"(b0), "r"(b1));
}

__device__ __forceinline__ void mma_f16(float* c, const uint32_t* a,
                                        uint32_t b0, uint32_t b1) {
    asm volatile(
        "mma.sync.aligned.m16n8k16.row.col.f32.f16.f16.f32 "
        "{%0,%1,%2,%3}, {%4,%5,%6,%7}, {%8,%9}, {%0,%1,%2,%3};"
        : "+f"(c[0]), "+f"(c[1]), "+f"(c[2]), "+f"(c[3])
        : "r"(a[0]), "r"(a[1]), "r"(a[2]), "r"(a[3]), "r"(b0), "r"(b1));
}

__device__ __forceinline__ void ldsm_x4(uint32_t& d0, uint32_t& d1,
                                        uint32_t& d2, uint32_t& d3, uint32_t a) {
    asm volatile("ldmatrix.sync.aligned.m8n8.x4.shared.b16 {%0,%1,%2,%3}, [%4];"
                 : "=r"(d0), "=r"(d1), "=r"(d2), "=r"(d3) : "r"(a));
}
__device__ __forceinline__ void ldsm_x4_t(uint32_t& d0, uint32_t& d1,
                                          uint32_t& d2, uint32_t& d3, uint32_t a) {
    asm volatile("ldmatrix.sync.aligned.m8n8.x4.trans.shared.b16 {%0,%1,%2,%3}, [%4];"
                 : "=r"(d0), "=r"(d1), "=r"(d2), "=r"(d3) : "r"(a));
}

__device__ __forceinline__ void cp_async16(uint32_t dst, const void* src) {
    asm volatile("cp.async.cg.shared.global [%0], [%1], 16;"
                 :: "r"(dst), "l"(src) : "memory");
}
__device__ __forceinline__ void cp_commit() {
    asm volatile("cp.async.commit_group;" ::: "memory");
}
template <int N>
__device__ __forceinline__ void cp_wait() {
    asm volatile("cp.async.wait_group %0;" :: "n"(N) : "memory");
}

// ---------------------------------------------------------------------------
// Prepass 1: weight transpose + bf16 split
// ---------------------------------------------------------------------------
struct TransArgs { const float* src[4]; __nv_bfloat16* dh; __nv_bfloat16* dl; };

__global__ __launch_bounds__(256) void transsplit4_kernel(TransArgs a)
{
    __shared__ float t[32][33];
    const int z = blockIdx.z;
    const float* W = a.src[z];
    __nv_bfloat16* Dh = a.dh + (size_t)z * NDIM * KDIM;
    __nv_bfloat16* Dl = a.dl + (size_t)z * NDIM * KDIM;

    int x = blockIdx.x * 32 + threadIdx.x;
    int y0 = blockIdx.y * 32;
#pragma unroll
    for (int j = 0; j < 32; j += 8)
        t[threadIdx.y + j][threadIdx.x] = W[(size_t)(y0 + threadIdx.y + j) * 1024 + x];
    __syncthreads();
    int x2 = blockIdx.y * 32 + threadIdx.x;
    int y2 = blockIdx.x * 32;
#pragma unroll
    for (int j = 0; j < 32; j += 8) {
        float v = t[threadIdx.x][threadIdx.y + j];
        __nv_bfloat16 h, l;
        bsplit(v, h, l);
        Dh[(size_t)(y2 + threadIdx.y + j) * 1024 + x2] = h;
        Dl[(size_t)(y2 + threadIdx.y + j) * 1024 + x2] = l;
    }
}

// ---------------------------------------------------------------------------
// Prepass 2: elementwise bf16 split of input activations
// ---------------------------------------------------------------------------
struct SplitArgs { const float* src[3]; __nv_bfloat16* dh[3]; __nv_bfloat16* dl[3]; };

__global__ __launch_bounds__(256) void split_kernel(SplitArgs a)
{
    const int z = blockIdx.z;
    const float* X = a.src[z];
    __nv_bfloat16* H = a.dh[z];
    __nv_bfloat16* L = a.dl[z];
    size_t i = ((size_t)blockIdx.x * 256 + threadIdx.x) * 4;
    if (i >= (size_t)MDIM * NDIM) return;
    float4 v = *(const float4*)(X + i);
    __nv_bfloat16 h[4], l[4];
    bsplit(v.x, h[0], l[0]);
    bsplit(v.y, h[1], l[1]);
    bsplit(v.z, h[2], l[2]);
    bsplit(v.w, h[3], l[3]);
    *(uint2*)(H + i) = *(uint2*)h;
    *(uint2*)(L + i) = *(uint2*)l;
}

// ---------------------------------------------------------------------------
// 3xbf16 mma.sync GEMM with selectable epilogue:
//   mode 0: C f32;  mode 1: D1=fp16(hi), D2=fp16(lo);  mode 2: D1=fp16
// ---------------------------------------------------------------------------
#define WROW 20
#define TILEW (128 * WROW)
#define STW (4 * TILEW)
#define GSMEM (2 * STW * 4)

struct GemmArgsB {
    const __nv_bfloat16 *Ah[3], *Al[3], *Bh[3], *Bl[3];
    float* C[3];
    __half* D1[3];
    __half* D2[3];
    int mode[3];
};

__device__ __forceinline__ void gemm_load_stage(
    const __nv_bfloat16* __restrict__ Ah, const __nv_bfloat16* __restrict__ Al,
    const __nv_bfloat16* __restrict__ Bh, const __nv_bfloat16* __restrict__ Bl,
    int s, uint32_t sbase, int tid)
{
    const int r = tid >> 2;
    const int c16 = tid & 3;
    const uint32_t doff = (uint32_t)(r * WROW + c16 * 4) * 4;
    const size_t goff = (size_t)r * KDIM + s * 32 + c16 * 8;
    cp_async16(sbase + doff,                 Ah + goff);
    cp_async16(sbase + TILEW * 4 + doff,     Al + goff);
    cp_async16(sbase + 2 * TILEW * 4 + doff, Bh + goff);
    cp_async16(sbase + 3 * TILEW * 4 + doff, Bl + goff);
    cp_commit();
}

__global__ void __launch_bounds__(512, 1)
gemm_bf16x3_kernel(GemmArgsB args)
{
    extern __shared__ uint32_t sw[];
    const int tid = threadIdx.x;
    const int lane = tid & 31;
    const int wid = tid >> 5;
    const int wm = wid >> 2;
    const int wn = wid & 3;
    const int r0 = lane >> 2;
    const int c0 = lane & 3;
    const int z = blockIdx.z;

    const size_t aoff = (size_t)blockIdx.y * 128 * KDIM;
    const size_t boff = (size_t)blockIdx.x * 128 * KDIM;
    const __nv_bfloat16* Ah = args.Ah[z] + aoff;
    const __nv_bfloat16* Al = args.Al[z] + aoff;
    const __nv_bfloat16* Bh = args.Bh[z] + boff;
    const __nv_bfloat16* Bl = args.Bl[z] + boff;

    const uint32_t sbase = smem_u32(sw);

    float acc[2][4][4];
#pragma unroll
    for (int i = 0; i < 2; i++)
#pragma unroll
        for (int j = 0; j < 4; j++)
#pragma unroll
            for (int k = 0; k < 4; k++) acc[i][j][k] = 0.0f;

    gemm_load_stage(Ah, Al, Bh, Bl, 0, sbase, tid);

    const int NST = KDIM / 32;
    for (int s = 0; s < NST; s++) {
        const int buf = s & 1;
        if (s + 1 < NST) {
            gemm_load_stage(Ah, Al, Bh, Bl, s + 1,
                            sbase + ((s + 1) & 1) * STW * 4, tid);
            cp_wait<1>();
        } else {
            cp_wait<0>();
        }
        __syncthreads();

        const uint32_t* St = sw + buf * STW;

#pragma unroll
        for (int ks = 0; ks < 2; ks++) {
            uint32_t ah[2][4], al[2][4];
#pragma unroll
            for (int mt = 0; mt < 2; mt++) {
                const int row = wm * 32 + mt * 16 + r0;
                const int base = row * WROW + ks * 8 + c0;
                ah[mt][0] = St[base];
                ah[mt][1] = St[base + 8 * WROW];
                ah[mt][2] = St[base + 4];
                ah[mt][3] = St[base + 8 * WROW + 4];
                al[mt][0] = St[TILEW + base];
                al[mt][1] = St[TILEW + base + 8 * WROW];
                al[mt][2] = St[TILEW + base + 4];
                al[mt][3] = St[TILEW + base + 8 * WROW + 4];
            }
            uint32_t bh[4][2], bl[4][2];
#pragma unroll
            for (int nt = 0; nt < 4; nt++) {
                const int n = wn * 32 + nt * 8 + r0;
                const int base = n * WROW + ks * 8 + c0;
                bh[nt][0] = St[2 * TILEW + base];
                bh[nt][1] = St[2 * TILEW + base + 4];
                bl[nt][0] = St[3 * TILEW + base];
                bl[nt][1] = St[3 * TILEW + base + 4];
            }
#pragma unroll
            for (int mt = 0; mt < 2; mt++)
#pragma unroll
                for (int nt = 0; nt < 4; nt++) {
                    float* c = acc[mt][nt];
                    mma_bf16(c, ah[mt], bh[nt][0], bh[nt][1]);
                    mma_bf16(c, al[mt], bh[nt][0], bh[nt][1]);
                    mma_bf16(c, ah[mt], bl[nt][0], bl[nt][1]);
                }
        }
        __syncthreads();
    }

    const int mode = args.mode[z];
    const size_t crow0 = (size_t)blockIdx.y * 128 + wm * 32;
    const size_t ccol0 = (size_t)blockIdx.x * 128 + wn * 32;
#pragma unroll
    for (int mt = 0; mt < 2; mt++) {
#pragma unroll
        for (int nt = 0; nt < 4; nt++) {
            const size_t row = crow0 + mt * 16 + r0;
            const size_t col = ccol0 + nt * 8 + c0 * 2;
            float* c = acc[mt][nt];
            if (mode == 0) {
                float* C = args.C[z];
                *(float2*)(C + row * NDIM + col)       = make_float2(c[0], c[1]);
                *(float2*)(C + (row + 8) * NDIM + col) = make_float2(c[2], c[3]);
            } else {
                __half* D1 = args.D1[z];
                __half2 h01 = __floats2half2_rn(c[0], c[1]);
                __half2 h23 = __floats2half2_rn(c[2], c[3]);
                *(__half2*)(D1 + row * NDIM + col)       = h01;
                *(__half2*)(D1 + (row + 8) * NDIM + col) = h23;
                if (mode == 1) {
                    __half* D2 = args.D2[z];
                    __half2 l01, l23;
                    l01.x = __float2half_rn(c[0] - __half2float(h01.x));
                    l01.y = __float2half_rn(c[1] - __half2float(h01.y));
                    l23.x = __float2half_rn(c[2] - __half2float(h23.x));
                    l23.y = __float2half_rn(c[3] - __half2float(h23.y));
                    *(__half2*)(D2 + row * NDIM + col)       = l01;
                    *(__half2*)(D2 + (row + 8) * NDIM + col) = l23;
                }
            }
        }
    }
}

// ---------------------------------------------------------------------------
// fp16 tensor-core attention.
// CTA = 128 queries of one (b,h); 8 warps x 16 query rows. 64-key tiles,
// double-buffered cp.async (fp16). QK^T: Q hi/lo fp16 x K fp16 (2 passes).
// PV: P fp16 x V fp16 via ldmatrix.trans. Error model identical to tf32 ver.
// Output written as bf16 hi/lo directly into out-proj A operands.
// ---------------------------------------------------------------------------
#define HKS 72                               // half stride per K/V smem row
#define HPS 72
#define HOFF_K 0
#define HOFF_V (2 * 64 * HKS)                // 9216 halfs
#define HOFF_P (HOFF_V + 2 * 64 * HKS)       // 18432
#define HSM_HALFS (HOFF_P + 8 * 16 * HPS)    // 27648
#define HSM_BYTES (HSM_HALFS * 2)            // 55296

__device__ __forceinline__ void attn_load_kv16(
    const __half* __restrict__ Kg, const __half* __restrict__ Vg,
    int t, int buf, uint32_t sb, int tid)
{
    const uint32_t kb = sb + (HOFF_K + buf * 64 * HKS) * 2;
    const uint32_t vb = sb + (HOFF_V + buf * 64 * HKS) * 2;
#pragma unroll
    for (int i = 0; i < 2; i++) {
        int idx = tid + i * 256;
        int r = idx >> 3;
        int c = idx & 7;
        const uint32_t doff = (uint32_t)(r * HKS + c * 8) * 2;
        cp_async16(kb + doff, Kg + (size_t)(t * 64 + r) * 64 + c * 8);
        cp_async16(vb + doff, Vg + (size_t)(t * 64 + r) * 64 + c * 8);
    }
    cp_commit();
}

__global__ void __launch_bounds__(256, 1)
attn_fp16_kernel(const __half* __restrict__ Qh, const __half* __restrict__ Ql,
                 const __half* __restrict__ Kh, const __half* __restrict__ Vh,
                 __nv_bfloat16* __restrict__ Oh, __nv_bfloat16* __restrict__ Ol)
{
    extern __shared__ __half hsm[];
    const int tid = threadIdx.x;
    const int lane = tid & 31;
    const int w = tid >> 5;
    const int r0 = lane >> 2;
    const int c0 = lane & 3;
    const int h = blockIdx.y;
    const int b = blockIdx.z;
    const int qbase = blockIdx.x * 128;
    const size_t off = ((size_t)b * 2048 + h * 128) * 1024;  // head block

    const __half* Qhg = Qh + off;
    const __half* Qlg = Ql + off;
    const __half* Kg = Kh + off;
    const __half* Vg = Vh + off;
    const uint32_t sb = smem_u32(hsm);

    // Q fragments (hi/lo), A-layout for m16n8k16
    uint32_t qfh[4][4], qfl[4][4];
    const int row0 = qbase + w * 16 + r0;
#pragma unroll
    for (int kg = 0; kg < 4; kg++)
#pragma unroll
        for (int q = 0; q < 4; q++) {
            int row = row0 + (q & 1) * 8;
            int col = kg * 16 + (q >> 1) * 8 + 2 * c0;
            qfh[kg][q] = *(const uint32_t*)(Qhg + (size_t)row * 64 + col);
            qfl[kg][q] = *(const uint32_t*)(Qlg + (size_t)row * 64 + col);
        }

    float oacc[8][4];
#pragma unroll
    for (int nt = 0; nt < 8; nt++)
#pragma unroll
        for (int j = 0; j < 4; j++) oacc[nt][j] = 0.0f;
    float ls0 = 0.f, ls1 = 0.f;

    attn_load_kv16(Kg, Vg, 0, 0, sb, tid);

    __half* Psw = hsm + HOFF_P + w * 16 * HPS;
    const uint32_t pwb = sb + (HOFF_P + w * 16 * HPS) * 2;

    for (int t = 0; t < 32; t++) {
        const int buf = t & 1;
        if (t + 1 < 32) {
            attn_load_kv16(Kg, Vg, t + 1, (t + 1) & 1, sb, tid);
            cp_wait<1>();
        } else {
            cp_wait<0>();
        }
        __syncthreads();

        const uint32_t kbase = sb + (HOFF_K + buf * 64 * HKS) * 2;
        const uint32_t vbase = sb + (HOFF_V + buf * 64 * HKS) * 2;

        // ---- S = Q @ K^T (2 passes: hi, lo) ----
        float sacc[8][4];
#pragma unroll
        for (int nt = 0; nt < 8; nt++)
#pragma unroll
            for (int j = 0; j < 4; j++) sacc[nt][j] = 0.0f;

#pragma unroll
        for (int nt = 0; nt < 8; nt++) {
            uint32_t bk[4][2];
#pragma unroll
            for (int p = 0; p < 2; p++) {
                // blocks: dims p*32 + j*8, rows nt*8 + (lane&7)
                uint32_t a = kbase +
                    (uint32_t)((nt * 8 + (lane & 7)) * HKS + p * 32 + (lane >> 3) * 8) * 2;
                ldsm_x4(bk[2 * p][0], bk[2 * p][1], bk[2 * p + 1][0], bk[2 * p + 1][1], a);
            }
#pragma unroll
            for (int kg = 0; kg < 4; kg++)
                mma_f16(sacc[nt], qfh[kg], bk[kg][0], bk[kg][1]);
#pragma unroll
            for (int kg = 0; kg < 4; kg++)
                mma_f16(sacc[nt], qfl[kg], bk[kg][0], bk[kg][1]);
        }

        // ---- P = exp(S/8) -> fp16 stash + row sums ----
#pragma unroll
        for (int nt = 0; nt < 8; nt++) {
            float p0 = __expf(sacc[nt][0] * 0.125f);
            float p1 = __expf(sacc[nt][1] * 0.125f);
            float p2 = __expf(sacc[nt][2] * 0.125f);
            float p3 = __expf(sacc[nt][3] * 0.125f);
            ls0 += p0 + p1;
            ls1 += p2 + p3;
            *(__half2*)(Psw + r0 * HPS + nt * 8 + 2 * c0)       = __floats2half2_rn(p0, p1);
            *(__half2*)(Psw + (r0 + 8) * HPS + nt * 8 + 2 * c0) = __floats2half2_rn(p2, p3);
        }
        __syncwarp();

        // ---- O += P @ V ----
#pragma unroll
        for (int kg = 0; kg < 4; kg++) {
            uint32_t pa[4];
            {
                // blocks: rows (j&1)*8 + lane&7, cols kg*16 + (j>>1)*8
                uint32_t a = pwb +
                    (uint32_t)((((lane >> 3) & 1) * 8 + (lane & 7)) * HPS +
                               kg * 16 + (lane >> 4) * 8) * 2;
                ldsm_x4(pa[0], pa[1], pa[2], pa[3], a);
            }
#pragma unroll
            for (int p = 0; p < 4; p++) {
                uint32_t bv0, bv1, bv2, bv3;
                // blocks: keys kg*16 + (j&1)*8 + lane&7, dims p*16 + (j>>1)*8
                uint32_t a = vbase +
                    (uint32_t)((kg * 16 + ((lane >> 3) & 1) * 8 + (lane & 7)) * HKS +
                               p * 16 + (lane >> 4) * 8) * 2;
                ldsm_x4_t(bv0, bv1, bv2, bv3, a);
                mma_f16(oacc[2 * p],     pa, bv0, bv1);
                mma_f16(oacc[2 * p + 1], pa, bv2, bv3);
            }
        }
        __syncthreads();
    }

    // reduce l over the quad
    ls0 += __shfl_xor_sync(0xffffffffu, ls0, 1);
    ls0 += __shfl_xor_sync(0xffffffffu, ls0, 2);
    ls1 += __shfl_xor_sync(0xffffffffu, ls1, 1);
    ls1 += __shfl_xor_sync(0xffffffffu, ls1, 2);
    const float inv0 = 1.0f / ls0;
    const float inv1 = 1.0f / ls1;

    // write ctx as bf16 hi/lo: O[b][q][h*64 + d]
#pragma unroll
    for (int nt = 0; nt < 8; nt++) {
        const int col = h * 64 + nt * 8 + 2 * c0;
        float v0 = oacc[nt][0] * inv0, v1 = oacc[nt][1] * inv0;
        float v2 = oacc[nt][2] * inv1, v3 = oacc[nt][3] * inv1;
        __nv_bfloat16 h0, l0, h1, l1, h2, l2, h3, l3;
        bsplit(v0, h0, l0); bsplit(v1, h1, l1);
        bsplit(v2, h2, l2); bsplit(v3, h3, l3);
        __nv_bfloat162 hh01, ll01, hh23, ll23;
        hh01.x = h0; hh01.y = h1; ll01.x = l0; ll01.y = l1;
        hh23.x = h2; hh23.y = h3; ll23.x = l2; ll23.y = l3;
        *(__nv_bfloat162*)(Oh + ((size_t)(b * 2048 + row0)) * 1024 + col)     = hh01;
        *(__nv_bfloat162*)(Ol + ((size_t)(b * 2048 + row0)) * 1024 + col)     = ll01;
        *(__nv_bfloat162*)(Oh + ((size_t)(b * 2048 + row0 + 8)) * 1024 + col) = hh23;
        *(__nv_bfloat162*)(Ol + ((size_t)(b * 2048 + row0 + 8)) * 1024 + col) = ll23;
    }
}

// ---------------------------------------------------------------------------
// Launch
// ---------------------------------------------------------------------------
extern "C" void kernel_launch(void* const* d_in, const int* in_sizes, int n_in,
                              void* d_out, int out_size)
{
    const float* Q  = (const float*)d_in[0];
    const float* K  = (const float*)d_in[1];
    const float* V  = (const float*)d_in[2];
    const float* WQ = (const float*)d_in[3];
    const float* WK = (const float*)d_in[4];
    const float* WV = (const float*)d_in[5];
    const float* Wf = (const float*)d_in[6];
    float* out = (float*)d_out;

    __nv_bfloat16 *Xh, *Xl, *WTh, *WTl;
    __half *Qh, *Ql, *Kh, *Vh;
    cudaGetSymbolAddress((void**)&Xh,  g_Xh);
    cudaGetSymbolAddress((void**)&Xl,  g_Xl);
    cudaGetSymbolAddress((void**)&WTh, g_WTh);
    cudaGetSymbolAddress((void**)&WTl, g_WTl);
    cudaGetSymbolAddress((void**)&Qh,  g_Qh);
    cudaGetSymbolAddress((void**)&Ql,  g_Ql);
    cudaGetSymbolAddress((void**)&Kh,  g_Kh);
    cudaGetSymbolAddress((void**)&Vh,  g_Vh);

    cudaFuncSetAttribute(gemm_bf16x3_kernel,
                         cudaFuncAttributeMaxDynamicSharedMemorySize, GSMEM);
    cudaFuncSetAttribute(attn_fp16_kernel,
                         cudaFuncAttributeMaxDynamicSharedMemorySize, HSM_BYTES);

    const size_t NEL = (size_t)MDIM * NDIM;

    // 1) weights: transpose + split
    TransArgs t;
    t.src[0] = WQ; t.src[1] = WK; t.src[2] = WV; t.src[3] = Wf;
    t.dh = WTh; t.dl = WTl;
    transsplit4_kernel<<<dim3(32, 32, 4), dim3(32, 8)>>>(t);

    // 2) input activations: split Q, K, V to bf16 hi/lo
    SplitArgs sp;
    sp.src[0] = Q; sp.src[1] = K; sp.src[2] = V;
    for (int i = 0; i < 3; i++) { sp.dh[i] = Xh + i * NEL; sp.dl[i] = Xl + i * NEL; }
    split_kernel<<<dim3((unsigned)(NEL / 4 / 256), 1, 3), 256>>>(sp);

    // 3) Q/K/V projections -> fp16 (Q hi/lo, K, V)
    GemmArgsB g1;
    for (int i = 0; i < 3; i++) {
        g1.Ah[i] = Xh + i * NEL;
        g1.Al[i] = Xl + i * NEL;
        g1.Bh[i] = WTh + (size_t)i * NDIM * KDIM;
        g1.Bl[i] = WTl + (size_t)i * NDIM * KDIM;
        g1.C[i] = nullptr;
        g1.D2[i] = nullptr;
    }
    g1.D1[0] = Qh; g1.D2[0] = Ql; g1.mode[0] = 1;
    g1.D1[1] = Kh;                g1.mode[1] = 2;
    g1.D1[2] = Vh;                g1.mode[2] = 2;
    gemm_bf16x3_kernel<<<dim3(NDIM / 128, MDIM / 128, 3), 512, GSMEM>>>(g1);

    // 4) attention (fp16 mma) -> ctx written as bf16 hi/lo into slot 0
    attn_fp16_kernel<<<dim3(16, 16, 4), 256, HSM_BYTES>>>(Qh, Ql, Kh, Vh, Xh, Xl);

    // 5) output projection (f32 out)
    GemmArgsB g2;
    for (int i = 0; i < 3; i++) {
        g2.Ah[i] = Xh;
        g2.Al[i] = Xl;
        g2.Bh[i] = WTh + (size_t)3 * NDIM * KDIM;
        g2.Bl[i] = WTl + (size_t)3 * NDIM * KDIM;
        g2.C[i] = out;
        g2.D1[i] = nullptr; g2.D2[i] = nullptr;
        g2.mode[i] = 0;
    }
    gemm_bf16x3_kernel<<<dim3(NDIM / 128, MDIM / 128, 1), 512, GSMEM>>>(g2);
}

// round 7
// speedup vs baseline: 3.8484x; 1.1118x over previous
#include <cuda_runtime.h>
#include <cuda_bf16.h>
#include <cuda_fp16.h>
#include <cstdint>

// Shapes (fixed): B=4, S=2048, D=1024, H=16, dk=64.
#define MDIM 8192
#define NDIM 1024
#define KDIM 1024

// ---------------------------------------------------------------------------
// Device scratch (allocation-free per harness rules)
// ---------------------------------------------------------------------------
__device__ __nv_bfloat16 g_Xh[3][MDIM * NDIM];   // split activations (hi) for GEMM A
__device__ __nv_bfloat16 g_Xl[3][MDIM * NDIM];   // split activations (lo)
__device__ __nv_bfloat16 g_WTh[4][NDIM * KDIM];  // transposed+split weights (hi)
__device__ __nv_bfloat16 g_WTl[4][NDIM * KDIM];  // transposed+split weights (lo)
__device__ __half g_Qh[MDIM * NDIM];             // fp16 projections for attention
__device__ __half g_Ql[MDIM * NDIM];
__device__ __half g_Kh[MDIM * NDIM];
__device__ __half g_Vh[MDIM * NDIM];

// ---------------------------------------------------------------------------
// Helpers
// ---------------------------------------------------------------------------
__device__ __forceinline__ uint32_t smem_u32(const void* p) {
    uint32_t a;
    asm("{ .reg .u64 t; cvta.to.shared.u64 t, %1; cvt.u32.u64 %0, t; }"
        : "=r"(a) : "l"(p));
    return a;
}

__device__ __forceinline__ void bsplit(float x, __nv_bfloat16& h, __nv_bfloat16& l) {
    h = __float2bfloat16_rn(x);
    l = __float2bfloat16_rn(x - __bfloat162float(h));
}

__device__ __forceinline__ void mma_bf16(float* c, const uint32_t* a,
                                         uint32_t b0, uint32_t b1) {
    asm volatile(
        "mma.sync.aligned.m16n8k16.row.col.f32.bf16.bf16.f32 "
        "{%0,%1,%2,%3}, {%4,%5,%6,%7}, {%8,%9}, {%0,%1,%2,%3};"
        : "+f"(c[0]), "+f"(c[1]), "+f"(c[2]), "+f"(c[3])
        : "r"(a[0]), "r"(a[1]), "r"(a[2]), "r"(a[3]), "r"(b0), "r"(b1));
}

__device__ __forceinline__ void mma_f16(float* c, const uint32_t* a,
                                        uint32_t b0, uint32_t b1) {
    asm volatile(
        "mma.sync.aligned.m16n8k16.row.col.f32.f16.f16.f32 "
        "{%0,%1,%2,%3}, {%4,%5,%6,%7}, {%8,%9}, {%0,%1,%2,%3};"
        : "+f"(c[0]), "+f"(c[1]), "+f"(c[2]), "+f"(c[3])
        : "r"(a[0]), "r"(a[1]), "r"(a[2]), "r"(a[3]), "r"(b0), "r"(b1));
}

__device__ __forceinline__ void ldsm_x4(uint32_t& d0, uint32_t& d1,
                                        uint32_t& d2, uint32_t& d3, uint32_t a) {
    asm volatile("ldmatrix.sync.aligned.m8n8.x4.shared.b16 {%0,%1,%2,%3}, [%4];"
                 : "=r"(d0), "=r"(d1), "=r"(d2), "=r"(d3) : "r"(a));
}
__device__ __forceinline__ void ldsm_x4_t(uint32_t& d0, uint32_t& d1,
                                          uint32_t& d2, uint32_t& d3, uint32_t a) {
    asm volatile("ldmatrix.sync.aligned.m8n8.x4.trans.shared.b16 {%0,%1,%2,%3}, [%4];"
                 : "=r"(d0), "=r"(d1), "=r"(d2), "=r"(d3) : "r"(a));
}

__device__ __forceinline__ void cp_async16(uint32_t dst, const void* src) {
    asm volatile("cp.async.cg.shared.global [%0], [%1], 16;"
                 :: "r"(dst), "l"(src) : "memory");
}
__device__ __forceinline__ void cp_commit() {
    asm volatile("cp.async.commit_group;" ::: "memory");
}
template <int N>
__device__ __forceinline__ void cp_wait() {
    asm volatile("cp.async.wait_group %0;" :: "n"(N) : "memory");
}

// ---------------------------------------------------------------------------
// Prepass 1: weight transpose + bf16 split
// ---------------------------------------------------------------------------
struct TransArgs { const float* src[4]; __nv_bfloat16* dh; __nv_bfloat16* dl; };

__global__ __launch_bounds__(256) void transsplit4_kernel(TransArgs a)
{
    __shared__ float t[32][33];
    const int z = blockIdx.z;
    const float* W = a.src[z];
    __nv_bfloat16* Dh = a.dh + (size_t)z * NDIM * KDIM;
    __nv_bfloat16* Dl = a.dl + (size_t)z * NDIM * KDIM;

    int x = blockIdx.x * 32 + threadIdx.x;
    int y0 = blockIdx.y * 32;
#pragma unroll
    for (int j = 0; j < 32; j += 8)
        t[threadIdx.y + j][threadIdx.x] = W[(size_t)(y0 + threadIdx.y + j) * 1024 + x];
    __syncthreads();
    int x2 = blockIdx.y * 32 + threadIdx.x;
    int y2 = blockIdx.x * 32;
#pragma unroll
    for (int j = 0; j < 32; j += 8) {
        float v = t[threadIdx.x][threadIdx.y + j];
        __nv_bfloat16 h, l;
        bsplit(v, h, l);
        Dh[(size_t)(y2 + threadIdx.y + j) * 1024 + x2] = h;
        Dl[(size_t)(y2 + threadIdx.y + j) * 1024 + x2] = l;
    }
}

// ---------------------------------------------------------------------------
// Prepass 2: elementwise bf16 split of input activations
// ---------------------------------------------------------------------------
struct SplitArgs { const float* src[3]; __nv_bfloat16* dh[3]; __nv_bfloat16* dl[3]; };

__global__ __launch_bounds__(256) void split_kernel(SplitArgs a)
{
    const int z = blockIdx.z;
    const float* X = a.src[z];
    __nv_bfloat16* H = a.dh[z];
    __nv_bfloat16* L = a.dl[z];
    size_t i = ((size_t)blockIdx.x * 256 + threadIdx.x) * 4;
    if (i >= (size_t)MDIM * NDIM) return;
    float4 v = *(const float4*)(X + i);
    __nv_bfloat16 h[4], l[4];
    bsplit(v.x, h[0], l[0]);
    bsplit(v.y, h[1], l[1]);
    bsplit(v.z, h[2], l[2]);
    bsplit(v.w, h[3], l[3]);
    *(uint2*)(H + i) = *(uint2*)h;
    *(uint2*)(L + i) = *(uint2*)l;
}

// ---------------------------------------------------------------------------
// 3xbf16 mma.sync GEMM, 256 threads, 2 CTAs/SM.
// CTA 128x128, 8 warps (2M x 4N), warp tile 64x32, BK=32, double-buffered.
// Sequential passes per ks (hh -> h*bl -> al*bh) to keep regs under 128.
// Epilogue modes: 0: C f32;  1: D1=fp16(hi), D2=fp16(lo);  2: D1=fp16
// ---------------------------------------------------------------------------
#define WROW 20
#define TILEW (128 * WROW)
#define STW (4 * TILEW)
#define GSMEM (2 * STW * 4)

struct GemmArgsB {
    const __nv_bfloat16 *Ah[3], *Al[3], *Bh[3], *Bl[3];
    float* C[3];
    __half* D1[3];
    __half* D2[3];
    int mode[3];
};

__device__ __forceinline__ void gemm_load_stage(
    const __nv_bfloat16* __restrict__ Ah, const __nv_bfloat16* __restrict__ Al,
    const __nv_bfloat16* __restrict__ Bh, const __nv_bfloat16* __restrict__ Bl,
    int s, uint32_t sbase, int tid)
{
#pragma unroll
    for (int i = 0; i < 2; i++) {
        const int idx = tid + i * 256;      // 0..511
        const int r = idx >> 2;             // 0..127
        const int c = idx & 3;              // 0..3 (16B chunks)
        const uint32_t doff = (uint32_t)(r * WROW + c * 4) * 4;
        const size_t goff = (size_t)r * KDIM + s * 32 + c * 8;
        cp_async16(sbase + doff,                 Ah + goff);
        cp_async16(sbase + TILEW * 4 + doff,     Al + goff);
        cp_async16(sbase + 2 * TILEW * 4 + doff, Bh + goff);
        cp_async16(sbase + 3 * TILEW * 4 + doff, Bl + goff);
    }
    cp_commit();
}

__global__ void __launch_bounds__(256, 2)
gemm_bf16x3_kernel(GemmArgsB args)
{
    extern __shared__ uint32_t sw[];
    const int tid = threadIdx.x;
    const int lane = tid & 31;
    const int wid = tid >> 5;          // 0..7
    const int wm = wid >> 2;           // 0..1 -> M offset wm*64
    const int wn = wid & 3;            // 0..3 -> N offset wn*32
    const int r0 = lane >> 2;
    const int c0 = lane & 3;
    const int z = blockIdx.z;

    const size_t aoff = (size_t)blockIdx.y * 128 * KDIM;
    const size_t boff = (size_t)blockIdx.x * 128 * KDIM;
    const __nv_bfloat16* Ah = args.Ah[z] + aoff;
    const __nv_bfloat16* Al = args.Al[z] + aoff;
    const __nv_bfloat16* Bh = args.Bh[z] + boff;
    const __nv_bfloat16* Bl = args.Bl[z] + boff;

    const uint32_t sbase = smem_u32(sw);

    float acc[4][4][4];
#pragma unroll
    for (int i = 0; i < 4; i++)
#pragma unroll
        for (int j = 0; j < 4; j++)
#pragma unroll
            for (int k = 0; k < 4; k++) acc[i][j][k] = 0.0f;

    gemm_load_stage(Ah, Al, Bh, Bl, 0, sbase, tid);

    const int NST = KDIM / 32;
    for (int s = 0; s < NST; s++) {
        const int buf = s & 1;
        if (s + 1 < NST) {
            gemm_load_stage(Ah, Al, Bh, Bl, s + 1,
                            sbase + ((s + 1) & 1) * STW * 4, tid);
            cp_wait<1>();
        } else {
            cp_wait<0>();
        }
        __syncthreads();

        const uint32_t* St = sw + buf * STW;

#pragma unroll
        for (int ks = 0; ks < 2; ks++) {
            uint32_t af[4][4], bf[4][2];
            // ---- pass 1: A-hi x B-hi ----
#pragma unroll
            for (int mt = 0; mt < 4; mt++) {
                const int row = wm * 64 + mt * 16 + r0;
                const int base = row * WROW + ks * 8 + c0;
                af[mt][0] = St[base];
                af[mt][1] = St[base + 8 * WROW];
                af[mt][2] = St[base + 4];
                af[mt][3] = St[base + 8 * WROW + 4];
            }
#pragma unroll
            for (int nt = 0; nt < 4; nt++) {
                const int n = wn * 32 + nt * 8 + r0;
                const int nb = 2 * TILEW + n * WROW + ks * 8 + c0;
                bf[nt][0] = St[nb];
                bf[nt][1] = St[nb + 4];
            }
#pragma unroll
            for (int mt = 0; mt < 4; mt++)
#pragma unroll
                for (int nt = 0; nt < 4; nt++)
                    mma_bf16(acc[mt][nt], af[mt], bf[nt][0], bf[nt][1]);

            // ---- pass 2: A-hi x B-lo ----
#pragma unroll
            for (int nt = 0; nt < 4; nt++) {
                const int n = wn * 32 + nt * 8 + r0;
                const int nb = 3 * TILEW + n * WROW + ks * 8 + c0;
                bf[nt][0] = St[nb];
                bf[nt][1] = St[nb + 4];
            }
#pragma unroll
            for (int mt = 0; mt < 4; mt++)
#pragma unroll
                for (int nt = 0; nt < 4; nt++)
                    mma_bf16(acc[mt][nt], af[mt], bf[nt][0], bf[nt][1]);

            // ---- pass 3: A-lo x B-hi ----
#pragma unroll
            for (int mt = 0; mt < 4; mt++) {
                const int row = wm * 64 + mt * 16 + r0;
                const int base = TILEW + row * WROW + ks * 8 + c0;
                af[mt][0] = St[base];
                af[mt][1] = St[base + 8 * WROW];
                af[mt][2] = St[base + 4];
                af[mt][3] = St[base + 8 * WROW + 4];
            }
#pragma unroll
            for (int nt = 0; nt < 4; nt++) {
                const int n = wn * 32 + nt * 8 + r0;
                const int nb = 2 * TILEW + n * WROW + ks * 8 + c0;
                bf[nt][0] = St[nb];
                bf[nt][1] = St[nb + 4];
            }
#pragma unroll
            for (int mt = 0; mt < 4; mt++)
#pragma unroll
                for (int nt = 0; nt < 4; nt++)
                    mma_bf16(acc[mt][nt], af[mt], bf[nt][0], bf[nt][1]);
        }
        __syncthreads();
    }

    const int mode = args.mode[z];
    const size_t crow0 = (size_t)blockIdx.y * 128 + wm * 64;
    const size_t ccol0 = (size_t)blockIdx.x * 128 + wn * 32;
#pragma unroll
    for (int mt = 0; mt < 4; mt++) {
#pragma unroll
        for (int nt = 0; nt < 4; nt++) {
            const size_t row = crow0 + mt * 16 + r0;
            const size_t col = ccol0 + nt * 8 + c0 * 2;
            float* c = acc[mt][nt];
            if (mode == 0) {
                float* C = args.C[z];
                *(float2*)(C + row * NDIM + col)       = make_float2(c[0], c[1]);
                *(float2*)(C + (row + 8) * NDIM + col) = make_float2(c[2], c[3]);
            } else {
                __half* D1 = args.D1[z];
                __half2 h01 = __floats2half2_rn(c[0], c[1]);
                __half2 h23 = __floats2half2_rn(c[2], c[3]);
                *(__half2*)(D1 + row * NDIM + col)       = h01;
                *(__half2*)(D1 + (row + 8) * NDIM + col) = h23;
                if (mode == 1) {
                    __half* D2 = args.D2[z];
                    __half2 l01, l23;
                    l01.x = __float2half_rn(c[0] - __half2float(h01.x));
                    l01.y = __float2half_rn(c[1] - __half2float(h01.y));
                    l23.x = __float2half_rn(c[2] - __half2float(h23.x));
                    l23.y = __float2half_rn(c[3] - __half2float(h23.y));
                    *(__half2*)(D2 + row * NDIM + col)       = l01;
                    *(__half2*)(D2 + (row + 8) * NDIM + col) = l23;
                }
            }
        }
    }
}

// ---------------------------------------------------------------------------
// fp16 tensor-core attention (verified round 6, unchanged).
// ---------------------------------------------------------------------------
#define HKS 72
#define HPS 72
#define HOFF_K 0
#define HOFF_V (2 * 64 * HKS)
#define HOFF_P (HOFF_V + 2 * 64 * HKS)
#define HSM_HALFS (HOFF_P + 8 * 16 * HPS)
#define HSM_BYTES (HSM_HALFS * 2)

__device__ __forceinline__ void attn_load_kv16(
    const __half* __restrict__ Kg, const __half* __restrict__ Vg,
    int t, int buf, uint32_t sb, int tid)
{
    const uint32_t kb = sb + (HOFF_K + buf * 64 * HKS) * 2;
    const uint32_t vb = sb + (HOFF_V + buf * 64 * HKS) * 2;
#pragma unroll
    for (int i = 0; i < 2; i++) {
        int idx = tid + i * 256;
        int r = idx >> 3;
        int c = idx & 7;
        const uint32_t doff = (uint32_t)(r * HKS + c * 8) * 2;
        cp_async16(kb + doff, Kg + (size_t)(t * 64 + r) * 64 + c * 8);
        cp_async16(vb + doff, Vg + (size_t)(t * 64 + r) * 64 + c * 8);
    }
    cp_commit();
}

__global__ void __launch_bounds__(256, 1)
attn_fp16_kernel(const __half* __restrict__ Qh, const __half* __restrict__ Ql,
                 const __half* __restrict__ Kh, const __half* __restrict__ Vh,
                 __nv_bfloat16* __restrict__ Oh, __nv_bfloat16* __restrict__ Ol)
{
    extern __shared__ __half hsm[];
    const int tid = threadIdx.x;
    const int lane = tid & 31;
    const int w = tid >> 5;
    const int r0 = lane >> 2;
    const int c0 = lane & 3;
    const int h = blockIdx.y;
    const int b = blockIdx.z;
    const int qbase = blockIdx.x * 128;
    const size_t off = ((size_t)b * 2048 + h * 128) * 1024;

    const __half* Qhg = Qh + off;
    const __half* Qlg = Ql + off;
    const __half* Kg = Kh + off;
    const __half* Vg = Vh + off;
    const uint32_t sb = smem_u32(hsm);

    uint32_t qfh[4][4], qfl[4][4];
    const int row0 = qbase + w * 16 + r0;
#pragma unroll
    for (int kg = 0; kg < 4; kg++)
#pragma unroll
        for (int q = 0; q < 4; q++) {
            int row = row0 + (q & 1) * 8;
            int col = kg * 16 + (q >> 1) * 8 + 2 * c0;
            qfh[kg][q] = *(const uint32_t*)(Qhg + (size_t)row * 64 + col);
            qfl[kg][q] = *(const uint32_t*)(Qlg + (size_t)row * 64 + col);
        }

    float oacc[8][4];
#pragma unroll
    for (int nt = 0; nt < 8; nt++)
#pragma unroll
        for (int j = 0; j < 4; j++) oacc[nt][j] = 0.0f;
    float ls0 = 0.f, ls1 = 0.f;

    attn_load_kv16(Kg, Vg, 0, 0, sb, tid);

    __half* Psw = hsm + HOFF_P + w * 16 * HPS;
    const uint32_t pwb = sb + (HOFF_P + w * 16 * HPS) * 2;

    for (int t = 0; t < 32; t++) {
        const int buf = t & 1;
        if (t + 1 < 32) {
            attn_load_kv16(Kg, Vg, t + 1, (t + 1) & 1, sb, tid);
            cp_wait<1>();
        } else {
            cp_wait<0>();
        }
        __syncthreads();

        const uint32_t kbase = sb + (HOFF_K + buf * 64 * HKS) * 2;
        const uint32_t vbase = sb + (HOFF_V + buf * 64 * HKS) * 2;

        float sacc[8][4];
#pragma unroll
        for (int nt = 0; nt < 8; nt++)
#pragma unroll
            for (int j = 0; j < 4; j++) sacc[nt][j] = 0.0f;

#pragma unroll
        for (int nt = 0; nt < 8; nt++) {
            uint32_t bk[4][2];
#pragma unroll
            for (int p = 0; p < 2; p++) {
                uint32_t a = kbase +
                    (uint32_t)((nt * 8 + (lane & 7)) * HKS + p * 32 + (lane >> 3) * 8) * 2;
                ldsm_x4(bk[2 * p][0], bk[2 * p][1], bk[2 * p + 1][0], bk[2 * p + 1][1], a);
            }
#pragma unroll
            for (int kg = 0; kg < 4; kg++)
                mma_f16(sacc[nt], qfh[kg], bk[kg][0], bk[kg][1]);
#pragma unroll
            for (int kg = 0; kg < 4; kg++)
                mma_f16(sacc[nt], qfl[kg], bk[kg][0], bk[kg][1]);
        }

#pragma unroll
        for (int nt = 0; nt < 8; nt++) {
            float p0 = __expf(sacc[nt][0] * 0.125f);
            float p1 = __expf(sacc[nt][1] * 0.125f);
            float p2 = __expf(sacc[nt][2] * 0.125f);
            float p3 = __expf(sacc[nt][3] * 0.125f);
            ls0 += p0 + p1;
            ls1 += p2 + p3;
            *(__half2*)(Psw + r0 * HPS + nt * 8 + 2 * c0)       = __floats2half2_rn(p0, p1);
            *(__half2*)(Psw + (r0 + 8) * HPS + nt * 8 + 2 * c0) = __floats2half2_rn(p2, p3);
        }
        __syncwarp();

#pragma unroll
        for (int kg = 0; kg < 4; kg++) {
            uint32_t pa[4];
            {
                uint32_t a = pwb +
                    (uint32_t)((((lane >> 3) & 1) * 8 + (lane & 7)) * HPS +
                               kg * 16 + (lane >> 4) * 8) * 2;
                ldsm_x4(pa[0], pa[1], pa[2], pa[3], a);
            }
#pragma unroll
            for (int p = 0; p < 4; p++) {
                uint32_t bv0, bv1, bv2, bv3;
                uint32_t a = vbase +
                    (uint32_t)((kg * 16 + ((lane >> 3) & 1) * 8 + (lane & 7)) * HKS +
                               p * 16 + (lane >> 4) * 8) * 2;
                ldsm_x4_t(bv0, bv1, bv2, bv3, a);
                mma_f16(oacc[2 * p],     pa, bv0, bv1);
                mma_f16(oacc[2 * p + 1], pa, bv2, bv3);
            }
        }
        __syncthreads();
    }

    ls0 += __shfl_xor_sync(0xffffffffu, ls0, 1);
    ls0 += __shfl_xor_sync(0xffffffffu, ls0, 2);
    ls1 += __shfl_xor_sync(0xffffffffu, ls1, 1);
    ls1 += __shfl_xor_sync(0xffffffffu, ls1, 2);
    const float inv0 = 1.0f / ls0;
    const float inv1 = 1.0f / ls1;

#pragma unroll
    for (int nt = 0; nt < 8; nt++) {
        const int col = h * 64 + nt * 8 + 2 * c0;
        float v0 = oacc[nt][0] * inv0, v1 = oacc[nt][1] * inv0;
        float v2 = oacc[nt][2] * inv1, v3 = oacc[nt][3] * inv1;
        __nv_bfloat16 h0, l0, h1, l1, h2, l2, h3, l3;
        bsplit(v0, h0, l0); bsplit(v1, h1, l1);
        bsplit(v2, h2, l2); bsplit(v3, h3, l3);
        __nv_bfloat162 hh01, ll01, hh23, ll23;
        hh01.x = h0; hh01.y = h1; ll01.x = l0; ll01.y = l1;
        hh23.x = h2; hh23.y = h3; ll23.x = l2; ll23.y = l3;
        *(__nv_bfloat162*)(Oh + ((size_t)(b * 2048 + row0)) * 1024 + col)     = hh01;
        *(__nv_bfloat162*)(Ol + ((size_t)(b * 2048 + row0)) * 1024 + col)     = ll01;
        *(__nv_bfloat162*)(Oh + ((size_t)(b * 2048 + row0 + 8)) * 1024 + col) = hh23;
        *(__nv_bfloat162*)(Ol + ((size_t)(b * 2048 + row0 + 8)) * 1024 + col) = ll23;
    }
}

// ---------------------------------------------------------------------------
// Launch
// ---------------------------------------------------------------------------
extern "C" void kernel_launch(void* const* d_in, const int* in_sizes, int n_in,
                              void* d_out, int out_size)
{
    const float* Q  = (const float*)d_in[0];
    const float* K  = (const float*)d_in[1];
    const float* V  = (const float*)d_in[2];
    const float* WQ = (const float*)d_in[3];
    const float* WK = (const float*)d_in[4];
    const float* WV = (const float*)d_in[5];
    const float* Wf = (const float*)d_in[6];
    float* out = (float*)d_out;

    __nv_bfloat16 *Xh, *Xl, *WTh, *WTl;
    __half *Qh, *Ql, *Kh, *Vh;
    cudaGetSymbolAddress((void**)&Xh,  g_Xh);
    cudaGetSymbolAddress((void**)&Xl,  g_Xl);
    cudaGetSymbolAddress((void**)&WTh, g_WTh);
    cudaGetSymbolAddress((void**)&WTl, g_WTl);
    cudaGetSymbolAddress((void**)&Qh,  g_Qh);
    cudaGetSymbolAddress((void**)&Ql,  g_Ql);
    cudaGetSymbolAddress((void**)&Kh,  g_Kh);
    cudaGetSymbolAddress((void**)&Vh,  g_Vh);

    cudaFuncSetAttribute(gemm_bf16x3_kernel,
                         cudaFuncAttributeMaxDynamicSharedMemorySize, GSMEM);
    cudaFuncSetAttribute(attn_fp16_kernel,
                         cudaFuncAttributeMaxDynamicSharedMemorySize, HSM_BYTES);

    const size_t NEL = (size_t)MDIM * NDIM;

    // 1) weights: transpose + split
    TransArgs t;
    t.src[0] = WQ; t.src[1] = WK; t.src[2] = WV; t.src[3] = Wf;
    t.dh = WTh; t.dl = WTl;
    transsplit4_kernel<<<dim3(32, 32, 4), dim3(32, 8)>>>(t);

    // 2) input activations: split Q, K, V to bf16 hi/lo
    SplitArgs sp;
    sp.src[0] = Q; sp.src[1] = K; sp.src[2] = V;
    for (int i = 0; i < 3; i++) { sp.dh[i] = Xh + i * NEL; sp.dl[i] = Xl + i * NEL; }
    split_kernel<<<dim3((unsigned)(NEL / 4 / 256), 1, 3), 256>>>(sp);

    // 3) Q/K/V projections -> fp16 (Q hi/lo, K, V)
    GemmArgsB g1;
    for (int i = 0; i < 3; i++) {
        g1.Ah[i] = Xh + i * NEL;
        g1.Al[i] = Xl + i * NEL;
        g1.Bh[i] = WTh + (size_t)i * NDIM * KDIM;
        g1.Bl[i] = WTl + (size_t)i * NDIM * KDIM;
        g1.C[i] = nullptr;
        g1.D2[i] = nullptr;
    }
    g1.D1[0] = Qh; g1.D2[0] = Ql; g1.mode[0] = 1;
    g1.D1[1] = Kh;                g1.mode[1] = 2;
    g1.D1[2] = Vh;                g1.mode[2] = 2;
    gemm_bf16x3_kernel<<<dim3(NDIM / 128, MDIM / 128, 3), 256, GSMEM>>>(g1);

    // 4) attention (fp16 mma) -> ctx written as bf16 hi/lo into slot 0
    attn_fp16_kernel<<<dim3(16, 16, 4), 256, HSM_BYTES>>>(Qh, Ql, Kh, Vh, Xh, Xl);

    // 5) output projection (f32 out)
    GemmArgsB g2;
    for (int i = 0; i < 3; i++) {
        g2.Ah[i] = Xh;
        g2.Al[i] = Xl;
        g2.Bh[i] = WTh + (size_t)3 * NDIM * KDIM;
        g2.Bl[i] = WTl + (size_t)3 * NDIM * KDIM;
        g2.C[i] = out;
        g2.D1[i] = nullptr; g2.D2[i] = nullptr;
        g2.mode[i] = 0;
    }
    gemm_bf16x3_kernel<<<dim3(NDIM / 128, MDIM / 128, 1), 256, GSMEM>>>(g2);
}

// round 8
// speedup vs baseline: 4.0415x; 1.0502x over previous
#include <cuda_runtime.h>
#include <cuda_bf16.h>
#include <cuda_fp16.h>
#include <cstdint>

// Shapes (fixed): B=4, S=2048, D=1024, H=16, dk=64.
#define MDIM 8192
#define NDIM 1024
#define KDIM 1024

// ---------------------------------------------------------------------------
// Device scratch (allocation-free per harness rules)
// ---------------------------------------------------------------------------
__device__ __nv_bfloat16 g_Xh[3][MDIM * NDIM];   // split activations (hi) for GEMM A
__device__ __nv_bfloat16 g_Xl[3][MDIM * NDIM];   // split activations (lo)
__device__ __nv_bfloat16 g_WTh[4][NDIM * KDIM];  // transposed+split weights (hi)
__device__ __nv_bfloat16 g_WTl[4][NDIM * KDIM];  // transposed+split weights (lo)
__device__ __half g_Qh[MDIM * NDIM];             // fp16 projections for attention
__device__ __half g_Ql[MDIM * NDIM];
__device__ __half g_Kh[MDIM * NDIM];
__device__ __half g_Vh[MDIM * NDIM];

// ---------------------------------------------------------------------------
// Helpers
// ---------------------------------------------------------------------------
__device__ __forceinline__ uint32_t smem_u32(const void* p) {
    uint32_t a;
    asm("{ .reg .u64 t; cvta.to.shared.u64 t, %1; cvt.u32.u64 %0, t; }"
        : "=r"(a) : "l"(p));
    return a;
}

__device__ __forceinline__ void bsplit(float x, __nv_bfloat16& h, __nv_bfloat16& l) {
    h = __float2bfloat16_rn(x);
    l = __float2bfloat16_rn(x - __bfloat162float(h));
}

__device__ __forceinline__ void mma_bf16(float* c, const uint32_t* a,
                                         uint32_t b0, uint32_t b1) {
    asm volatile(
        "mma.sync.aligned.m16n8k16.row.col.f32.bf16.bf16.f32 "
        "{%0,%1,%2,%3}, {%4,%5,%6,%7}, {%8,%9}, {%0,%1,%2,%3};"
        : "+f"(c[0]), "+f"(c[1]), "+f"(c[2]), "+f"(c[3])
        : "r"(a[0]), "r"(a[1]), "r"(a[2]), "r"(a[3]), "r"(b0), "r"(b1));
}

__device__ __forceinline__ void mma_f16(float* c, const uint32_t* a,
                                        uint32_t b0, uint32_t b1) {
    asm volatile(
        "mma.sync.aligned.m16n8k16.row.col.f32.f16.f16.f32 "
        "{%0,%1,%2,%3}, {%4,%5,%6,%7}, {%8,%9}, {%0,%1,%2,%3};"
        : "+f"(c[0]), "+f"(c[1]), "+f"(c[2]), "+f"(c[3])
        : "r"(a[0]), "r"(a[1]), "r"(a[2]), "r"(a[3]), "r"(b0), "r"(b1));
}

__device__ __forceinline__ void ldsm_x4(uint32_t& d0, uint32_t& d1,
                                        uint32_t& d2, uint32_t& d3, uint32_t a) {
    asm volatile("ldmatrix.sync.aligned.m8n8.x4.shared.b16 {%0,%1,%2,%3}, [%4];"
                 : "=r"(d0), "=r"(d1), "=r"(d2), "=r"(d3) : "r"(a));
}
__device__ __forceinline__ void ldsm_x4_t(uint32_t& d0, uint32_t& d1,
                                          uint32_t& d2, uint32_t& d3, uint32_t a) {
    asm volatile("ldmatrix.sync.aligned.m8n8.x4.trans.shared.b16 {%0,%1,%2,%3}, [%4];"
                 : "=r"(d0), "=r"(d1), "=r"(d2), "=r"(d3) : "r"(a));
}

__device__ __forceinline__ void cp_async16(uint32_t dst, const void* src) {
    asm volatile("cp.async.cg.shared.global [%0], [%1], 16;"
                 :: "r"(dst), "l"(src) : "memory");
}
__device__ __forceinline__ void cp_commit() {
    asm volatile("cp.async.commit_group;" ::: "memory");
}
template <int N>
__device__ __forceinline__ void cp_wait() {
    asm volatile("cp.async.wait_group %0;" :: "n"(N) : "memory");
}

// ---------------------------------------------------------------------------
// Prepass 1: weight transpose + bf16 split
// ---------------------------------------------------------------------------
struct TransArgs { const float* src[4]; __nv_bfloat16* dh; __nv_bfloat16* dl; };

__global__ __launch_bounds__(256) void transsplit4_kernel(TransArgs a)
{
    __shared__ float t[32][33];
    const int z = blockIdx.z;
    const float* W = a.src[z];
    __nv_bfloat16* Dh = a.dh + (size_t)z * NDIM * KDIM;
    __nv_bfloat16* Dl = a.dl + (size_t)z * NDIM * KDIM;

    int x = blockIdx.x * 32 + threadIdx.x;
    int y0 = blockIdx.y * 32;
#pragma unroll
    for (int j = 0; j < 32; j += 8)
        t[threadIdx.y + j][threadIdx.x] = W[(size_t)(y0 + threadIdx.y + j) * 1024 + x];
    __syncthreads();
    int x2 = blockIdx.y * 32 + threadIdx.x;
    int y2 = blockIdx.x * 32;
#pragma unroll
    for (int j = 0; j < 32; j += 8) {
        float v = t[threadIdx.x][threadIdx.y + j];
        __nv_bfloat16 h, l;
        bsplit(v, h, l);
        Dh[(size_t)(y2 + threadIdx.y + j) * 1024 + x2] = h;
        Dl[(size_t)(y2 + threadIdx.y + j) * 1024 + x2] = l;
    }
}

// ---------------------------------------------------------------------------
// Prepass 2: elementwise bf16 split of input activations
// ---------------------------------------------------------------------------
struct SplitArgs { const float* src[3]; __nv_bfloat16* dh[3]; __nv_bfloat16* dl[3]; };

__global__ __launch_bounds__(256) void split_kernel(SplitArgs a)
{
    const int z = blockIdx.z;
    const float* X = a.src[z];
    __nv_bfloat16* H = a.dh[z];
    __nv_bfloat16* L = a.dl[z];
    size_t i = ((size_t)blockIdx.x * 256 + threadIdx.x) * 4;
    if (i >= (size_t)MDIM * NDIM) return;
    float4 v = *(const float4*)(X + i);
    __nv_bfloat16 h[4], l[4];
    bsplit(v.x, h[0], l[0]);
    bsplit(v.y, h[1], l[1]);
    bsplit(v.z, h[2], l[2]);
    bsplit(v.w, h[3], l[3]);
    *(uint2*)(H + i) = *(uint2*)h;
    *(uint2*)(L + i) = *(uint2*)l;
}

// ---------------------------------------------------------------------------
// 3xbf16 mma.sync GEMM, 256 threads, 2 CTAs/SM (verified round 7).
// ---------------------------------------------------------------------------
#define WROW 20
#define TILEW (128 * WROW)
#define STW (4 * TILEW)
#define GSMEM (2 * STW * 4)

struct GemmArgsB {
    const __nv_bfloat16 *Ah[3], *Al[3], *Bh[3], *Bl[3];
    float* C[3];
    __half* D1[3];
    __half* D2[3];
    int mode[3];
};

__device__ __forceinline__ void gemm_load_stage(
    const __nv_bfloat16* __restrict__ Ah, const __nv_bfloat16* __restrict__ Al,
    const __nv_bfloat16* __restrict__ Bh, const __nv_bfloat16* __restrict__ Bl,
    int s, uint32_t sbase, int tid)
{
#pragma unroll
    for (int i = 0; i < 2; i++) {
        const int idx = tid + i * 256;
        const int r = idx >> 2;
        const int c = idx & 3;
        const uint32_t doff = (uint32_t)(r * WROW + c * 4) * 4;
        const size_t goff = (size_t)r * KDIM + s * 32 + c * 8;
        cp_async16(sbase + doff,                 Ah + goff);
        cp_async16(sbase + TILEW * 4 + doff,     Al + goff);
        cp_async16(sbase + 2 * TILEW * 4 + doff, Bh + goff);
        cp_async16(sbase + 3 * TILEW * 4 + doff, Bl + goff);
    }
    cp_commit();
}

__global__ void __launch_bounds__(256, 2)
gemm_bf16x3_kernel(GemmArgsB args)
{
    extern __shared__ uint32_t sw[];
    const int tid = threadIdx.x;
    const int lane = tid & 31;
    const int wid = tid >> 5;
    const int wm = wid >> 2;
    const int wn = wid & 3;
    const int r0 = lane >> 2;
    const int c0 = lane & 3;
    const int z = blockIdx.z;

    const size_t aoff = (size_t)blockIdx.y * 128 * KDIM;
    const size_t boff = (size_t)blockIdx.x * 128 * KDIM;
    const __nv_bfloat16* Ah = args.Ah[z] + aoff;
    const __nv_bfloat16* Al = args.Al[z] + aoff;
    const __nv_bfloat16* Bh = args.Bh[z] + boff;
    const __nv_bfloat16* Bl = args.Bl[z] + boff;

    const uint32_t sbase = smem_u32(sw);

    float acc[4][4][4];
#pragma unroll
    for (int i = 0; i < 4; i++)
#pragma unroll
        for (int j = 0; j < 4; j++)
#pragma unroll
            for (int k = 0; k < 4; k++) acc[i][j][k] = 0.0f;

    gemm_load_stage(Ah, Al, Bh, Bl, 0, sbase, tid);

    const int NST = KDIM / 32;
    for (int s = 0; s < NST; s++) {
        const int buf = s & 1;
        if (s + 1 < NST) {
            gemm_load_stage(Ah, Al, Bh, Bl, s + 1,
                            sbase + ((s + 1) & 1) * STW * 4, tid);
            cp_wait<1>();
        } else {
            cp_wait<0>();
        }
        __syncthreads();

        const uint32_t* St = sw + buf * STW;

#pragma unroll
        for (int ks = 0; ks < 2; ks++) {
            uint32_t af[4][4], bf[4][2];
            // ---- pass 1: A-hi x B-hi ----
#pragma unroll
            for (int mt = 0; mt < 4; mt++) {
                const int row = wm * 64 + mt * 16 + r0;
                const int base = row * WROW + ks * 8 + c0;
                af[mt][0] = St[base];
                af[mt][1] = St[base + 8 * WROW];
                af[mt][2] = St[base + 4];
                af[mt][3] = St[base + 8 * WROW + 4];
            }
#pragma unroll
            for (int nt = 0; nt < 4; nt++) {
                const int n = wn * 32 + nt * 8 + r0;
                const int nb = 2 * TILEW + n * WROW + ks * 8 + c0;
                bf[nt][0] = St[nb];
                bf[nt][1] = St[nb + 4];
            }
#pragma unroll
            for (int mt = 0; mt < 4; mt++)
#pragma unroll
                for (int nt = 0; nt < 4; nt++)
                    mma_bf16(acc[mt][nt], af[mt], bf[nt][0], bf[nt][1]);

            // ---- pass 2: A-hi x B-lo ----
#pragma unroll
            for (int nt = 0; nt < 4; nt++) {
                const int n = wn * 32 + nt * 8 + r0;
                const int nb = 3 * TILEW + n * WROW + ks * 8 + c0;
                bf[nt][0] = St[nb];
                bf[nt][1] = St[nb + 4];
            }
#pragma unroll
            for (int mt = 0; mt < 4; mt++)
#pragma unroll
                for (int nt = 0; nt < 4; nt++)
                    mma_bf16(acc[mt][nt], af[mt], bf[nt][0], bf[nt][1]);

            // ---- pass 3: A-lo x B-hi ----
#pragma unroll
            for (int mt = 0; mt < 4; mt++) {
                const int row = wm * 64 + mt * 16 + r0;
                const int base = TILEW + row * WROW + ks * 8 + c0;
                af[mt][0] = St[base];
                af[mt][1] = St[base + 8 * WROW];
                af[mt][2] = St[base + 4];
                af[mt][3] = St[base + 8 * WROW + 4];
            }
#pragma unroll
            for (int nt = 0; nt < 4; nt++) {
                const int n = wn * 32 + nt * 8 + r0;
                const int nb = 2 * TILEW + n * WROW + ks * 8 + c0;
                bf[nt][0] = St[nb];
                bf[nt][1] = St[nb + 4];
            }
#pragma unroll
            for (int mt = 0; mt < 4; mt++)
#pragma unroll
                for (int nt = 0; nt < 4; nt++)
                    mma_bf16(acc[mt][nt], af[mt], bf[nt][0], bf[nt][1]);
        }
        __syncthreads();
    }

    const int mode = args.mode[z];
    const size_t crow0 = (size_t)blockIdx.y * 128 + wm * 64;
    const size_t ccol0 = (size_t)blockIdx.x * 128 + wn * 32;
#pragma unroll
    for (int mt = 0; mt < 4; mt++) {
#pragma unroll
        for (int nt = 0; nt < 4; nt++) {
            const size_t row = crow0 + mt * 16 + r0;
            const size_t col = ccol0 + nt * 8 + c0 * 2;
            float* c = acc[mt][nt];
            if (mode == 0) {
                float* C = args.C[z];
                *(float2*)(C + row * NDIM + col)       = make_float2(c[0], c[1]);
                *(float2*)(C + (row + 8) * NDIM + col) = make_float2(c[2], c[3]);
            } else {
                __half* D1 = args.D1[z];
                __half2 h01 = __floats2half2_rn(c[0], c[1]);
                __half2 h23 = __floats2half2_rn(c[2], c[3]);
                *(__half2*)(D1 + row * NDIM + col)       = h01;
                *(__half2*)(D1 + (row + 8) * NDIM + col) = h23;
                if (mode == 1) {
                    __half* D2 = args.D2[z];
                    __half2 l01, l23;
                    l01.x = __float2half_rn(c[0] - __half2float(h01.x));
                    l01.y = __float2half_rn(c[1] - __half2float(h01.y));
                    l23.x = __float2half_rn(c[2] - __half2float(h23.x));
                    l23.y = __float2half_rn(c[3] - __half2float(h23.y));
                    *(__half2*)(D2 + row * NDIM + col)       = l01;
                    *(__half2*)(D2 + (row + 8) * NDIM + col) = l23;
                }
            }
        }
    }
}

// ---------------------------------------------------------------------------
// fp16 tensor-core attention, P kept in registers.
// Key identity: the QK C-fragment (c0,c1=row r0 keys 2c0,2c0+1; c2,c3=row r0+8)
// packs directly into the PV A-fragment:
//   pa[kg] = { h2(sacc[2kg][0],[1]), h2(sacc[2kg][2],[3]),
//              h2(sacc[2kg+1][0],[1]), h2(sacc[2kg+1][2],[3]) }
// so no smem round-trip for P is needed at all.
// ---------------------------------------------------------------------------
#define HKS 72
#define HOFF_K 0
#define HOFF_V (2 * 64 * HKS)
#define HSM_HALFS (HOFF_V + 2 * 64 * HKS)    // 18432 halfs
#define HSM_BYTES (HSM_HALFS * 2)            // 36864 B

__device__ __forceinline__ void attn_load_kv16(
    const __half* __restrict__ Kg, const __half* __restrict__ Vg,
    int t, int buf, uint32_t sb, int tid)
{
    const uint32_t kb = sb + (HOFF_K + buf * 64 * HKS) * 2;
    const uint32_t vb = sb + (HOFF_V + buf * 64 * HKS) * 2;
#pragma unroll
    for (int i = 0; i < 2; i++) {
        int idx = tid + i * 256;
        int r = idx >> 3;
        int c = idx & 7;
        const uint32_t doff = (uint32_t)(r * HKS + c * 8) * 2;
        cp_async16(kb + doff, Kg + (size_t)(t * 64 + r) * 64 + c * 8);
        cp_async16(vb + doff, Vg + (size_t)(t * 64 + r) * 64 + c * 8);
    }
    cp_commit();
}

__global__ void __launch_bounds__(256, 1)
attn_fp16_kernel(const __half* __restrict__ Qh, const __half* __restrict__ Ql,
                 const __half* __restrict__ Kh, const __half* __restrict__ Vh,
                 __nv_bfloat16* __restrict__ Oh, __nv_bfloat16* __restrict__ Ol)
{
    extern __shared__ __half hsm[];
    const int tid = threadIdx.x;
    const int lane = tid & 31;
    const int w = tid >> 5;
    const int r0 = lane >> 2;
    const int c0 = lane & 3;
    const int h = blockIdx.y;
    const int b = blockIdx.z;
    const int qbase = blockIdx.x * 128;
    const size_t off = ((size_t)b * 2048 + h * 128) * 1024;

    const __half* Qhg = Qh + off;
    const __half* Qlg = Ql + off;
    const __half* Kg = Kh + off;
    const __half* Vg = Vh + off;
    const uint32_t sb = smem_u32(hsm);

    uint32_t qfh[4][4], qfl[4][4];
    const int row0 = qbase + w * 16 + r0;
#pragma unroll
    for (int kg = 0; kg < 4; kg++)
#pragma unroll
        for (int q = 0; q < 4; q++) {
            int row = row0 + (q & 1) * 8;
            int col = kg * 16 + (q >> 1) * 8 + 2 * c0;
            qfh[kg][q] = *(const uint32_t*)(Qhg + (size_t)row * 64 + col);
            qfl[kg][q] = *(const uint32_t*)(Qlg + (size_t)row * 64 + col);
        }

    float oacc[8][4];
#pragma unroll
    for (int nt = 0; nt < 8; nt++)
#pragma unroll
        for (int j = 0; j < 4; j++) oacc[nt][j] = 0.0f;
    float ls0 = 0.f, ls1 = 0.f;

    attn_load_kv16(Kg, Vg, 0, 0, sb, tid);

    for (int t = 0; t < 32; t++) {
        const int buf = t & 1;
        if (t + 1 < 32) {
            attn_load_kv16(Kg, Vg, t + 1, (t + 1) & 1, sb, tid);
            cp_wait<1>();
        } else {
            cp_wait<0>();
        }
        __syncthreads();

        const uint32_t kbase = sb + (HOFF_K + buf * 64 * HKS) * 2;
        const uint32_t vbase = sb + (HOFF_V + buf * 64 * HKS) * 2;

        // ---- S = Q @ K^T (2 passes: hi, lo) ----
        float sacc[8][4];
#pragma unroll
        for (int nt = 0; nt < 8; nt++)
#pragma unroll
            for (int j = 0; j < 4; j++) sacc[nt][j] = 0.0f;

#pragma unroll
        for (int nt = 0; nt < 8; nt++) {
            uint32_t bk[4][2];
#pragma unroll
            for (int p = 0; p < 2; p++) {
                uint32_t a = kbase +
                    (uint32_t)((nt * 8 + (lane & 7)) * HKS + p * 32 + (lane >> 3) * 8) * 2;
                ldsm_x4(bk[2 * p][0], bk[2 * p][1], bk[2 * p + 1][0], bk[2 * p + 1][1], a);
            }
#pragma unroll
            for (int kg = 0; kg < 4; kg++)
                mma_f16(sacc[nt], qfh[kg], bk[kg][0], bk[kg][1]);
#pragma unroll
            for (int kg = 0; kg < 4; kg++)
                mma_f16(sacc[nt], qfl[kg], bk[kg][0], bk[kg][1]);
        }

        // ---- P = exp(S/8): pack QK C-frags directly into PV A-frags ----
        uint32_t pfrag[4][4];
#pragma unroll
        for (int nt = 0; nt < 8; nt++) {
            float p0 = __expf(sacc[nt][0] * 0.125f);
            float p1 = __expf(sacc[nt][1] * 0.125f);
            float p2 = __expf(sacc[nt][2] * 0.125f);
            float p3 = __expf(sacc[nt][3] * 0.125f);
            ls0 += p0 + p1;
            ls1 += p2 + p3;
            __half2 h01 = __floats2half2_rn(p0, p1);
            __half2 h23 = __floats2half2_rn(p2, p3);
            pfrag[nt >> 1][(nt & 1) * 2 + 0] = *(uint32_t*)&h01;
            pfrag[nt >> 1][(nt & 1) * 2 + 1] = *(uint32_t*)&h23;
        }

        // ---- O += P @ V ----
#pragma unroll
        for (int kg = 0; kg < 4; kg++) {
#pragma unroll
            for (int p = 0; p < 4; p++) {
                uint32_t bv0, bv1, bv2, bv3;
                uint32_t a = vbase +
                    (uint32_t)((kg * 16 + ((lane >> 3) & 1) * 8 + (lane & 7)) * HKS +
                               p * 16 + (lane >> 4) * 8) * 2;
                ldsm_x4_t(bv0, bv1, bv2, bv3, a);
                mma_f16(oacc[2 * p],     pfrag[kg], bv0, bv1);
                mma_f16(oacc[2 * p + 1], pfrag[kg], bv2, bv3);
            }
        }
        __syncthreads();
    }

    ls0 += __shfl_xor_sync(0xffffffffu, ls0, 1);
    ls0 += __shfl_xor_sync(0xffffffffu, ls0, 2);
    ls1 += __shfl_xor_sync(0xffffffffu, ls1, 1);
    ls1 += __shfl_xor_sync(0xffffffffu, ls1, 2);
    const float inv0 = 1.0f / ls0;
    const float inv1 = 1.0f / ls1;

#pragma unroll
    for (int nt = 0; nt < 8; nt++) {
        const int col = h * 64 + nt * 8 + 2 * c0;
        float v0 = oacc[nt][0] * inv0, v1 = oacc[nt][1] * inv0;
        float v2 = oacc[nt][2] * inv1, v3 = oacc[nt][3] * inv1;
        __nv_bfloat16 h0, l0, h1, l1, h2, l2, h3, l3;
        bsplit(v0, h0, l0); bsplit(v1, h1, l1);
        bsplit(v2, h2, l2); bsplit(v3, h3, l3);
        __nv_bfloat162 hh01, ll01, hh23, ll23;
        hh01.x = h0; hh01.y = h1; ll01.x = l0; ll01.y = l1;
        hh23.x = h2; hh23.y = h3; ll23.x = l2; ll23.y = l3;
        *(__nv_bfloat162*)(Oh + ((size_t)(b * 2048 + row0)) * 1024 + col)     = hh01;
        *(__nv_bfloat162*)(Ol + ((size_t)(b * 2048 + row0)) * 1024 + col)     = ll01;
        *(__nv_bfloat162*)(Oh + ((size_t)(b * 2048 + row0 + 8)) * 1024 + col) = hh23;
        *(__nv_bfloat162*)(Ol + ((size_t)(b * 2048 + row0 + 8)) * 1024 + col) = ll23;
    }
}

// ---------------------------------------------------------------------------
// Launch
// ---------------------------------------------------------------------------
extern "C" void kernel_launch(void* const* d_in, const int* in_sizes, int n_in,
                              void* d_out, int out_size)
{
    const float* Q  = (const float*)d_in[0];
    const float* K  = (const float*)d_in[1];
    const float* V  = (const float*)d_in[2];
    const float* WQ = (const float*)d_in[3];
    const float* WK = (const float*)d_in[4];
    const float* WV = (const float*)d_in[5];
    const float* Wf = (const float*)d_in[6];
    float* out = (float*)d_out;

    __nv_bfloat16 *Xh, *Xl, *WTh, *WTl;
    __half *Qh, *Ql, *Kh, *Vh;
    cudaGetSymbolAddress((void**)&Xh,  g_Xh);
    cudaGetSymbolAddress((void**)&Xl,  g_Xl);
    cudaGetSymbolAddress((void**)&WTh, g_WTh);
    cudaGetSymbolAddress((void**)&WTl, g_WTl);
    cudaGetSymbolAddress((void**)&Qh,  g_Qh);
    cudaGetSymbolAddress((void**)&Ql,  g_Ql);
    cudaGetSymbolAddress((void**)&Kh,  g_Kh);
    cudaGetSymbolAddress((void**)&Vh,  g_Vh);

    cudaFuncSetAttribute(gemm_bf16x3_kernel,
                         cudaFuncAttributeMaxDynamicSharedMemorySize, GSMEM);
    cudaFuncSetAttribute(attn_fp16_kernel,
                         cudaFuncAttributeMaxDynamicSharedMemorySize, HSM_BYTES);

    const size_t NEL = (size_t)MDIM * NDIM;

    // 1) weights: transpose + split
    TransArgs t;
    t.src[0] = WQ; t.src[1] = WK; t.src[2] = WV; t.src[3] = Wf;
    t.dh = WTh; t.dl = WTl;
    transsplit4_kernel<<<dim3(32, 32, 4), dim3(32, 8)>>>(t);

    // 2) input activations: split Q, K, V to bf16 hi/lo
    SplitArgs sp;
    sp.src[0] = Q; sp.src[1] = K; sp.src[2] = V;
    for (int i = 0; i < 3; i++) { sp.dh[i] = Xh + i * NEL; sp.dl[i] = Xl + i * NEL; }
    split_kernel<<<dim3((unsigned)(NEL / 4 / 256), 1, 3), 256>>>(sp);

    // 3) Q/K/V projections -> fp16 (Q hi/lo, K, V)
    GemmArgsB g1;
    for (int i = 0; i < 3; i++) {
        g1.Ah[i] = Xh + i * NEL;
        g1.Al[i] = Xl + i * NEL;
        g1.Bh[i] = WTh + (size_t)i * NDIM * KDIM;
        g1.Bl[i] = WTl + (size_t)i * NDIM * KDIM;
        g1.C[i] = nullptr;
        g1.D2[i] = nullptr;
    }
    g1.D1[0] = Qh; g1.D2[0] = Ql; g1.mode[0] = 1;
    g1.D1[1] = Kh;                g1.mode[1] = 2;
    g1.D1[2] = Vh;                g1.mode[2] = 2;
    gemm_bf16x3_kernel<<<dim3(NDIM / 128, MDIM / 128, 3), 256, GSMEM>>>(g1);

    // 4) attention (fp16 mma, P in registers) -> ctx as bf16 hi/lo into slot 0
    attn_fp16_kernel<<<dim3(16, 16, 4), 256, HSM_BYTES>>>(Qh, Ql, Kh, Vh, Xh, Xl);

    // 5) output projection (f32 out)
    GemmArgsB g2;
    for (int i = 0; i < 3; i++) {
        g2.Ah[i] = Xh;
        g2.Al[i] = Xl;
        g2.Bh[i] = WTh + (size_t)3 * NDIM * KDIM;
        g2.Bl[i] = WTl + (size_t)3 * NDIM * KDIM;
        g2.C[i] = out;
        g2.D1[i] = nullptr; g2.D2[i] = nullptr;
        g2.mode[i] = 0;
    }
    gemm_bf16x3_kernel<<<dim3(NDIM / 128, MDIM / 128, 1), 256, GSMEM>>>(g2);
}

// round 9
// speedup vs baseline: 4.8699x; 1.2050x over previous
#include <cuda_runtime.h>
#include <cuda_bf16.h>
#include <cuda_fp16.h>
#include <cstdint>

// Shapes (fixed): B=4, S=2048, D=1024, H=16, dk=64.
#define MDIM 8192
#define NDIM 1024
#define KDIM 1024

// ---------------------------------------------------------------------------
// Device scratch (allocation-free per harness rules)
// ---------------------------------------------------------------------------
__device__ __half g_Xh[3][MDIM * NDIM];   // split activations (hi) for GEMM A
__device__ __half g_Xl[3][MDIM * NDIM];   // split activations (lo)
__device__ __half g_WT[4][NDIM * KDIM];   // transposed weights, single fp16
__device__ __half g_Qh[MDIM * NDIM];      // fp16 projections for attention
__device__ __half g_Ql[MDIM * NDIM];
__device__ __half g_Kh[MDIM * NDIM];
__device__ __half g_Vh[MDIM * NDIM];

// ---------------------------------------------------------------------------
// Helpers
// ---------------------------------------------------------------------------
__device__ __forceinline__ uint32_t smem_u32(const void* p) {
    uint32_t a;
    asm("{ .reg .u64 t; cvta.to.shared.u64 t, %1; cvt.u32.u64 %0, t; }"
        : "=r"(a) : "l"(p));
    return a;
}

__device__ __forceinline__ void hsplit(float x, __half& h, __half& l) {
    h = __float2half_rn(x);
    l = __float2half_rn(x - __half2float(h));
}

__device__ __forceinline__ void mma_f16(float* c, const uint32_t* a,
                                        uint32_t b0, uint32_t b1) {
    asm volatile(
        "mma.sync.aligned.m16n8k16.row.col.f32.f16.f16.f32 "
        "{%0,%1,%2,%3}, {%4,%5,%6,%7}, {%8,%9}, {%0,%1,%2,%3};"
        : "+f"(c[0]), "+f"(c[1]), "+f"(c[2]), "+f"(c[3])
        : "r"(a[0]), "r"(a[1]), "r"(a[2]), "r"(a[3]), "r"(b0), "r"(b1));
}

__device__ __forceinline__ void ldsm_x4(uint32_t& d0, uint32_t& d1,
                                        uint32_t& d2, uint32_t& d3, uint32_t a) {
    asm volatile("ldmatrix.sync.aligned.m8n8.x4.shared.b16 {%0,%1,%2,%3}, [%4];"
                 : "=r"(d0), "=r"(d1), "=r"(d2), "=r"(d3) : "r"(a));
}
__device__ __forceinline__ void ldsm_x4_t(uint32_t& d0, uint32_t& d1,
                                          uint32_t& d2, uint32_t& d3, uint32_t a) {
    asm volatile("ldmatrix.sync.aligned.m8n8.x4.trans.shared.b16 {%0,%1,%2,%3}, [%4];"
                 : "=r"(d0), "=r"(d1), "=r"(d2), "=r"(d3) : "r"(a));
}

__device__ __forceinline__ void cp_async16(uint32_t dst, const void* src) {
    asm volatile("cp.async.cg.shared.global [%0], [%1], 16;"
                 :: "r"(dst), "l"(src) : "memory");
}
__device__ __forceinline__ void cp_commit() {
    asm volatile("cp.async.commit_group;" ::: "memory");
}
template <int N>
__device__ __forceinline__ void cp_wait() {
    asm volatile("cp.async.wait_group %0;" :: "n"(N) : "memory");
}

// ---------------------------------------------------------------------------
// Prepass 1: weight transpose -> single fp16: WT[z][n][k] = fp16(W[z][k][n])
// ---------------------------------------------------------------------------
struct TransArgs { const float* src[4]; __half* dst; };

__global__ __launch_bounds__(256) void trans4_kernel(TransArgs a)
{
    __shared__ float t[32][33];
    const int z = blockIdx.z;
    const float* W = a.src[z];
    __half* D = a.dst + (size_t)z * NDIM * KDIM;

    int x = blockIdx.x * 32 + threadIdx.x;
    int y0 = blockIdx.y * 32;
#pragma unroll
    for (int j = 0; j < 32; j += 8)
        t[threadIdx.y + j][threadIdx.x] = W[(size_t)(y0 + threadIdx.y + j) * 1024 + x];
    __syncthreads();
    int x2 = blockIdx.y * 32 + threadIdx.x;
    int y2 = blockIdx.x * 32;
#pragma unroll
    for (int j = 0; j < 32; j += 8)
        D[(size_t)(y2 + threadIdx.y + j) * 1024 + x2] =
            __float2half_rn(t[threadIdx.x][threadIdx.y + j]);
}

// ---------------------------------------------------------------------------
// Prepass 2: elementwise fp16 hi/lo split of input activations
// ---------------------------------------------------------------------------
struct SplitArgs { const float* src[3]; __half* dh[3]; __half* dl[3]; };

__global__ __launch_bounds__(256) void split_kernel(SplitArgs a)
{
    const int z = blockIdx.z;
    const float* X = a.src[z];
    __half* H = a.dh[z];
    __half* L = a.dl[z];
    size_t i = ((size_t)blockIdx.x * 256 + threadIdx.x) * 4;
    if (i >= (size_t)MDIM * NDIM) return;
    float4 v = *(const float4*)(X + i);
    __half h[4], l[4];
    hsplit(v.x, h[0], l[0]);
    hsplit(v.y, h[1], l[1]);
    hsplit(v.z, h[2], l[2]);
    hsplit(v.w, h[3], l[3]);
    *(uint2*)(H + i) = *(uint2*)h;
    *(uint2*)(L + i) = *(uint2*)l;
}

// ---------------------------------------------------------------------------
// 2-pass fp16 mma.sync GEMM: C = (Ah + Al) @ B^T, A split fp16, B single fp16.
// CTA 128x128, 256 thr, 8 warps (2M x 4N), warp tile 64x32, BK=32,
// double-buffered cp.async, 2 CTAs/SM.
// Epilogue modes: 0: C f32;  1: D1=fp16(hi), D2=fp16(lo);  2: D1=fp16
// ---------------------------------------------------------------------------
#define WROW 20
#define TILEW (128 * WROW)
#define STW (3 * TILEW)                  // Ah, Al, B
#define GSMEM (2 * STW * 4)              // 61440 bytes

struct GemmArgsH {
    const __half *Ah[3], *Al[3], *B[3];
    float* C[3];
    __half* D1[3];
    __half* D2[3];
    int mode[3];
};

__device__ __forceinline__ void gemm_load_stage(
    const __half* __restrict__ Ah, const __half* __restrict__ Al,
    const __half* __restrict__ B,
    int s, uint32_t sbase, int tid)
{
#pragma unroll
    for (int i = 0; i < 2; i++) {
        const int idx = tid + i * 256;      // 0..511
        const int r = idx >> 2;             // 0..127
        const int c = idx & 3;              // 0..3 (16B chunks)
        const uint32_t doff = (uint32_t)(r * WROW + c * 4) * 4;
        const size_t goff = (size_t)r * KDIM + s * 32 + c * 8;
        cp_async16(sbase + doff,                 Ah + goff);
        cp_async16(sbase + TILEW * 4 + doff,     Al + goff);
        cp_async16(sbase + 2 * TILEW * 4 + doff, B + goff);
    }
    cp_commit();
}

__global__ void __launch_bounds__(256, 2)
gemm_f16x2_kernel(GemmArgsH args)
{
    extern __shared__ uint32_t sw[];
    const int tid = threadIdx.x;
    const int lane = tid & 31;
    const int wid = tid >> 5;          // 0..7
    const int wm = wid >> 2;           // 0..1 -> M offset wm*64
    const int wn = wid & 3;            // 0..3 -> N offset wn*32
    const int r0 = lane >> 2;
    const int c0 = lane & 3;
    const int z = blockIdx.z;

    const size_t aoff = (size_t)blockIdx.y * 128 * KDIM;
    const size_t boff = (size_t)blockIdx.x * 128 * KDIM;
    const __half* Ah = args.Ah[z] + aoff;
    const __half* Al = args.Al[z] + aoff;
    const __half* Bw = args.B[z] + boff;

    const uint32_t sbase = smem_u32(sw);

    float acc[4][4][4];
#pragma unroll
    for (int i = 0; i < 4; i++)
#pragma unroll
        for (int j = 0; j < 4; j++)
#pragma unroll
            for (int k = 0; k < 4; k++) acc[i][j][k] = 0.0f;

    gemm_load_stage(Ah, Al, Bw, 0, sbase, tid);

    const int NST = KDIM / 32;
    for (int s = 0; s < NST; s++) {
        const int buf = s & 1;
        if (s + 1 < NST) {
            gemm_load_stage(Ah, Al, Bw, s + 1,
                            sbase + ((s + 1) & 1) * STW * 4, tid);
            cp_wait<1>();
        } else {
            cp_wait<0>();
        }
        __syncthreads();

        const uint32_t* St = sw + buf * STW;

#pragma unroll
        for (int ks = 0; ks < 2; ks++) {
            uint32_t af[4][4], bf[4][2];
            // B fragments (single fp16), reused across both passes
#pragma unroll
            for (int nt = 0; nt < 4; nt++) {
                const int n = wn * 32 + nt * 8 + r0;
                const int nb = 2 * TILEW + n * WROW + ks * 8 + c0;
                bf[nt][0] = St[nb];
                bf[nt][1] = St[nb + 4];
            }
            // ---- pass 1: A-hi ----
#pragma unroll
            for (int mt = 0; mt < 4; mt++) {
                const int row = wm * 64 + mt * 16 + r0;
                const int base = row * WROW + ks * 8 + c0;
                af[mt][0] = St[base];
                af[mt][1] = St[base + 8 * WROW];
                af[mt][2] = St[base + 4];
                af[mt][3] = St[base + 8 * WROW + 4];
            }
#pragma unroll
            for (int mt = 0; mt < 4; mt++)
#pragma unroll
                for (int nt = 0; nt < 4; nt++)
                    mma_f16(acc[mt][nt], af[mt], bf[nt][0], bf[nt][1]);

            // ---- pass 2: A-lo (overwrite af) ----
#pragma unroll
            for (int mt = 0; mt < 4; mt++) {
                const int row = wm * 64 + mt * 16 + r0;
                const int base = TILEW + row * WROW + ks * 8 + c0;
                af[mt][0] = St[base];
                af[mt][1] = St[base + 8 * WROW];
                af[mt][2] = St[base + 4];
                af[mt][3] = St[base + 8 * WROW + 4];
            }
#pragma unroll
            for (int mt = 0; mt < 4; mt++)
#pragma unroll
                for (int nt = 0; nt < 4; nt++)
                    mma_f16(acc[mt][nt], af[mt], bf[nt][0], bf[nt][1]);
        }
        __syncthreads();
    }

    const int mode = args.mode[z];
    const size_t crow0 = (size_t)blockIdx.y * 128 + wm * 64;
    const size_t ccol0 = (size_t)blockIdx.x * 128 + wn * 32;
#pragma unroll
    for (int mt = 0; mt < 4; mt++) {
#pragma unroll
        for (int nt = 0; nt < 4; nt++) {
            const size_t row = crow0 + mt * 16 + r0;
            const size_t col = ccol0 + nt * 8 + c0 * 2;
            float* c = acc[mt][nt];
            if (mode == 0) {
                float* C = args.C[z];
                *(float2*)(C + row * NDIM + col)       = make_float2(c[0], c[1]);
                *(float2*)(C + (row + 8) * NDIM + col) = make_float2(c[2], c[3]);
            } else {
                __half* D1 = args.D1[z];
                __half2 h01 = __floats2half2_rn(c[0], c[1]);
                __half2 h23 = __floats2half2_rn(c[2], c[3]);
                *(__half2*)(D1 + row * NDIM + col)       = h01;
                *(__half2*)(D1 + (row + 8) * NDIM + col) = h23;
                if (mode == 1) {
                    __half* D2 = args.D2[z];
                    __half2 l01, l23;
                    l01.x = __float2half_rn(c[0] - __half2float(h01.x));
                    l01.y = __float2half_rn(c[1] - __half2float(h01.y));
                    l23.x = __float2half_rn(c[2] - __half2float(h23.x));
                    l23.y = __float2half_rn(c[3] - __half2float(h23.y));
                    *(__half2*)(D2 + row * NDIM + col)       = l01;
                    *(__half2*)(D2 + (row + 8) * NDIM + col) = l23;
                }
            }
        }
    }
}

// ---------------------------------------------------------------------------
// fp16 tensor-core attention, P in registers (verified round 8).
// Output ctx written as fp16 hi/lo directly into the out-proj A operands.
// ---------------------------------------------------------------------------
#define HKS 72
#define HOFF_K 0
#define HOFF_V (2 * 64 * HKS)
#define HSM_HALFS (HOFF_V + 2 * 64 * HKS)    // 18432 halfs
#define HSM_BYTES (HSM_HALFS * 2)            // 36864 B

__device__ __forceinline__ void attn_load_kv16(
    const __half* __restrict__ Kg, const __half* __restrict__ Vg,
    int t, int buf, uint32_t sb, int tid)
{
    const uint32_t kb = sb + (HOFF_K + buf * 64 * HKS) * 2;
    const uint32_t vb = sb + (HOFF_V + buf * 64 * HKS) * 2;
#pragma unroll
    for (int i = 0; i < 2; i++) {
        int idx = tid + i * 256;
        int r = idx >> 3;
        int c = idx & 7;
        const uint32_t doff = (uint32_t)(r * HKS + c * 8) * 2;
        cp_async16(kb + doff, Kg + (size_t)(t * 64 + r) * 64 + c * 8);
        cp_async16(vb + doff, Vg + (size_t)(t * 64 + r) * 64 + c * 8);
    }
    cp_commit();
}

__global__ void __launch_bounds__(256, 1)
attn_fp16_kernel(const __half* __restrict__ Qh, const __half* __restrict__ Ql,
                 const __half* __restrict__ Kh, const __half* __restrict__ Vh,
                 __half* __restrict__ Oh, __half* __restrict__ Ol)
{
    extern __shared__ __half hsm[];
    const int tid = threadIdx.x;
    const int lane = tid & 31;
    const int w = tid >> 5;
    const int r0 = lane >> 2;
    const int c0 = lane & 3;
    const int h = blockIdx.y;
    const int b = blockIdx.z;
    const int qbase = blockIdx.x * 128;
    const size_t off = ((size_t)b * 2048 + h * 128) * 1024;

    const __half* Qhg = Qh + off;
    const __half* Qlg = Ql + off;
    const __half* Kg = Kh + off;
    const __half* Vg = Vh + off;
    const uint32_t sb = smem_u32(hsm);

    uint32_t qfh[4][4], qfl[4][4];
    const int row0 = qbase + w * 16 + r0;
#pragma unroll
    for (int kg = 0; kg < 4; kg++)
#pragma unroll
        for (int q = 0; q < 4; q++) {
            int row = row0 + (q & 1) * 8;
            int col = kg * 16 + (q >> 1) * 8 + 2 * c0;
            qfh[kg][q] = *(const uint32_t*)(Qhg + (size_t)row * 64 + col);
            qfl[kg][q] = *(const uint32_t*)(Qlg + (size_t)row * 64 + col);
        }

    float oacc[8][4];
#pragma unroll
    for (int nt = 0; nt < 8; nt++)
#pragma unroll
        for (int j = 0; j < 4; j++) oacc[nt][j] = 0.0f;
    float ls0 = 0.f, ls1 = 0.f;

    attn_load_kv16(Kg, Vg, 0, 0, sb, tid);

    for (int t = 0; t < 32; t++) {
        const int buf = t & 1;
        if (t + 1 < 32) {
            attn_load_kv16(Kg, Vg, t + 1, (t + 1) & 1, sb, tid);
            cp_wait<1>();
        } else {
            cp_wait<0>();
        }
        __syncthreads();

        const uint32_t kbase = sb + (HOFF_K + buf * 64 * HKS) * 2;
        const uint32_t vbase = sb + (HOFF_V + buf * 64 * HKS) * 2;

        // ---- S = Q @ K^T (2 passes: hi, lo) ----
        float sacc[8][4];
#pragma unroll
        for (int nt = 0; nt < 8; nt++)
#pragma unroll
            for (int j = 0; j < 4; j++) sacc[nt][j] = 0.0f;

#pragma unroll
        for (int nt = 0; nt < 8; nt++) {
            uint32_t bk[4][2];
#pragma unroll
            for (int p = 0; p < 2; p++) {
                uint32_t a = kbase +
                    (uint32_t)((nt * 8 + (lane & 7)) * HKS + p * 32 + (lane >> 3) * 8) * 2;
                ldsm_x4(bk[2 * p][0], bk[2 * p][1], bk[2 * p + 1][0], bk[2 * p + 1][1], a);
            }
#pragma unroll
            for (int kg = 0; kg < 4; kg++)
                mma_f16(sacc[nt], qfh[kg], bk[kg][0], bk[kg][1]);
#pragma unroll
            for (int kg = 0; kg < 4; kg++)
                mma_f16(sacc[nt], qfl[kg], bk[kg][0], bk[kg][1]);
        }

        // ---- P = exp(S/8): pack QK C-frags directly into PV A-frags ----
        uint32_t pfrag[4][4];
#pragma unroll
        for (int nt = 0; nt < 8; nt++) {
            float p0 = __expf(sacc[nt][0] * 0.125f);
            float p1 = __expf(sacc[nt][1] * 0.125f);
            float p2 = __expf(sacc[nt][2] * 0.125f);
            float p3 = __expf(sacc[nt][3] * 0.125f);
            ls0 += p0 + p1;
            ls1 += p2 + p3;
            __half2 h01 = __floats2half2_rn(p0, p1);
            __half2 h23 = __floats2half2_rn(p2, p3);
            pfrag[nt >> 1][(nt & 1) * 2 + 0] = *(uint32_t*)&h01;
            pfrag[nt >> 1][(nt & 1) * 2 + 1] = *(uint32_t*)&h23;
        }

        // ---- O += P @ V ----
#pragma unroll
        for (int kg = 0; kg < 4; kg++) {
#pragma unroll
            for (int p = 0; p < 4; p++) {
                uint32_t bv0, bv1, bv2, bv3;
                uint32_t a = vbase +
                    (uint32_t)((kg * 16 + ((lane >> 3) & 1) * 8 + (lane & 7)) * HKS +
                               p * 16 + (lane >> 4) * 8) * 2;
                ldsm_x4_t(bv0, bv1, bv2, bv3, a);
                mma_f16(oacc[2 * p],     pfrag[kg], bv0, bv1);
                mma_f16(oacc[2 * p + 1], pfrag[kg], bv2, bv3);
            }
        }
        __syncthreads();
    }

    ls0 += __shfl_xor_sync(0xffffffffu, ls0, 1);
    ls0 += __shfl_xor_sync(0xffffffffu, ls0, 2);
    ls1 += __shfl_xor_sync(0xffffffffu, ls1, 1);
    ls1 += __shfl_xor_sync(0xffffffffu, ls1, 2);
    const float inv0 = 1.0f / ls0;
    const float inv1 = 1.0f / ls1;

#pragma unroll
    for (int nt = 0; nt < 8; nt++) {
        const int col = h * 64 + nt * 8 + 2 * c0;
        float v0 = oacc[nt][0] * inv0, v1 = oacc[nt][1] * inv0;
        float v2 = oacc[nt][2] * inv1, v3 = oacc[nt][3] * inv1;
        __half h0, l0, h1, l1, h2, l2, h3, l3;
        hsplit(v0, h0, l0); hsplit(v1, h1, l1);
        hsplit(v2, h2, l2); hsplit(v3, h3, l3);
        __half2 hh01, ll01, hh23, ll23;
        hh01.x = h0; hh01.y = h1; ll01.x = l0; ll01.y = l1;
        hh23.x = h2; hh23.y = h3; ll23.x = l2; ll23.y = l3;
        *(__half2*)(Oh + ((size_t)(b * 2048 + row0)) * 1024 + col)     = hh01;
        *(__half2*)(Ol + ((size_t)(b * 2048 + row0)) * 1024 + col)     = ll01;
        *(__half2*)(Oh + ((size_t)(b * 2048 + row0 + 8)) * 1024 + col) = hh23;
        *(__half2*)(Ol + ((size_t)(b * 2048 + row0 + 8)) * 1024 + col) = ll23;
    }
}

// ---------------------------------------------------------------------------
// Launch
// ---------------------------------------------------------------------------
extern "C" void kernel_launch(void* const* d_in, const int* in_sizes, int n_in,
                              void* d_out, int out_size)
{
    const float* Q  = (const float*)d_in[0];
    const float* K  = (const float*)d_in[1];
    const float* V  = (const float*)d_in[2];
    const float* WQ = (const float*)d_in[3];
    const float* WK = (const float*)d_in[4];
    const float* WV = (const float*)d_in[5];
    const float* Wf = (const float*)d_in[6];
    float* out = (float*)d_out;

    __half *Xh, *Xl, *WT, *Qh, *Ql, *Kh, *Vh;
    cudaGetSymbolAddress((void**)&Xh, g_Xh);
    cudaGetSymbolAddress((void**)&Xl, g_Xl);
    cudaGetSymbolAddress((void**)&WT, g_WT);
    cudaGetSymbolAddress((void**)&Qh, g_Qh);
    cudaGetSymbolAddress((void**)&Ql, g_Ql);
    cudaGetSymbolAddress((void**)&Kh, g_Kh);
    cudaGetSymbolAddress((void**)&Vh, g_Vh);

    cudaFuncSetAttribute(gemm_f16x2_kernel,
                         cudaFuncAttributeMaxDynamicSharedMemorySize, GSMEM);
    cudaFuncSetAttribute(attn_fp16_kernel,
                         cudaFuncAttributeMaxDynamicSharedMemorySize, HSM_BYTES);

    const size_t NEL = (size_t)MDIM * NDIM;

    // 1) weights: transpose -> fp16
    TransArgs t;
    t.src[0] = WQ; t.src[1] = WK; t.src[2] = WV; t.src[3] = Wf;
    t.dst = WT;
    trans4_kernel<<<dim3(32, 32, 4), dim3(32, 8)>>>(t);

    // 2) input activations: split Q, K, V to fp16 hi/lo
    SplitArgs sp;
    sp.src[0] = Q; sp.src[1] = K; sp.src[2] = V;
    for (int i = 0; i < 3; i++) { sp.dh[i] = Xh + i * NEL; sp.dl[i] = Xl + i * NEL; }
    split_kernel<<<dim3((unsigned)(NEL / 4 / 256), 1, 3), 256>>>(sp);

    // 3) Q/K/V projections -> fp16 (Q hi/lo, K, V)
    GemmArgsH g1;
    for (int i = 0; i < 3; i++) {
        g1.Ah[i] = Xh + i * NEL;
        g1.Al[i] = Xl + i * NEL;
        g1.B[i]  = WT + (size_t)i * NDIM * KDIM;
        g1.C[i] = nullptr;
        g1.D2[i] = nullptr;
    }
    g1.D1[0] = Qh; g1.D2[0] = Ql; g1.mode[0] = 1;
    g1.D1[1] = Kh;                g1.mode[1] = 2;
    g1.D1[2] = Vh;                g1.mode[2] = 2;
    gemm_f16x2_kernel<<<dim3(NDIM / 128, MDIM / 128, 3), 256, GSMEM>>>(g1);

    // 4) attention (fp16 mma, P in registers) -> ctx as fp16 hi/lo into slot 0
    attn_fp16_kernel<<<dim3(16, 16, 4), 256, HSM_BYTES>>>(Qh, Ql, Kh, Vh, Xh, Xl);

    // 5) output projection (f32 out)
    GemmArgsH g2;
    for (int i = 0; i < 3; i++) {
        g2.Ah[i] = Xh;
        g2.Al[i] = Xl;
        g2.B[i]  = WT + (size_t)3 * NDIM * KDIM;
        g2.C[i] = out;
        g2.D1[i] = nullptr; g2.D2[i] = nullptr;
        g2.mode[i] = 0;
    }
    gemm_f16x2_kernel<<<dim3(NDIM / 128, MDIM / 128, 1), 256, GSMEM>>>(g2);
}

// round 10
// speedup vs baseline: 6.9244x; 1.4219x over previous
#include <cuda_runtime.h>
#include <cuda_fp16.h>
#include <cstdint>

// Shapes (fixed): B=4, S=2048, D=1024, H=16, dk=64.
#define MDIM 8192
#define NDIM 1024
#define KDIM 1024

// ---------------------------------------------------------------------------
// Device scratch (allocation-free per harness rules)
// ---------------------------------------------------------------------------
__device__ __half g_X[3][MDIM * NDIM];    // fp16 activations (slot 0 reused for ctx)
__device__ __half g_WT[4][NDIM * KDIM];   // transposed weights, fp16
__device__ __half g_Qh[MDIM * NDIM];      // fp16 projections for attention
__device__ __half g_Kh[MDIM * NDIM];
__device__ __half g_Vh[MDIM * NDIM];

// ---------------------------------------------------------------------------
// Helpers
// ---------------------------------------------------------------------------
__device__ __forceinline__ uint32_t smem_u32(const void* p) {
    uint32_t a;
    asm("{ .reg .u64 t; cvta.to.shared.u64 t, %1; cvt.u32.u64 %0, t; }"
        : "=r"(a) : "l"(p));
    return a;
}

__device__ __forceinline__ void mma_f16(float* c, const uint32_t* a,
                                        uint32_t b0, uint32_t b1) {
    asm volatile(
        "mma.sync.aligned.m16n8k16.row.col.f32.f16.f16.f32 "
        "{%0,%1,%2,%3}, {%4,%5,%6,%7}, {%8,%9}, {%0,%1,%2,%3};"
        : "+f"(c[0]), "+f"(c[1]), "+f"(c[2]), "+f"(c[3])
        : "r"(a[0]), "r"(a[1]), "r"(a[2]), "r"(a[3]), "r"(b0), "r"(b1));
}

__device__ __forceinline__ void ldsm_x4(uint32_t& d0, uint32_t& d1,
                                        uint32_t& d2, uint32_t& d3, uint32_t a) {
    asm volatile("ldmatrix.sync.aligned.m8n8.x4.shared.b16 {%0,%1,%2,%3}, [%4];"
                 : "=r"(d0), "=r"(d1), "=r"(d2), "=r"(d3) : "r"(a));
}
__device__ __forceinline__ void ldsm_x4_t(uint32_t& d0, uint32_t& d1,
                                          uint32_t& d2, uint32_t& d3, uint32_t a) {
    asm volatile("ldmatrix.sync.aligned.m8n8.x4.trans.shared.b16 {%0,%1,%2,%3}, [%4];"
                 : "=r"(d0), "=r"(d1), "=r"(d2), "=r"(d3) : "r"(a));
}

__device__ __forceinline__ void cp_async16(uint32_t dst, const void* src) {
    asm volatile("cp.async.cg.shared.global [%0], [%1], 16;"
                 :: "r"(dst), "l"(src) : "memory");
}
__device__ __forceinline__ void cp_commit() {
    asm volatile("cp.async.commit_group;" ::: "memory");
}
template <int N>
__device__ __forceinline__ void cp_wait() {
    asm volatile("cp.async.wait_group %0;" :: "n"(N) : "memory");
}

// ---------------------------------------------------------------------------
// Prepass 1: weight transpose -> fp16: WT[z][n][k] = fp16(W[z][k][n])
// ---------------------------------------------------------------------------
struct TransArgs { const float* src[4]; __half* dst; };

__global__ __launch_bounds__(256) void trans4_kernel(TransArgs a)
{
    __shared__ float t[32][33];
    const int z = blockIdx.z;
    const float* W = a.src[z];
    __half* D = a.dst + (size_t)z * NDIM * KDIM;

    int x = blockIdx.x * 32 + threadIdx.x;
    int y0 = blockIdx.y * 32;
#pragma unroll
    for (int j = 0; j < 32; j += 8)
        t[threadIdx.y + j][threadIdx.x] = W[(size_t)(y0 + threadIdx.y + j) * 1024 + x];
    __syncthreads();
    int x2 = blockIdx.y * 32 + threadIdx.x;
    int y2 = blockIdx.x * 32;
#pragma unroll
    for (int j = 0; j < 32; j += 8)
        D[(size_t)(y2 + threadIdx.y + j) * 1024 + x2] =
            __float2half_rn(t[threadIdx.x][threadIdx.y + j]);
}

// ---------------------------------------------------------------------------
// Prepass 2: fp32 -> fp16 convert of input activations
// ---------------------------------------------------------------------------
struct CvtArgs { const float* src[3]; __half* dst[3]; };

__global__ __launch_bounds__(256) void cvt_kernel(CvtArgs a)
{
    const int z = blockIdx.z;
    const float* X = a.src[z];
    __half* H = a.dst[z];
    size_t i = ((size_t)blockIdx.x * 256 + threadIdx.x) * 4;
    if (i >= (size_t)MDIM * NDIM) return;
    float4 v = *(const float4*)(X + i);
    __half2 h01 = __floats2half2_rn(v.x, v.y);
    __half2 h23 = __floats2half2_rn(v.z, v.w);
    uint2 pk;
    pk.x = *(uint32_t*)&h01;
    pk.y = *(uint32_t*)&h23;
    *(uint2*)(H + i) = pk;
}

// ---------------------------------------------------------------------------
// Single-pass fp16 mma.sync GEMM: C = A @ B^T (both fp16).
// CTA 128x128, 256 thr, 8 warps (2M x 4N), warp tile 64x32, BK=32,
// double-buffered cp.async, 2 CTAs/SM.
// Epilogue modes: 0: C f32;  2: D1 fp16
// ---------------------------------------------------------------------------
#define WROW 20
#define TILEW (128 * WROW)
#define STW (2 * TILEW)                  // A, B
#define GSMEM (2 * STW * 4)              // 40960 bytes

struct GemmArgsH {
    const __half *A[3], *B[3];
    float* C[3];
    __half* D1[3];
    int mode[3];
};

__device__ __forceinline__ void gemm_load_stage(
    const __half* __restrict__ A, const __half* __restrict__ B,
    int s, uint32_t sbase, int tid)
{
#pragma unroll
    for (int i = 0; i < 2; i++) {
        const int idx = tid + i * 256;      // 0..511
        const int r = idx >> 2;             // 0..127
        const int c = idx & 3;              // 0..3 (16B chunks)
        const uint32_t doff = (uint32_t)(r * WROW + c * 4) * 4;
        const size_t goff = (size_t)r * KDIM + s * 32 + c * 8;
        cp_async16(sbase + doff,             A + goff);
        cp_async16(sbase + TILEW * 4 + doff, B + goff);
    }
    cp_commit();
}

__global__ void __launch_bounds__(256, 2)
gemm_f16_kernel(GemmArgsH args)
{
    extern __shared__ uint32_t sw[];
    const int tid = threadIdx.x;
    const int lane = tid & 31;
    const int wid = tid >> 5;          // 0..7
    const int wm = wid >> 2;           // 0..1 -> M offset wm*64
    const int wn = wid & 3;            // 0..3 -> N offset wn*32
    const int r0 = lane >> 2;
    const int c0 = lane & 3;
    const int z = blockIdx.z;

    const size_t aoff = (size_t)blockIdx.y * 128 * KDIM;
    const size_t boff = (size_t)blockIdx.x * 128 * KDIM;
    const __half* A = args.A[z] + aoff;
    const __half* Bw = args.B[z] + boff;

    const uint32_t sbase = smem_u32(sw);

    float acc[4][4][4];
#pragma unroll
    for (int i = 0; i < 4; i++)
#pragma unroll
        for (int j = 0; j < 4; j++)
#pragma unroll
            for (int k = 0; k < 4; k++) acc[i][j][k] = 0.0f;

    gemm_load_stage(A, Bw, 0, sbase, tid);

    const int NST = KDIM / 32;
    for (int s = 0; s < NST; s++) {
        const int buf = s & 1;
        if (s + 1 < NST) {
            gemm_load_stage(A, Bw, s + 1,
                            sbase + ((s + 1) & 1) * STW * 4, tid);
            cp_wait<1>();
        } else {
            cp_wait<0>();
        }
        __syncthreads();

        const uint32_t* St = sw + buf * STW;

#pragma unroll
        for (int ks = 0; ks < 2; ks++) {
            uint32_t af[4][4], bf[4][2];
#pragma unroll
            for (int nt = 0; nt < 4; nt++) {
                const int n = wn * 32 + nt * 8 + r0;
                const int nb = TILEW + n * WROW + ks * 8 + c0;
                bf[nt][0] = St[nb];
                bf[nt][1] = St[nb + 4];
            }
#pragma unroll
            for (int mt = 0; mt < 4; mt++) {
                const int row = wm * 64 + mt * 16 + r0;
                const int base = row * WROW + ks * 8 + c0;
                af[mt][0] = St[base];
                af[mt][1] = St[base + 8 * WROW];
                af[mt][2] = St[base + 4];
                af[mt][3] = St[base + 8 * WROW + 4];
            }
#pragma unroll
            for (int mt = 0; mt < 4; mt++)
#pragma unroll
                for (int nt = 0; nt < 4; nt++)
                    mma_f16(acc[mt][nt], af[mt], bf[nt][0], bf[nt][1]);
        }
        __syncthreads();
    }

    const int mode = args.mode[z];
    const size_t crow0 = (size_t)blockIdx.y * 128 + wm * 64;
    const size_t ccol0 = (size_t)blockIdx.x * 128 + wn * 32;
#pragma unroll
    for (int mt = 0; mt < 4; mt++) {
#pragma unroll
        for (int nt = 0; nt < 4; nt++) {
            const size_t row = crow0 + mt * 16 + r0;
            const size_t col = ccol0 + nt * 8 + c0 * 2;
            float* c = acc[mt][nt];
            if (mode == 0) {
                float* C = args.C[z];
                *(float2*)(C + row * NDIM + col)       = make_float2(c[0], c[1]);
                *(float2*)(C + (row + 8) * NDIM + col) = make_float2(c[2], c[3]);
            } else {
                __half* D1 = args.D1[z];
                __half2 h01 = __floats2half2_rn(c[0], c[1]);
                __half2 h23 = __floats2half2_rn(c[2], c[3]);
                *(__half2*)(D1 + row * NDIM + col)       = h01;
                *(__half2*)(D1 + (row + 8) * NDIM + col) = h23;
            }
        }
    }
}

// ---------------------------------------------------------------------------
// fp16 tensor-core attention, P in registers, single-pass QK (Q single fp16).
// CTA = 128 queries of one (b,h); 8 warps x 16 query rows. 64-key tiles,
// double-buffered cp.async. ctx written as single fp16 into out-proj A.
// ---------------------------------------------------------------------------
#define HKS 72
#define HOFF_K 0
#define HOFF_V (2 * 64 * HKS)
#define HSM_HALFS (HOFF_V + 2 * 64 * HKS)    // 18432 halfs
#define HSM_BYTES (HSM_HALFS * 2)            // 36864 B

__device__ __forceinline__ void attn_load_kv16(
    const __half* __restrict__ Kg, const __half* __restrict__ Vg,
    int t, int buf, uint32_t sb, int tid)
{
    const uint32_t kb = sb + (HOFF_K + buf * 64 * HKS) * 2;
    const uint32_t vb = sb + (HOFF_V + buf * 64 * HKS) * 2;
#pragma unroll
    for (int i = 0; i < 2; i++) {
        int idx = tid + i * 256;
        int r = idx >> 3;
        int c = idx & 7;
        const uint32_t doff = (uint32_t)(r * HKS + c * 8) * 2;
        cp_async16(kb + doff, Kg + (size_t)(t * 64 + r) * 64 + c * 8);
        cp_async16(vb + doff, Vg + (size_t)(t * 64 + r) * 64 + c * 8);
    }
    cp_commit();
}

__global__ void __launch_bounds__(256, 1)
attn_fp16_kernel(const __half* __restrict__ Qh, const __half* __restrict__ Kh,
                 const __half* __restrict__ Vh, __half* __restrict__ Oh)
{
    extern __shared__ __half hsm[];
    const int tid = threadIdx.x;
    const int lane = tid & 31;
    const int w = tid >> 5;
    const int r0 = lane >> 2;
    const int c0 = lane & 3;
    const int h = blockIdx.y;
    const int b = blockIdx.z;
    const int qbase = blockIdx.x * 128;
    const size_t off = ((size_t)b * 2048 + h * 128) * 1024;

    const __half* Qg = Qh + off;
    const __half* Kg = Kh + off;
    const __half* Vg = Vh + off;
    const uint32_t sb = smem_u32(hsm);

    uint32_t qf[4][4];
    const int row0 = qbase + w * 16 + r0;
#pragma unroll
    for (int kg = 0; kg < 4; kg++)
#pragma unroll
        for (int q = 0; q < 4; q++) {
            int row = row0 + (q & 1) * 8;
            int col = kg * 16 + (q >> 1) * 8 + 2 * c0;
            qf[kg][q] = *(const uint32_t*)(Qg + (size_t)row * 64 + col);
        }

    float oacc[8][4];
#pragma unroll
    for (int nt = 0; nt < 8; nt++)
#pragma unroll
        for (int j = 0; j < 4; j++) oacc[nt][j] = 0.0f;
    float ls0 = 0.f, ls1 = 0.f;

    attn_load_kv16(Kg, Vg, 0, 0, sb, tid);

    for (int t = 0; t < 32; t++) {
        const int buf = t & 1;
        if (t + 1 < 32) {
            attn_load_kv16(Kg, Vg, t + 1, (t + 1) & 1, sb, tid);
            cp_wait<1>();
        } else {
            cp_wait<0>();
        }
        __syncthreads();

        const uint32_t kbase = sb + (HOFF_K + buf * 64 * HKS) * 2;
        const uint32_t vbase = sb + (HOFF_V + buf * 64 * HKS) * 2;

        // ---- S = Q @ K^T (single pass) ----
        float sacc[8][4];
#pragma unroll
        for (int nt = 0; nt < 8; nt++)
#pragma unroll
            for (int j = 0; j < 4; j++) sacc[nt][j] = 0.0f;

#pragma unroll
        for (int nt = 0; nt < 8; nt++) {
            uint32_t bk[4][2];
#pragma unroll
            for (int p = 0; p < 2; p++) {
                uint32_t a = kbase +
                    (uint32_t)((nt * 8 + (lane & 7)) * HKS + p * 32 + (lane >> 3) * 8) * 2;
                ldsm_x4(bk[2 * p][0], bk[2 * p][1], bk[2 * p + 1][0], bk[2 * p + 1][1], a);
            }
#pragma unroll
            for (int kg = 0; kg < 4; kg++)
                mma_f16(sacc[nt], qf[kg], bk[kg][0], bk[kg][1]);
        }

        // ---- P = exp(S/8): pack QK C-frags directly into PV A-frags ----
        uint32_t pfrag[4][4];
#pragma unroll
        for (int nt = 0; nt < 8; nt++) {
            float p0 = __expf(sacc[nt][0] * 0.125f);
            float p1 = __expf(sacc[nt][1] * 0.125f);
            float p2 = __expf(sacc[nt][2] * 0.125f);
            float p3 = __expf(sacc[nt][3] * 0.125f);
            ls0 += p0 + p1;
            ls1 += p2 + p3;
            __half2 h01 = __floats2half2_rn(p0, p1);
            __half2 h23 = __floats2half2_rn(p2, p3);
            pfrag[nt >> 1][(nt & 1) * 2 + 0] = *(uint32_t*)&h01;
            pfrag[nt >> 1][(nt & 1) * 2 + 1] = *(uint32_t*)&h23;
        }

        // ---- O += P @ V ----
#pragma unroll
        for (int kg = 0; kg < 4; kg++) {
#pragma unroll
            for (int p = 0; p < 4; p++) {
                uint32_t bv0, bv1, bv2, bv3;
                uint32_t a = vbase +
                    (uint32_t)((kg * 16 + ((lane >> 3) & 1) * 8 + (lane & 7)) * HKS +
                               p * 16 + (lane >> 4) * 8) * 2;
                ldsm_x4_t(bv0, bv1, bv2, bv3, a);
                mma_f16(oacc[2 * p],     pfrag[kg], bv0, bv1);
                mma_f16(oacc[2 * p + 1], pfrag[kg], bv2, bv3);
            }
        }
        __syncthreads();
    }

    ls0 += __shfl_xor_sync(0xffffffffu, ls0, 1);
    ls0 += __shfl_xor_sync(0xffffffffu, ls0, 2);
    ls1 += __shfl_xor_sync(0xffffffffu, ls1, 1);
    ls1 += __shfl_xor_sync(0xffffffffu, ls1, 2);
    const float inv0 = 1.0f / ls0;
    const float inv1 = 1.0f / ls1;

#pragma unroll
    for (int nt = 0; nt < 8; nt++) {
        const int col = h * 64 + nt * 8 + 2 * c0;
        __half2 hh01 = __floats2half2_rn(oacc[nt][0] * inv0, oacc[nt][1] * inv0);
        __half2 hh23 = __floats2half2_rn(oacc[nt][2] * inv1, oacc[nt][3] * inv1);
        *(__half2*)(Oh + ((size_t)(b * 2048 + row0)) * 1024 + col)     = hh01;
        *(__half2*)(Oh + ((size_t)(b * 2048 + row0 + 8)) * 1024 + col) = hh23;
    }
}

// ---------------------------------------------------------------------------
// Launch
// ---------------------------------------------------------------------------
extern "C" void kernel_launch(void* const* d_in, const int* in_sizes, int n_in,
                              void* d_out, int out_size)
{
    const float* Q  = (const float*)d_in[0];
    const float* K  = (const float*)d_in[1];
    const float* V  = (const float*)d_in[2];
    const float* WQ = (const float*)d_in[3];
    const float* WK = (const float*)d_in[4];
    const float* WV = (const float*)d_in[5];
    const float* Wf = (const float*)d_in[6];
    float* out = (float*)d_out;

    __half *X, *WT, *Qh, *Kh, *Vh;
    cudaGetSymbolAddress((void**)&X,  g_X);
    cudaGetSymbolAddress((void**)&WT, g_WT);
    cudaGetSymbolAddress((void**)&Qh, g_Qh);
    cudaGetSymbolAddress((void**)&Kh, g_Kh);
    cudaGetSymbolAddress((void**)&Vh, g_Vh);

    cudaFuncSetAttribute(gemm_f16_kernel,
                         cudaFuncAttributeMaxDynamicSharedMemorySize, GSMEM);
    cudaFuncSetAttribute(attn_fp16_kernel,
                         cudaFuncAttributeMaxDynamicSharedMemorySize, HSM_BYTES);

    const size_t NEL = (size_t)MDIM * NDIM;

    // 1) weights: transpose -> fp16
    TransArgs t;
    t.src[0] = WQ; t.src[1] = WK; t.src[2] = WV; t.src[3] = Wf;
    t.dst = WT;
    trans4_kernel<<<dim3(32, 32, 4), dim3(32, 8)>>>(t);

    // 2) input activations -> fp16
    CvtArgs cv;
    cv.src[0] = Q; cv.src[1] = K; cv.src[2] = V;
    for (int i = 0; i < 3; i++) cv.dst[i] = X + i * NEL;
    cvt_kernel<<<dim3((unsigned)(NEL / 4 / 256), 1, 3), 256>>>(cv);

    // 3) Q/K/V projections -> fp16
    GemmArgsH g1;
    for (int i = 0; i < 3; i++) {
        g1.A[i] = X + i * NEL;
        g1.B[i] = WT + (size_t)i * NDIM * KDIM;
        g1.C[i] = nullptr;
        g1.mode[i] = 2;
    }
    g1.D1[0] = Qh; g1.D1[1] = Kh; g1.D1[2] = Vh;
    gemm_f16_kernel<<<dim3(NDIM / 128, MDIM / 128, 3), 256, GSMEM>>>(g1);

    // 4) attention -> ctx fp16 into slot 0
    attn_fp16_kernel<<<dim3(16, 16, 4), 256, HSM_BYTES>>>(Qh, Kh, Vh, X);

    // 5) output projection (f32 out)
    GemmArgsH g2;
    for (int i = 0; i < 3; i++) {
        g2.A[i] = X;
        g2.B[i] = WT + (size_t)3 * NDIM * KDIM;
        g2.C[i] = out;
        g2.D1[i] = nullptr;
        g2.mode[i] = 0;
    }
    gemm_f16_kernel<<<dim3(NDIM / 128, MDIM / 128, 1), 256, GSMEM>>>(g2);
}

// round 11
// speedup vs baseline: 7.3865x; 1.0667x over previous
#include <cuda_runtime.h>
#include <cuda_fp16.h>
#include <cstdint>

// Shapes (fixed): B=4, S=2048, D=1024, H=16, dk=64.
#define MDIM 8192
#define NDIM 1024
#define KDIM 1024

// ---------------------------------------------------------------------------
// Device scratch (allocation-free per harness rules)
// ---------------------------------------------------------------------------
__device__ __half g_X[3][MDIM * NDIM];    // fp16 activations (slot 0 reused for ctx)
__device__ __half g_WT[4][NDIM * KDIM];   // transposed weights, fp16
__device__ __half g_Qh[MDIM * NDIM];      // fp16 projections for attention
__device__ __half g_Kh[MDIM * NDIM];
__device__ __half g_Vh[MDIM * NDIM];

// ---------------------------------------------------------------------------
// Helpers
// ---------------------------------------------------------------------------
__device__ __forceinline__ uint32_t smem_u32(const void* p) {
    uint32_t a;
    asm("{ .reg .u64 t; cvta.to.shared.u64 t, %1; cvt.u32.u64 %0, t; }"
        : "=r"(a) : "l"(p));
    return a;
}

__device__ __forceinline__ void mma_f16(float* c, const uint32_t* a,
                                        uint32_t b0, uint32_t b1) {
    asm volatile(
        "mma.sync.aligned.m16n8k16.row.col.f32.f16.f16.f32 "
        "{%0,%1,%2,%3}, {%4,%5,%6,%7}, {%8,%9}, {%0,%1,%2,%3};"
        : "+f"(c[0]), "+f"(c[1]), "+f"(c[2]), "+f"(c[3])
        : "r"(a[0]), "r"(a[1]), "r"(a[2]), "r"(a[3]), "r"(b0), "r"(b1));
}

__device__ __forceinline__ void ldsm_x4(uint32_t& d0, uint32_t& d1,
                                        uint32_t& d2, uint32_t& d3, uint32_t a) {
    asm volatile("ldmatrix.sync.aligned.m8n8.x4.shared.b16 {%0,%1,%2,%3}, [%4];"
                 : "=r"(d0), "=r"(d1), "=r"(d2), "=r"(d3) : "r"(a));
}
__device__ __forceinline__ void ldsm_x4_t(uint32_t& d0, uint32_t& d1,
                                          uint32_t& d2, uint32_t& d3, uint32_t a) {
    asm volatile("ldmatrix.sync.aligned.m8n8.x4.trans.shared.b16 {%0,%1,%2,%3}, [%4];"
                 : "=r"(d0), "=r"(d1), "=r"(d2), "=r"(d3) : "r"(a));
}

__device__ __forceinline__ void cp_async16(uint32_t dst, const void* src) {
    asm volatile("cp.async.cg.shared.global [%0], [%1], 16;"
                 :: "r"(dst), "l"(src) : "memory");
}
__device__ __forceinline__ void cp_commit() {
    asm volatile("cp.async.commit_group;" ::: "memory");
}
template <int N>
__device__ __forceinline__ void cp_wait() {
    asm volatile("cp.async.wait_group %0;" :: "n"(N) : "memory");
}

// ---------------------------------------------------------------------------
// Prepass 1: weight transpose -> fp16: WT[z][n][k] = fp16(W[z][k][n])
// ---------------------------------------------------------------------------
struct TransArgs { const float* src[4]; __half* dst; };

__global__ __launch_bounds__(256) void trans4_kernel(TransArgs a)
{
    __shared__ float t[32][33];
    const int z = blockIdx.z;
    const float* W = a.src[z];
    __half* D = a.dst + (size_t)z * NDIM * KDIM;

    int x = blockIdx.x * 32 + threadIdx.x;
    int y0 = blockIdx.y * 32;
#pragma unroll
    for (int j = 0; j < 32; j += 8)
        t[threadIdx.y + j][threadIdx.x] = W[(size_t)(y0 + threadIdx.y + j) * 1024 + x];
    __syncthreads();
    int x2 = blockIdx.y * 32 + threadIdx.x;
    int y2 = blockIdx.x * 32;
#pragma unroll
    for (int j = 0; j < 32; j += 8)
        D[(size_t)(y2 + threadIdx.y + j) * 1024 + x2] =
            __float2half_rn(t[threadIdx.x][threadIdx.y + j]);
}

// ---------------------------------------------------------------------------
// Prepass 2: fp32 -> fp16 convert of input activations
// ---------------------------------------------------------------------------
struct CvtArgs { const float* src[3]; __half* dst[3]; };

__global__ __launch_bounds__(256) void cvt_kernel(CvtArgs a)
{
    const int z = blockIdx.z;
    const float* X = a.src[z];
    __half* H = a.dst[z];
    size_t i = ((size_t)blockIdx.x * 256 + threadIdx.x) * 4;
    if (i >= (size_t)MDIM * NDIM) return;
    float4 v = *(const float4*)(X + i);
    __half2 h01 = __floats2half2_rn(v.x, v.y);
    __half2 h23 = __floats2half2_rn(v.z, v.w);
    uint2 pk;
    pk.x = *(uint32_t*)&h01;
    pk.y = *(uint32_t*)&h23;
    *(uint2*)(H + i) = pk;
}

// ---------------------------------------------------------------------------
// Single-pass fp16 mma.sync GEMM: C = A @ B^T (both fp16).
// CTA 128x128, 256 thr, 8 warps (2M x 4N), warp tile 64x32, BK=32,
// 3-stage cp.async pipeline (one sync per K-step), 2 CTAs/SM.
// Epilogue modes: 0: C f32;  2: D1 fp16
// ---------------------------------------------------------------------------
#define WROW 20
#define TILEW (128 * WROW)
#define STW (2 * TILEW)                  // A, B
#define NBUF 3
#define GSMEM (NBUF * STW * 4)           // 61440 bytes

struct GemmArgsH {
    const __half *A[3], *B[3];
    float* C[3];
    __half* D1[3];
    int mode[3];
};

__device__ __forceinline__ void gemm_load_stage(
    const __half* __restrict__ A, const __half* __restrict__ B,
    int s, uint32_t sbase, int tid)
{
#pragma unroll
    for (int i = 0; i < 2; i++) {
        const int idx = tid + i * 256;      // 0..511
        const int r = idx >> 2;             // 0..127
        const int c = idx & 3;              // 0..3 (16B chunks)
        const uint32_t doff = (uint32_t)(r * WROW + c * 4) * 4;
        const size_t goff = (size_t)r * KDIM + s * 32 + c * 8;
        cp_async16(sbase + doff,             A + goff);
        cp_async16(sbase + TILEW * 4 + doff, B + goff);
    }
    cp_commit();
}

__global__ void __launch_bounds__(256, 2)
gemm_f16_kernel(GemmArgsH args)
{
    extern __shared__ uint32_t sw[];
    const int tid = threadIdx.x;
    const int lane = tid & 31;
    const int wid = tid >> 5;          // 0..7
    const int wm = wid >> 2;           // 0..1 -> M offset wm*64
    const int wn = wid & 3;            // 0..3 -> N offset wn*32
    const int r0 = lane >> 2;
    const int c0 = lane & 3;
    const int z = blockIdx.z;

    const size_t aoff = (size_t)blockIdx.y * 128 * KDIM;
    const size_t boff = (size_t)blockIdx.x * 128 * KDIM;
    const __half* A = args.A[z] + aoff;
    const __half* Bw = args.B[z] + boff;

    const uint32_t sbase = smem_u32(sw);

    float acc[4][4][4];
#pragma unroll
    for (int i = 0; i < 4; i++)
#pragma unroll
        for (int j = 0; j < 4; j++)
#pragma unroll
            for (int k = 0; k < 4; k++) acc[i][j][k] = 0.0f;

    // prologue: stages 0 and 1 in flight
    gemm_load_stage(A, Bw, 0, sbase + 0 * STW * 4, tid);
    gemm_load_stage(A, Bw, 1, sbase + 1 * STW * 4, tid);

    const int NST = KDIM / 32;
    for (int s = 0; s < NST; s++) {
        // 1) wait for stage s (pending: s, s+1 -> allow 1; tail: allow 0)
        if (s + 1 < NST) cp_wait<1>();
        else             cp_wait<0>();
        // 2) joint point: data for s visible, all warps done with s-1
        __syncthreads();
        // 3) refill buffer of s-1 with stage s+2
        if (s + 2 < NST)
            gemm_load_stage(A, Bw, s + 2, sbase + ((s + 2) % NBUF) * STW * 4, tid);
        // 4) compute stage s
        const uint32_t* St = sw + (s % NBUF) * STW;

#pragma unroll
        for (int ks = 0; ks < 2; ks++) {
            uint32_t af[4][4], bf[4][2];
#pragma unroll
            for (int nt = 0; nt < 4; nt++) {
                const int n = wn * 32 + nt * 8 + r0;
                const int nb = TILEW + n * WROW + ks * 8 + c0;
                bf[nt][0] = St[nb];
                bf[nt][1] = St[nb + 4];
            }
#pragma unroll
            for (int mt = 0; mt < 4; mt++) {
                const int row = wm * 64 + mt * 16 + r0;
                const int base = row * WROW + ks * 8 + c0;
                af[mt][0] = St[base];
                af[mt][1] = St[base + 8 * WROW];
                af[mt][2] = St[base + 4];
                af[mt][3] = St[base + 8 * WROW + 4];
            }
#pragma unroll
            for (int mt = 0; mt < 4; mt++)
#pragma unroll
                for (int nt = 0; nt < 4; nt++)
                    mma_f16(acc[mt][nt], af[mt], bf[nt][0], bf[nt][1]);
        }
    }

    const int mode = args.mode[z];
    const size_t crow0 = (size_t)blockIdx.y * 128 + wm * 64;
    const size_t ccol0 = (size_t)blockIdx.x * 128 + wn * 32;
#pragma unroll
    for (int mt = 0; mt < 4; mt++) {
#pragma unroll
        for (int nt = 0; nt < 4; nt++) {
            const size_t row = crow0 + mt * 16 + r0;
            const size_t col = ccol0 + nt * 8 + c0 * 2;
            float* c = acc[mt][nt];
            if (mode == 0) {
                float* C = args.C[z];
                *(float2*)(C + row * NDIM + col)       = make_float2(c[0], c[1]);
                *(float2*)(C + (row + 8) * NDIM + col) = make_float2(c[2], c[3]);
            } else {
                __half* D1 = args.D1[z];
                __half2 h01 = __floats2half2_rn(c[0], c[1]);
                __half2 h23 = __floats2half2_rn(c[2], c[3]);
                *(__half2*)(D1 + row * NDIM + col)       = h01;
                *(__half2*)(D1 + (row + 8) * NDIM + col) = h23;
            }
        }
    }
}

// ---------------------------------------------------------------------------
// fp16 tensor-core attention, P in registers, single-pass QK.
// Now 2 CTAs/SM (launch_bounds cap 128 regs; live analysis ~108 peak).
// ---------------------------------------------------------------------------
#define HKS 72
#define HOFF_K 0
#define HOFF_V (2 * 64 * HKS)
#define HSM_HALFS (HOFF_V + 2 * 64 * HKS)    // 18432 halfs
#define HSM_BYTES (HSM_HALFS * 2)            // 36864 B

__device__ __forceinline__ void attn_load_kv16(
    const __half* __restrict__ Kg, const __half* __restrict__ Vg,
    int t, int buf, uint32_t sb, int tid)
{
    const uint32_t kb = sb + (HOFF_K + buf * 64 * HKS) * 2;
    const uint32_t vb = sb + (HOFF_V + buf * 64 * HKS) * 2;
#pragma unroll
    for (int i = 0; i < 2; i++) {
        int idx = tid + i * 256;
        int r = idx >> 3;
        int c = idx & 7;
        const uint32_t doff = (uint32_t)(r * HKS + c * 8) * 2;
        cp_async16(kb + doff, Kg + (size_t)(t * 64 + r) * 64 + c * 8);
        cp_async16(vb + doff, Vg + (size_t)(t * 64 + r) * 64 + c * 8);
    }
    cp_commit();
}

__global__ void __launch_bounds__(256, 2)
attn_fp16_kernel(const __half* __restrict__ Qh, const __half* __restrict__ Kh,
                 const __half* __restrict__ Vh, __half* __restrict__ Oh)
{
    extern __shared__ __half hsm[];
    const int tid = threadIdx.x;
    const int lane = tid & 31;
    const int w = tid >> 5;
    const int r0 = lane >> 2;
    const int c0 = lane & 3;
    const int h = blockIdx.y;
    const int b = blockIdx.z;
    const int qbase = blockIdx.x * 128;
    const size_t off = ((size_t)b * 2048 + h * 128) * 1024;

    const __half* Qg = Qh + off;
    const __half* Kg = Kh + off;
    const __half* Vg = Vh + off;
    const uint32_t sb = smem_u32(hsm);

    uint32_t qf[4][4];
    const int row0 = qbase + w * 16 + r0;
#pragma unroll
    for (int kg = 0; kg < 4; kg++)
#pragma unroll
        for (int q = 0; q < 4; q++) {
            int row = row0 + (q & 1) * 8;
            int col = kg * 16 + (q >> 1) * 8 + 2 * c0;
            qf[kg][q] = *(const uint32_t*)(Qg + (size_t)row * 64 + col);
        }

    float oacc[8][4];
#pragma unroll
    for (int nt = 0; nt < 8; nt++)
#pragma unroll
        for (int j = 0; j < 4; j++) oacc[nt][j] = 0.0f;
    float ls0 = 0.f, ls1 = 0.f;

    attn_load_kv16(Kg, Vg, 0, 0, sb, tid);

    for (int t = 0; t < 32; t++) {
        const int buf = t & 1;
        if (t + 1 < 32) {
            attn_load_kv16(Kg, Vg, t + 1, (t + 1) & 1, sb, tid);
            cp_wait<1>();
        } else {
            cp_wait<0>();
        }
        __syncthreads();

        const uint32_t kbase = sb + (HOFF_K + buf * 64 * HKS) * 2;
        const uint32_t vbase = sb + (HOFF_V + buf * 64 * HKS) * 2;

        // ---- S = Q @ K^T (single pass) ----
        float sacc[8][4];
#pragma unroll
        for (int nt = 0; nt < 8; nt++)
#pragma unroll
            for (int j = 0; j < 4; j++) sacc[nt][j] = 0.0f;

#pragma unroll
        for (int nt = 0; nt < 8; nt++) {
            uint32_t bk[4][2];
#pragma unroll
            for (int p = 0; p < 2; p++) {
                uint32_t a = kbase +
                    (uint32_t)((nt * 8 + (lane & 7)) * HKS + p * 32 + (lane >> 3) * 8) * 2;
                ldsm_x4(bk[2 * p][0], bk[2 * p][1], bk[2 * p + 1][0], bk[2 * p + 1][1], a);
            }
#pragma unroll
            for (int kg = 0; kg < 4; kg++)
                mma_f16(sacc[nt], qf[kg], bk[kg][0], bk[kg][1]);
        }

        // ---- P = exp(S/8): pack QK C-frags directly into PV A-frags ----
        uint32_t pfrag[4][4];
#pragma unroll
        for (int nt = 0; nt < 8; nt++) {
            float p0 = __expf(sacc[nt][0] * 0.125f);
            float p1 = __expf(sacc[nt][1] * 0.125f);
            float p2 = __expf(sacc[nt][2] * 0.125f);
            float p3 = __expf(sacc[nt][3] * 0.125f);
            ls0 += p0 + p1;
            ls1 += p2 + p3;
            __half2 h01 = __floats2half2_rn(p0, p1);
            __half2 h23 = __floats2half2_rn(p2, p3);
            pfrag[nt >> 1][(nt & 1) * 2 + 0] = *(uint32_t*)&h01;
            pfrag[nt >> 1][(nt & 1) * 2 + 1] = *(uint32_t*)&h23;
        }

        // ---- O += P @ V ----
#pragma unroll
        for (int kg = 0; kg < 4; kg++) {
#pragma unroll
            for (int p = 0; p < 4; p++) {
                uint32_t bv0, bv1, bv2, bv3;
                uint32_t a = vbase +
                    (uint32_t)((kg * 16 + ((lane >> 3) & 1) * 8 + (lane & 7)) * HKS +
                               p * 16 + (lane >> 4) * 8) * 2;
                ldsm_x4_t(bv0, bv1, bv2, bv3, a);
                mma_f16(oacc[2 * p],     pfrag[kg], bv0, bv1);
                mma_f16(oacc[2 * p + 1], pfrag[kg], bv2, bv3);
            }
        }
        __syncthreads();
    }

    ls0 += __shfl_xor_sync(0xffffffffu, ls0, 1);
    ls0 += __shfl_xor_sync(0xffffffffu, ls0, 2);
    ls1 += __shfl_xor_sync(0xffffffffu, ls1, 1);
    ls1 += __shfl_xor_sync(0xffffffffu, ls1, 2);
    const float inv0 = 1.0f / ls0;
    const float inv1 = 1.0f / ls1;

#pragma unroll
    for (int nt = 0; nt < 8; nt++) {
        const int col = h * 64 + nt * 8 + 2 * c0;
        __half2 hh01 = __floats2half2_rn(oacc[nt][0] * inv0, oacc[nt][1] * inv0);
        __half2 hh23 = __floats2half2_rn(oacc[nt][2] * inv1, oacc[nt][3] * inv1);
        *(__half2*)(Oh + ((size_t)(b * 2048 + row0)) * 1024 + col)     = hh01;
        *(__half2*)(Oh + ((size_t)(b * 2048 + row0 + 8)) * 1024 + col) = hh23;
    }
}

// ---------------------------------------------------------------------------
// Launch
// ---------------------------------------------------------------------------
extern "C" void kernel_launch(void* const* d_in, const int* in_sizes, int n_in,
                              void* d_out, int out_size)
{
    const float* Q  = (const float*)d_in[0];
    const float* K  = (const float*)d_in[1];
    const float* V  = (const float*)d_in[2];
    const float* WQ = (const float*)d_in[3];
    const float* WK = (const float*)d_in[4];
    const float* WV = (const float*)d_in[5];
    const float* Wf = (const float*)d_in[6];
    float* out = (float*)d_out;

    __half *X, *WT, *Qh, *Kh, *Vh;
    cudaGetSymbolAddress((void**)&X,  g_X);
    cudaGetSymbolAddress((void**)&WT, g_WT);
    cudaGetSymbolAddress((void**)&Qh, g_Qh);
    cudaGetSymbolAddress((void**)&Kh, g_Kh);
    cudaGetSymbolAddress((void**)&Vh, g_Vh);

    cudaFuncSetAttribute(gemm_f16_kernel,
                         cudaFuncAttributeMaxDynamicSharedMemorySize, GSMEM);
    cudaFuncSetAttribute(attn_fp16_kernel,
                         cudaFuncAttributeMaxDynamicSharedMemorySize, HSM_BYTES);

    const size_t NEL = (size_t)MDIM * NDIM;

    // 1) weights: transpose -> fp16
    TransArgs t;
    t.src[0] = WQ; t.src[1] = WK; t.src[2] = WV; t.src[3] = Wf;
    t.dst = WT;
    trans4_kernel<<<dim3(32, 32, 4), dim3(32, 8)>>>(t);

    // 2) input activations -> fp16
    CvtArgs cv;
    cv.src[0] = Q; cv.src[1] = K; cv.src[2] = V;
    for (int i = 0; i < 3; i++) cv.dst[i] = X + i * NEL;
    cvt_kernel<<<dim3((unsigned)(NEL / 4 / 256), 1, 3), 256>>>(cv);

    // 3) Q/K/V projections -> fp16
    GemmArgsH g1;
    for (int i = 0; i < 3; i++) {
        g1.A[i] = X + i * NEL;
        g1.B[i] = WT + (size_t)i * NDIM * KDIM;
        g1.C[i] = nullptr;
        g1.mode[i] = 2;
    }
    g1.D1[0] = Qh; g1.D1[1] = Kh; g1.D1[2] = Vh;
    gemm_f16_kernel<<<dim3(NDIM / 128, MDIM / 128, 3), 256, GSMEM>>>(g1);

    // 4) attention -> ctx fp16 into slot 0
    attn_fp16_kernel<<<dim3(16, 16, 4), 256, HSM_BYTES>>>(Qh, Kh, Vh, X);

    // 5) output projection (f32 out)
    GemmArgsH g2;
    for (int i = 0; i < 3; i++) {
        g2.A[i] = X;
        g2.B[i] = WT + (size_t)3 * NDIM * KDIM;
        g2.C[i] = out;
        g2.D1[i] = nullptr;
        g2.mode[i] = 0;
    }
    gemm_f16_kernel<<<dim3(NDIM / 128, MDIM / 128, 1), 256, GSMEM>>>(g2);
}